// round 10
// baseline (speedup 1.0000x reference)
#include <cuda_runtime.h>
#include <cuda_bf16.h>
#include <math.h>
#include <stdint.h>

#define TT   128
#define BB   512
#define DD   512
#define MM   6
#define JJ   (TT + MM)
#define HH   2
#define DFF  64
#define ACT  64
#define NROW (TT * BB)
#define BG   0.1f

typedef __nv_bfloat16 bf16;

// ---------- static scratch ----------
__device__ __align__(256) float g_B1[NROW * DD];
__device__ __align__(256) float g_B4[NROW * DD];
__device__ __align__(256) float g_qkv[NROW * 192];
__device__ __align__(256) float g_kvm[MM * BB * 128];
__device__ __align__(256) float g_p  [JJ * 64];
__device__ __align__(256) float g_ts [BB * DD];
__device__ __align__(256) float g_h1 [BB * 1024];
__device__ __align__(256) float g_h2 [BB * 512];
__device__ __align__(256) float g_h3 [BB * 300];
__device__ __align__(256) float g_bc [2 * 1024];            // concat biases for merged r/z
__device__ __align__(256) bf16 gb_x  [NROW * DD];
__device__ __align__(256) bf16 gb_ln [NROW * DD];
__device__ __align__(256) bf16 gb_y  [NROW * DD];
__device__ __align__(256) bf16 gb_rx [NROW * DD];
__device__ __align__(256) bf16 gb_z  [NROW * DD];
__device__ __align__(256) bf16 gb_src[NROW * DD];
__device__ __align__(256) bf16 gb_ffh[NROW * DFF];
__device__ __align__(256) bf16 gb_av [NROW * 64];
__device__ __align__(256) bf16 gb_mem[MM * BB * DD];
__device__ __align__(256) bf16 gb_wqkv[192 * DD];
__device__ __align__(256) bf16 gb_wout[DD * 64];
__device__ __align__(256) bf16 gb_g1  [6 * DD * DD];        // slots: [W0t,W2t,W1t,W3t,W4t,W5t]
__device__ __align__(256) bf16 gb_g2  [6 * DD * DD];
__device__ __align__(256) bf16 gb_ff1 [DFF * DD];
__device__ __align__(256) bf16 gb_ff2 [DD * DFF];

// ---------- helpers ----------
__device__ __forceinline__ uint32_t s2u(const void* p) {
    return (uint32_t)__cvta_generic_to_shared(p);
}
__device__ __forceinline__ void cp16(uint32_t s, const void* g) {
    asm volatile("cp.async.cg.shared.global [%0], [%1], 16;" :: "r"(s), "l"(g));
}
__device__ __forceinline__ void cp_commit() { asm volatile("cp.async.commit_group;" ::: "memory"); }
__device__ __forceinline__ void cp_wait0()  { asm volatile("cp.async.wait_group 0;" ::: "memory"); }
__device__ __forceinline__ void cp_wait1()  { asm volatile("cp.async.wait_group 1;" ::: "memory"); }
__device__ __forceinline__ void ldsm4(uint32_t* r, uint32_t addr) {
    asm volatile("ldmatrix.sync.aligned.m8n8.x4.shared.b16 {%0,%1,%2,%3}, [%4];"
                 : "=r"(r[0]), "=r"(r[1]), "=r"(r[2]), "=r"(r[3]) : "r"(addr));
}
__device__ __forceinline__ void mma_bf16(float* c, const uint32_t* a, const uint32_t* b) {
    asm volatile(
        "mma.sync.aligned.m16n8k16.row.col.f32.bf16.bf16.f32 "
        "{%0,%1,%2,%3}, {%4,%5,%6,%7}, {%8,%9}, {%0,%1,%2,%3};"
        : "+f"(c[0]), "+f"(c[1]), "+f"(c[2]), "+f"(c[3])
        : "r"(a[0]), "r"(a[1]), "r"(a[2]), "r"(a[3]), "r"(b[0]), "r"(b[1]));
}

// ---------- bf16 dual-source tensor GEMM (ldmatrix + 3-stage cp.async) ----------
// C[M,N] = A0[M,K0]@W0[N,K0]^T + A1[M,K1]@W1[N,K1]^T (+bias1+bias2+cadd)
// modes: 0 f32 | 2 bf16 | 3 bf16 relu | 4 bf16 = sigmoid(v)*aux
//        5 f32(+opt bf16) = (1-sig(zpre))*aux + sig(zpre)*tanh(v)
//        6 merged r/z: col<512 -> Cb[r*512+c]=bf16(sig(v)*aux[r*512+c]);
//                      col>=512 -> ((bf16*)Cf)[r*512+c-512]=bf16(v)

template<int NT>
__global__ __launch_bounds__(256, 2)
void bgemm(const bf16* __restrict__ A0, const bf16* __restrict__ W0, int K0,
           const bf16* __restrict__ A1, const bf16* __restrict__ W1, int K1,
           int N,
           float* __restrict__ Cf, bf16* __restrict__ Cb,
           const float* __restrict__ bias1, const float* __restrict__ bias2,
           float cadd, const bf16* __restrict__ zpre, const float* __restrict__ aux,
           int mode)
{
    extern __shared__ char dsm[];
    constexpr int NTI = NT / 32;
    constexpr int STG = (128 + NT) * 144;

    const int tid  = threadIdx.x;
    const int warp = tid >> 5, lane = tid & 31;
    const int grp  = lane >> 2, thr = lane & 3;
    const int wm   = warp & 1,  wn  = warp >> 1;
    const int m_base = wm * 64;
    const int n_base = wn * (NT / 4);
    const int row0 = blockIdx.y * 128;
    const int col0 = blockIdx.x * NT;
    const uint32_t sb = s2u(dsm);

    float acc[4][NTI][4];
#pragma unroll
    for (int i = 0; i < 4; i++)
#pragma unroll
        for (int j = 0; j < NTI; j++)
#pragma unroll
            for (int r = 0; r < 4; r++) acc[i][j][r] = 0.f;

    const int NC0 = K0 >> 6;
    const int NC  = NC0 + (K1 >> 6);

    auto load_stage = [&](int c, int buf) {
        const bf16 *a, *w; int k, kb;
        if (c < NC0) { a = A0; w = W0; k = K0; kb = c << 6; }
        else         { a = A1; w = W1; k = K1; kb = (c - NC0) << 6; }
        uint32_t ab = sb + (uint32_t)buf * STG;
#pragma unroll
        for (int i = 0; i < 4; i++) {
            int u = tid + i * 256;
            int r = u >> 3, cc = u & 7;
            cp16(ab + (uint32_t)(r * 144 + cc * 16),
                 a + (size_t)(row0 + r) * k + kb + cc * 8);
        }
        uint32_t bb = ab + 128u * 144u;
#pragma unroll
        for (int i = 0; i < NT / 32; i++) {
            int u = tid + i * 256;
            int r = u >> 3, cc = u & 7;
            cp16(bb + (uint32_t)(r * 144 + cc * 16),
                 w + (size_t)(col0 + r) * k + kb + cc * 8);
        }
        cp_commit();
    };

    load_stage(0, 0);
    if (NC > 1) load_stage(1, 1);

    for (int c = 0; c < NC; c++) {
        if (c == NC - 1) cp_wait0(); else cp_wait1();
        __syncthreads();
        if (c + 2 < NC) load_stage(c + 2, (c + 2) % 3);

        uint32_t ab = sb + (uint32_t)(c % 3) * STG;
        uint32_t bb = ab + 128u * 144u;

        const uint32_t a_lrow = (uint32_t)(lane & 15);
        const uint32_t a_koff = (uint32_t)((lane >> 4) << 3);
        const uint32_t b_cofs = (uint32_t)(((lane >> 4) << 3) + (lane & 7));
        const uint32_t b_koff = (uint32_t)(((lane >> 3) & 1) << 3);

#pragma unroll
        for (int ks = 0; ks < 4; ks++) {
            const int kc = ks * 16;
            uint32_t af[4][4], bfr[NTI][2];
#pragma unroll
            for (int mt = 0; mt < 4; mt++) {
                uint32_t addr = ab + (uint32_t)(m_base + mt * 16 + a_lrow) * 144u
                                   + (uint32_t)(kc + a_koff) * 2u;
                ldsm4(af[mt], addr);
            }
#pragma unroll
            for (int p = 0; p < NTI / 2; p++) {
                uint32_t col = (uint32_t)(n_base + p * 16) + b_cofs;
                uint32_t addr = bb + col * 144u + (uint32_t)(kc + b_koff) * 2u;
                uint32_t r[4];
                ldsm4(r, addr);
                bfr[2 * p][0]     = r[0]; bfr[2 * p][1]     = r[1];
                bfr[2 * p + 1][0] = r[2]; bfr[2 * p + 1][1] = r[3];
            }
#pragma unroll
            for (int mt = 0; mt < 4; mt++)
#pragma unroll
                for (int nt = 0; nt < NTI; nt++)
                    mma_bf16(acc[mt][nt], af[mt], bfr[nt]);
        }
    }

    // epilogue
#pragma unroll
    for (int mt = 0; mt < 4; mt++) {
#pragma unroll
        for (int nt = 0; nt < NTI; nt++) {
            int cbase = col0 + n_base + nt * 8 + thr * 2;
            float b0 = cadd, b1 = cadd;
            if (bias1) { b0 += bias1[cbase]; b1 += bias1[cbase + 1]; }
            if (bias2) { b0 += bias2[cbase]; b1 += bias2[cbase + 1]; }
#pragma unroll
            for (int half = 0; half < 2; half++) {
                int r = row0 + m_base + mt * 16 + grp + half * 8;
                size_t idx0 = (size_t)r * N + cbase;
#pragma unroll
                for (int e = 0; e < 2; e++) {
                    float v = acc[mt][nt][half * 2 + e] + (e ? b1 : b0);
                    size_t idx = idx0 + e;
                    int gc = cbase + e;
                    if (mode == 0) {
                        Cf[idx] = v;
                    } else if (mode == 2) {
                        Cb[idx] = __float2bfloat16(v);
                    } else if (mode == 3) {
                        Cb[idx] = __float2bfloat16(fmaxf(v, 0.f));
                    } else if (mode == 4) {
                        float s = 1.f / (1.f + __expf(-v));
                        Cb[idx] = __float2bfloat16(s * aux[idx]);
                    } else if (mode == 5) {
                        float z = 1.f / (1.f + __expf(-__bfloat162float(zpre[idx])));
                        float o = (1.f - z) * aux[idx] + z * tanhf(v);
                        Cf[idx] = o;
                        if (Cb) Cb[idx] = __float2bfloat16(o);
                    } else {
                        // mode 6: merged r/z, outputs at N=512 stride
                        if (gc < 512) {
                            size_t oi = (size_t)r * 512 + gc;
                            float s = 1.f / (1.f + __expf(-v));
                            Cb[oi] = __float2bfloat16(s * aux[oi]);
                        } else {
                            size_t oi = (size_t)r * 512 + (gc - 512);
                            ((bf16*)Cf)[oi] = __float2bfloat16(v);
                        }
                    }
                }
            }
        }
    }
}

// ---------- exact fp32 GEMM, 64x64 tiles (critic head) ----------
__global__ void sgemm64_kernel(const float* __restrict__ A, const float* __restrict__ W,
                               float* __restrict__ C, int M, int N, int K,
                               const float* __restrict__ bias, float cadd, int flags)
{
    __shared__ float As[8][64];
    __shared__ float Bs[8][65];
    int tid = threadIdx.x;
    int row0 = blockIdx.y * 64, col0 = blockIdx.x * 64;
    int tx = tid & 15, ty = tid >> 4;
    float acc[4][4];
#pragma unroll
    for (int i = 0; i < 4; i++)
#pragma unroll
        for (int j = 0; j < 4; j++) acc[i][j] = 0.f;

    int ar = tid >> 2, ac2 = (tid & 3) * 2;
    int br = tid >> 5, bc = tid & 31;

    for (int k0 = 0; k0 < K; k0 += 8) {
        float2 a2 = *reinterpret_cast<const float2*>(A + (size_t)(row0 + ar) * K + k0 + ac2);
        As[ac2][ar] = a2.x;
        As[ac2 + 1][ar] = a2.y;
        float w0 = (col0 + bc < N)      ? W[(size_t)(k0 + br) * N + col0 + bc]      : 0.f;
        float w1 = (col0 + bc + 32 < N) ? W[(size_t)(k0 + br) * N + col0 + bc + 32] : 0.f;
        Bs[br][bc] = w0;
        Bs[br][bc + 32] = w1;
        __syncthreads();
#pragma unroll
        for (int kk = 0; kk < 8; kk++) {
            float av[4], bv[4];
#pragma unroll
            for (int i = 0; i < 4; i++) av[i] = As[kk][ty * 4 + i];
#pragma unroll
            for (int j = 0; j < 4; j++) bv[j] = Bs[kk][tx * 4 + j];
#pragma unroll
            for (int i = 0; i < 4; i++)
#pragma unroll
                for (int j = 0; j < 4; j++) acc[i][j] += av[i] * bv[j];
        }
        __syncthreads();
    }
#pragma unroll
    for (int i = 0; i < 4; i++) {
        int r = row0 + ty * 4 + i;
        if (r >= M) continue;
#pragma unroll
        for (int j = 0; j < 4; j++) {
            int c = col0 + tx * 4 + j;
            if (c >= N) continue;
            float val = acc[i][j] + cadd;
            if (bias) val += bias[c];
            size_t idx = (size_t)r * N + c;
            if (flags & 1) val += C[idx];
            if (flags & 2) val = fmaxf(val, 0.f);
            C[idx] = val;
        }
    }
}

// ---------- LayerNorm (bf16 out) ----------
__global__ void ln_kernel(const float* __restrict__ x, bf16* __restrict__ out,
                          const float* __restrict__ g, const float* __restrict__ b, int rows)
{
    int warp = blockIdx.x * (blockDim.x >> 5) + (threadIdx.x >> 5);
    if (warp >= rows) return;
    int lane = threadIdx.x & 31;
    const float* xr = x + (size_t)warp * DD;
    float v[16], s1 = 0.f, s2 = 0.f;
#pragma unroll
    for (int i = 0; i < 16; i++) {
        float t = xr[i * 32 + lane];
        v[i] = t; s1 += t; s2 += t * t;
    }
#pragma unroll
    for (int o = 16; o; o >>= 1) {
        s1 += __shfl_xor_sync(0xffffffffu, s1, o);
        s2 += __shfl_xor_sync(0xffffffffu, s2, o);
    }
    float mu = s1 * (1.f / DD);
    float inv = rsqrtf(s2 * (1.f / DD) - mu * mu + 1e-5f);
    bf16* orow = out + (size_t)warp * DD;
#pragma unroll
    for (int i = 0; i < 16; i++) {
        int d = i * 32 + lane;
        orow[d] = __float2bfloat16((v[i] - mu) * inv * g[d] + b[d]);
    }
}

// ---------- pos-emb @ W_p ----------
__global__ void prep_p_kernel(const float* __restrict__ Wp, float* __restrict__ p)
{
    int jj = blockIdx.x;
    __shared__ float pe[DD];
    float pos = (float)(JJ - 1 - jj);
    for (int d = threadIdx.x; d < DD; d += 64) {
        int i = (d < 256) ? d : d - 256;
        float f = __expf(-(float)(2 * i) * (1.f / 512.f) * 9.210340371976184f);
        float a = pos * f;
        pe[d] = (d < 256) ? sinf(a) : cosf(a);
    }
    __syncthreads();
    int c = threadIdx.x;
    float acc = 0.f;
    for (int d = 0; d < DD; d++) acc += pe[d] * Wp[d * 64 + c];
    p[jj * 64 + c] = acc;
}

// ---------- attention: q/kv from fused QKV + memory kv ----------
__global__ void attn_kernel(const float* __restrict__ qkv, const float* __restrict__ kvm,
                            const float* __restrict__ p, const float* __restrict__ uu,
                            const float* __restrict__ vvec, bf16* __restrict__ av)
{
    int b = blockIdx.x, h = blockIdx.y;
    __shared__ float Ks[JJ][33];
    __shared__ float Vs[JJ][33];
    __shared__ float att[4][JJ];
    __shared__ float qsu[4][32];
    __shared__ float qsv[4][32];
    int tid = threadIdx.x;
    for (int idx = tid; idx < JJ * 32; idx += 128) {
        int j = idx >> 5, d = idx & 31;
        const float* row;
        if (j < MM)
            row = kvm + ((size_t)j * BB + b) * 128 + h * 32 + d;
        else
            row = qkv + ((size_t)(j - MM) * BB + b) * 192 + 64 + h * 32 + d;
        Ks[j][d] = row[0];
        Vs[j][d] = row[64];
    }
    __syncthreads();
    int warp = tid >> 5, lane = tid & 31;
    float ul = uu[h * 32 + lane], vl = vvec[h * 32 + lane];
    for (int i = warp; i < TT; i += 4) {
        float qv = qkv[((size_t)i * BB + b) * 192 + h * 32 + lane];
        qsu[warp][lane] = qv + ul;
        qsv[warp][lane] = qv + vl;
        __syncwarp();
        int jmax = i + MM;
        float sv[5], smax = -1e30f;
        int cnt = 0;
        for (int j = lane; j <= jmax; j += 32) {
            const float* prow = p + (size_t)(j + TT - 1 - i) * 64 + h * 32;
            float s = 0.f;
#pragma unroll
            for (int d = 0; d < 32; d++)
                s += qsu[warp][d] * Ks[j][d] + qsv[warp][d] * prow[d];
            s *= 0.1767766952966369f;
            sv[cnt++] = s;
            smax = fmaxf(smax, s);
        }
#pragma unroll
        for (int o = 16; o; o >>= 1) smax = fmaxf(smax, __shfl_xor_sync(0xffffffffu, smax, o));
        float sum = 0.f; cnt = 0;
        for (int j = lane; j <= jmax; j += 32) {
            float e = __expf(sv[cnt++] - smax);
            att[warp][j] = e;
            sum += e;
        }
#pragma unroll
        for (int o = 16; o; o >>= 1) sum += __shfl_xor_sync(0xffffffffu, sum, o);
        float inv = 1.f / sum;
        __syncwarp();
        float acc = 0.f;
        for (int j = 0; j <= jmax; j++) acc += att[warp][j] * Vs[j][lane];
        av[((size_t)i * BB + b) * 64 + h * 32 + lane] = __float2bfloat16(acc * inv);
        __syncwarp();
    }
}

// ---------- transpose+convert W[K,N] f32 -> [N,K] bf16 ----------
__global__ void tpose_kernel(const float* __restrict__ in, bf16* __restrict__ out, int K, int N)
{
    __shared__ float t[32][33];
    int k0 = blockIdx.y * 32, n0 = blockIdx.x * 32;
    int x = threadIdx.x, y = threadIdx.y;
    for (int i = y; i < 32; i += 8)
        t[i][x] = in[(size_t)(k0 + i) * N + n0 + x];
    __syncthreads();
    for (int i = y; i < 32; i += 8)
        out[(size_t)(n0 + i) * K + k0 + x] = __float2bfloat16(t[x][i]);
}

// ---------- batched transpose for the 12 gate matrices, with slot permutation ----------
// slot order per gate: [W0^T, W2^T, W1^T, W3^T, W4^T, W5^T] so that the merged r/z
// GEMM sees contiguous 1024-row weights at slots 0 (y-side) and 2 (x-side).
__global__ void btpose_kernel(const float* __restrict__ g1, const float* __restrict__ g2,
                              bf16* __restrict__ o1, bf16* __restrict__ o2)
{
    __shared__ float t[32][33];
    const int perm[6] = {0, 2, 1, 3, 4, 5};   // perm[slot] = source matrix
    int z = blockIdx.z;
    int gi = z % 6;
    const float* base = (z < 6) ? g1 : g2;
    bf16* obase = (z < 6) ? o1 : o2;
    const float* in = base + (size_t)perm[gi] * DD * DD;
    bf16* out = obase + (size_t)gi * DD * DD;
    int k0 = blockIdx.y * 32, n0 = blockIdx.x * 32;
    int x = threadIdx.x, y = threadIdx.y;
    for (int i = y; i < 32; i += 8)
        t[i][x] = in[(size_t)(k0 + i) * DD + n0 + x];
    __syncthreads();
    for (int i = y; i < 32; i += 8)
        out[(size_t)(n0 + i) * DD + k0 + x] = __float2bfloat16(t[x][i]);
}

// ---------- concat-bias prep for merged r/z ----------
__global__ void bcat_kernel(const float* __restrict__ g1b, const float* __restrict__ g2b,
                            float* __restrict__ bc)
{
    int i = blockIdx.x * 256 + threadIdx.x;
    if (i >= 2048) return;
    const float* gb = (i < 1024) ? g1b : g2b;
    int c = i & 1023;
    float v;
    if (c < 512) v = gb[0 * 512 + c] + gb[1 * 512 + c];
    else         v = gb[2 * 512 + (c - 512)] + gb[3 * 512 + (c - 512)] - BG;
    bc[i] = v;
}

// ---------- f32 -> bf16 ----------
__global__ void cvt_kernel(const float* __restrict__ in, bf16* __restrict__ out, int n4)
{
    int i = blockIdx.x * blockDim.x + threadIdx.x;
    if (i >= n4) return;
    float4 v = reinterpret_cast<const float4*>(in)[i];
    __nv_bfloat162* o = reinterpret_cast<__nv_bfloat162*>(out + (size_t)i * 4);
    o[0] = __floats2bfloat162_rn(v.x, v.y);
    o[1] = __floats2bfloat162_rn(v.z, v.w);
}

// ---------- mean pool (vectorized) ----------
__global__ void meanpool_kernel(const float4* __restrict__ in, float4* __restrict__ ts)
{
    int idx = blockIdx.x * blockDim.x + threadIdx.x;
    const int n4 = BB * DD / 4;
    if (idx >= n4) return;
    float4 s = make_float4(0.f, 0.f, 0.f, 0.f);
    for (int t = 0; t < TT; t++) {
        float4 v = in[(size_t)t * n4 + idx];
        s.x += v.x; s.y += v.y; s.z += v.z; s.w += v.w;
    }
    const float inv = 1.f / TT;
    s.x *= inv; s.y *= inv; s.z *= inv; s.w *= inv;
    ts[idx] = s;
}

// ---------- final head ----------
__global__ void final_kernel(const float* __restrict__ h3, const float* __restrict__ w,
                             const float* __restrict__ bb, float* __restrict__ out)
{
    int row = blockIdx.x * 4 + (threadIdx.x >> 5);
    int lane = threadIdx.x & 31;
    if (row >= BB) return;
    float s = 0.f;
    for (int k = lane; k < 300; k += 32) s += h3[(size_t)row * 300 + k] * w[k];
#pragma unroll
    for (int o = 16; o; o >>= 1) s += __shfl_xor_sync(0xffffffffu, s, o);
    if (lane == 0) out[row] = fmaxf(s + bb[0], 0.f);
}

// ---------- host ----------
static inline void launch_tc(const bf16* A0, const bf16* W0, int K0,
                             const bf16* A1, const bf16* W1, int K1,
                             int M, int N, int NT,
                             float* Cf, bf16* Cb,
                             const float* b1, const float* b2, float cadd,
                             const bf16* zpre, const float* aux, int mode)
{
    dim3 grid(N / NT, M / 128);
    if (NT == 128) {
        size_t dsz = 3 * (size_t)(128 + 128) * 144;
        bgemm<128><<<grid, 256, dsz>>>(A0, W0, K0, A1, W1, K1, N, Cf, Cb, b1, b2, cadd, zpre, aux, mode);
    } else {
        size_t dsz = 3 * (size_t)(128 + 64) * 144;
        bgemm<64><<<grid, 256, dsz>>>(A0, W0, K0, A1, W1, K1, N, Cf, Cb, b1, b2, cadd, zpre, aux, mode);
    }
}
static inline void launch_sgemm(const float* A, const float* W, float* C,
                                int M, int N, int K, const float* bias, float cadd, int flags)
{
    dim3 grid((N + 63) / 64, (M + 63) / 64);
    sgemm64_kernel<<<grid, 256>>>(A, W, C, M, N, K, bias, cadd, flags);
}
static inline void launch_tpose(const float* in, bf16* out, int K, int N)
{
    tpose_kernel<<<dim3(N / 32, K / 32), dim3(32, 8)>>>(in, out, K, N);
}

extern "C" void kernel_launch(void* const* d_in, const int* in_sizes, int n_in,
                              void* d_out, int out_size)
{
    const float* x      = (const float*)d_in[0];
    const float* action = (const float*)d_in[1];
    const float* memory = (const float*)d_in[2];
    const float* W_q    = (const float*)d_in[3];
    const float* W_kv   = (const float*)d_in[4];
    const float* W_p    = (const float*)d_in[5];
    const float* W_out  = (const float*)d_in[6];
    const float* u      = (const float*)d_in[7];
    const float* v      = (const float*)d_in[8];
    const float* ln1_g  = (const float*)d_in[9];
    const float* ln1_b  = (const float*)d_in[10];
    const float* ln2_g  = (const float*)d_in[11];
    const float* ln2_b  = (const float*)d_in[12];
    const float* ff_W1  = (const float*)d_in[13];
    const float* ff_b1  = (const float*)d_in[14];
    const float* ff_W2  = (const float*)d_in[15];
    const float* ff_b2  = (const float*)d_in[16];
    const float* g1W    = (const float*)d_in[17];
    const float* g1b    = (const float*)d_in[18];
    const float* g2W    = (const float*)d_in[19];
    const float* g2b    = (const float*)d_in[20];
    const float* d1W    = (const float*)d_in[21];
    const float* d1b    = (const float*)d_in[22];
    const float* d2W    = (const float*)d_in[23];
    const float* d2b    = (const float*)d_in[24];
    const float* d3W    = (const float*)d_in[25];
    const float* d3b    = (const float*)d_in[26];
    const float* d4W    = (const float*)d_in[27];
    const float* d4b    = (const float*)d_in[28];

    cudaFuncSetAttribute(bgemm<128>, cudaFuncAttributeMaxDynamicSharedMemorySize, 111000);
    cudaFuncSetAttribute(bgemm<64>,  cudaFuncAttributeMaxDynamicSharedMemorySize, 84000);

    float *B1, *B4, *QKV, *KVM, *P, *TS, *H1, *H2, *H3, *BC;
    bf16 *XB, *LNB, *YB, *RXB, *ZB, *SRCB, *FFHB, *AVB, *MEMB;
    bf16 *WQKVT, *WOUTT, *G1T, *G2T, *FF1T, *FF2T;
    cudaGetSymbolAddress((void**)&B1,   g_B1);
    cudaGetSymbolAddress((void**)&B4,   g_B4);
    cudaGetSymbolAddress((void**)&QKV,  g_qkv);
    cudaGetSymbolAddress((void**)&KVM,  g_kvm);
    cudaGetSymbolAddress((void**)&P,    g_p);
    cudaGetSymbolAddress((void**)&TS,   g_ts);
    cudaGetSymbolAddress((void**)&H1,   g_h1);
    cudaGetSymbolAddress((void**)&H2,   g_h2);
    cudaGetSymbolAddress((void**)&H3,   g_h3);
    cudaGetSymbolAddress((void**)&BC,   g_bc);
    cudaGetSymbolAddress((void**)&XB,   gb_x);
    cudaGetSymbolAddress((void**)&LNB,  gb_ln);
    cudaGetSymbolAddress((void**)&YB,   gb_y);
    cudaGetSymbolAddress((void**)&RXB,  gb_rx);
    cudaGetSymbolAddress((void**)&ZB,   gb_z);
    cudaGetSymbolAddress((void**)&SRCB, gb_src);
    cudaGetSymbolAddress((void**)&FFHB, gb_ffh);
    cudaGetSymbolAddress((void**)&AVB,  gb_av);
    cudaGetSymbolAddress((void**)&MEMB, gb_mem);
    cudaGetSymbolAddress((void**)&WQKVT,gb_wqkv);
    cudaGetSymbolAddress((void**)&WOUTT,gb_wout);
    cudaGetSymbolAddress((void**)&G1T,  gb_g1);
    cudaGetSymbolAddress((void**)&G2T,  gb_g2);
    cudaGetSymbolAddress((void**)&FF1T, gb_ff1);
    cudaGetSymbolAddress((void**)&FF2T, gb_ff2);

    const size_t SZ = (size_t)DD * DD;

    // weight prep: permuted gate slots [W0t,W2t,W1t,W3t,W4t,W5t]; q|kv fused
    btpose_kernel<<<dim3(16, 16, 12), dim3(32, 8)>>>(g1W, g2W, G1T, G2T);
    bcat_kernel<<<8, 256>>>(g1b, g2b, BC);
    launch_tpose(W_q,   WQKVT,            DD, 64);
    launch_tpose(W_kv,  WQKVT + 64 * DD,  DD, 128);
    launch_tpose(W_out, WOUTT, 64, DD);
    launch_tpose(ff_W1, FF1T, DD, DFF);
    launch_tpose(ff_W2, FF2T, DFF, DD);

    // activation converts
    cvt_kernel<<<(NROW * DD / 4 + 255) / 256, 256>>>(x, XB, NROW * DD / 4);
    cvt_kernel<<<(MM * BB * DD / 4 + 255) / 256, 256>>>(memory, MEMB, MM * BB * DD / 4);

    // pos emb
    prep_p_kernel<<<JJ, 64>>>(W_p, P);

    // LN1 -> LNB (bf16)
    ln_kernel<<<NROW / 8, 256>>>(x, LNB, ln1_g, ln1_b, NROW);

    // fused qkv = LN1 @ [Wq|Wkv] (f32 out, N=192)
    launch_tc(LNB, WQKVT, DD, 0, 0, 0, NROW, 192, 64, QKV, 0, 0, 0, 0.f, 0, 0, 0);

    // memory kv = memory @ Wkv (f32 out)
    launch_tc(MEMB, WQKVT + 64 * DD, DD, 0, 0, 0, MM * BB, 128, 128, KVM, 0, 0, 0, 0.f, 0, 0, 0);

    // attention -> AVB (bf16)
    attn_kernel<<<dim3(BB, HH), 128>>>(QKV, KVM, P, u, v, AVB);

    // y = av @ W_out -> YB (bf16)
    launch_tc(AVB, WOUTT, 64, 0, 0, 0, NROW, DD, 128, 0, YB, 0, 0, 0.f, 0, 0, 2);

    // gate 1: merged r/z (N=1024, mode 6), then combine
    launch_tc(YB, G1T + 0 * SZ, DD, XB, G1T + 2 * SZ, DD, NROW, 1024, 128,
              (float*)ZB, RXB, BC, 0, 0.f, 0, x, 6);
    launch_tc(YB, G1T + 4 * SZ, DD, RXB, G1T + 5 * SZ, DD, NROW, DD, 128,
              B4, SRCB, g1b + 4 * DD, g1b + 5 * DD, 0.f, ZB, x, 5);

    // ff = relu(LN2(src)@W1+b1)@W2+b2 -> XB (x no longer needed)
    ln_kernel<<<NROW / 8, 256>>>(B4, LNB, ln2_g, ln2_b, NROW);
    launch_tc(LNB, FF1T, DD, 0, 0, 0, NROW, DFF, 64, 0, FFHB, ff_b1, 0, 0.f, 0, 0, 3);
    launch_tc(FFHB, FF2T, DFF, 0, 0, 0, NROW, DD, 128, 0, XB, ff_b2, 0, 0.f, 0, 0, 2);

    // gate 2: merged r/z (mode 6), then combine -> B1 (f32)
    launch_tc(XB, G2T + 0 * SZ, DD, SRCB, G2T + 2 * SZ, DD, NROW, 1024, 128,
              (float*)ZB, RXB, BC + 1024, 0, 0.f, 0, B4, 6);
    launch_tc(XB, G2T + 4 * SZ, DD, RXB, G2T + 5 * SZ, DD, NROW, DD, 128,
              B1, 0, g2b + 4 * DD, g2b + 5 * DD, 0.f, ZB, B4, 5);

    // mean pool
    meanpool_kernel<<<(BB * DD / 4 + 255) / 256, 256>>>((const float4*)B1, (float4*)TS);

    // critic head (exact fp32)
    launch_sgemm(TS, d1W, H1, BB, 1024, DD, d1b, 0.f, 2);
    launch_sgemm(H1, d2W, H2, BB, 512, 1024, nullptr, 0.f, 0);
    launch_sgemm(action, d2W + (size_t)1024 * 512, H2, BB, 512, ACT, d2b, 0.f, 3);
    launch_sgemm(H2, d3W, H3, BB, 300, DD, d3b, 0.f, 2);
    final_kernel<<<BB / 4, 128>>>(H3, d4W, d4b, (float*)d_out);
}

// round 11
// speedup vs baseline: 1.0209x; 1.0209x over previous
#include <cuda_runtime.h>
#include <cuda_bf16.h>
#include <math.h>
#include <stdint.h>

#define TT   128
#define BB   512
#define DD   512
#define MM   6
#define JJ   (TT + MM)
#define HH   2
#define DFF  64
#define ACT  64
#define NROW (TT * BB)
#define MROW (MM * BB)
#define AROW (NROW + MROW)      // 68608
#define BG   0.1f

typedef __nv_bfloat16 bf16;

// ---------- static scratch ----------
__device__ __align__(256) float g_B1[NROW * DD];
__device__ __align__(256) float g_qkv[AROW * 192];
__device__ __align__(256) float g_p  [JJ * 64];
__device__ __align__(256) float g_ts [BB * DD];
__device__ __align__(256) float g_h1 [BB * 1024];
__device__ __align__(256) float g_h2 [BB * 512];
__device__ __align__(256) float g_h3 [BB * 300];
__device__ __align__(256) bf16 gb_x   [NROW * DD];
__device__ __align__(256) bf16 gb_lnm [AROW * DD];   // rows 0..NROW-1: LN out; NROW..: memory bf16
__device__ __align__(256) bf16 gb_y   [NROW * DD];
__device__ __align__(256) bf16 gb_rx  [NROW * DD];
__device__ __align__(256) bf16 gb_z   [NROW * DD];
__device__ __align__(256) bf16 gb_src [NROW * DD];
__device__ __align__(256) bf16 gb_ffh [NROW * DFF];
__device__ __align__(256) bf16 gb_av  [NROW * 64];
__device__ __align__(256) bf16 gb_wqkv[192 * DD];
__device__ __align__(256) bf16 gb_wout[DD * 64];
__device__ __align__(256) bf16 gb_g1  [6 * DD * DD];
__device__ __align__(256) bf16 gb_g2  [6 * DD * DD];
__device__ __align__(256) bf16 gb_ff1 [DFF * DD];
__device__ __align__(256) bf16 gb_ff2 [DD * DFF];

// ---------- helpers ----------
__device__ __forceinline__ uint32_t s2u(const void* p) {
    return (uint32_t)__cvta_generic_to_shared(p);
}
__device__ __forceinline__ void cp16(uint32_t s, const void* g) {
    asm volatile("cp.async.cg.shared.global [%0], [%1], 16;" :: "r"(s), "l"(g));
}
__device__ __forceinline__ void cp_commit() { asm volatile("cp.async.commit_group;" ::: "memory"); }
__device__ __forceinline__ void cp_wait0()  { asm volatile("cp.async.wait_group 0;" ::: "memory"); }
__device__ __forceinline__ void cp_wait1()  { asm volatile("cp.async.wait_group 1;" ::: "memory"); }
__device__ __forceinline__ void ldsm4(uint32_t* r, uint32_t addr) {
    asm volatile("ldmatrix.sync.aligned.m8n8.x4.shared.b16 {%0,%1,%2,%3}, [%4];"
                 : "=r"(r[0]), "=r"(r[1]), "=r"(r[2]), "=r"(r[3]) : "r"(addr));
}
__device__ __forceinline__ void mma_bf16(float* c, const uint32_t* a, const uint32_t* b) {
    asm volatile(
        "mma.sync.aligned.m16n8k16.row.col.f32.bf16.bf16.f32 "
        "{%0,%1,%2,%3}, {%4,%5,%6,%7}, {%8,%9}, {%0,%1,%2,%3};"
        : "+f"(c[0]), "+f"(c[1]), "+f"(c[2]), "+f"(c[3])
        : "r"(a[0]), "r"(a[1]), "r"(a[2]), "r"(a[3]), "r"(b[0]), "r"(b[1]));
}

// ---------- bf16 dual-source tensor GEMM (ldmatrix + 3-stage cp.async) ----------
// C[M,N] = A0[M,K0]@W0[N,K0]^T + A1[M,K1]@W1[N,K1]^T (+bias1+bias2+cadd)
// modes: 0 f32 | 2 bf16 | 3 bf16 relu | 4 bf16 = sigmoid(v)*aux(bf16)
//        5 (1-sig(zpre))*aux + sig(zpre)*tanh(v) -> Cf (if set) and/or Cb (if set)

template<int NT>
__global__ __launch_bounds__(256, 2)
void bgemm(const bf16* __restrict__ A0, const bf16* __restrict__ W0, int K0,
           const bf16* __restrict__ A1, const bf16* __restrict__ W1, int K1,
           int N,
           float* __restrict__ Cf, bf16* __restrict__ Cb,
           const float* __restrict__ bias1, const float* __restrict__ bias2,
           float cadd, const bf16* __restrict__ zpre, const bf16* __restrict__ aux,
           int mode)
{
    extern __shared__ char dsm[];
    constexpr int NTI = NT / 32;
    constexpr int STG = (128 + NT) * 144;

    const int tid  = threadIdx.x;
    const int warp = tid >> 5, lane = tid & 31;
    const int grp  = lane >> 2, thr = lane & 3;
    const int wm   = warp & 1,  wn  = warp >> 1;
    const int m_base = wm * 64;
    const int n_base = wn * (NT / 4);
    const int row0 = blockIdx.y * 128;
    const int col0 = blockIdx.x * NT;
    const uint32_t sb = s2u(dsm);

    float acc[4][NTI][4];
#pragma unroll
    for (int i = 0; i < 4; i++)
#pragma unroll
        for (int j = 0; j < NTI; j++)
#pragma unroll
            for (int r = 0; r < 4; r++) acc[i][j][r] = 0.f;

    const int NC0 = K0 >> 6;
    const int NC  = NC0 + (K1 >> 6);

    auto load_stage = [&](int c, int buf) {
        const bf16 *a, *w; int k, kb;
        if (c < NC0) { a = A0; w = W0; k = K0; kb = c << 6; }
        else         { a = A1; w = W1; k = K1; kb = (c - NC0) << 6; }
        uint32_t ab = sb + (uint32_t)buf * STG;
#pragma unroll
        for (int i = 0; i < 4; i++) {
            int u = tid + i * 256;
            int r = u >> 3, cc = u & 7;
            cp16(ab + (uint32_t)(r * 144 + cc * 16),
                 a + (size_t)(row0 + r) * k + kb + cc * 8);
        }
        uint32_t bb = ab + 128u * 144u;
#pragma unroll
        for (int i = 0; i < NT / 32; i++) {
            int u = tid + i * 256;
            int r = u >> 3, cc = u & 7;
            cp16(bb + (uint32_t)(r * 144 + cc * 16),
                 w + (size_t)(col0 + r) * k + kb + cc * 8);
        }
        cp_commit();
    };

    load_stage(0, 0);
    if (NC > 1) load_stage(1, 1);

    for (int c = 0; c < NC; c++) {
        if (c == NC - 1) cp_wait0(); else cp_wait1();
        __syncthreads();
        if (c + 2 < NC) load_stage(c + 2, (c + 2) % 3);

        uint32_t ab = sb + (uint32_t)(c % 3) * STG;
        uint32_t bb = ab + 128u * 144u;

        const uint32_t a_lrow = (uint32_t)(lane & 15);
        const uint32_t a_koff = (uint32_t)((lane >> 4) << 3);
        const uint32_t b_cofs = (uint32_t)(((lane >> 4) << 3) + (lane & 7));
        const uint32_t b_koff = (uint32_t)(((lane >> 3) & 1) << 3);

#pragma unroll
        for (int ks = 0; ks < 4; ks++) {
            const int kc = ks * 16;
            uint32_t af[4][4], bfr[NTI][2];
#pragma unroll
            for (int mt = 0; mt < 4; mt++) {
                uint32_t addr = ab + (uint32_t)(m_base + mt * 16 + a_lrow) * 144u
                                   + (uint32_t)(kc + a_koff) * 2u;
                ldsm4(af[mt], addr);
            }
#pragma unroll
            for (int p = 0; p < NTI / 2; p++) {
                uint32_t col = (uint32_t)(n_base + p * 16) + b_cofs;
                uint32_t addr = bb + col * 144u + (uint32_t)(kc + b_koff) * 2u;
                uint32_t r[4];
                ldsm4(r, addr);
                bfr[2 * p][0]     = r[0]; bfr[2 * p][1]     = r[1];
                bfr[2 * p + 1][0] = r[2]; bfr[2 * p + 1][1] = r[3];
            }
#pragma unroll
            for (int mt = 0; mt < 4; mt++)
#pragma unroll
                for (int nt = 0; nt < NTI; nt++)
                    mma_bf16(acc[mt][nt], af[mt], bfr[nt]);
        }
    }

    // epilogue
#pragma unroll
    for (int mt = 0; mt < 4; mt++) {
#pragma unroll
        for (int nt = 0; nt < NTI; nt++) {
            int cbase = col0 + n_base + nt * 8 + thr * 2;
            float b0 = cadd, b1 = cadd;
            if (bias1) { b0 += bias1[cbase]; b1 += bias1[cbase + 1]; }
            if (bias2) { b0 += bias2[cbase]; b1 += bias2[cbase + 1]; }
#pragma unroll
            for (int half = 0; half < 2; half++) {
                int r = row0 + m_base + mt * 16 + grp + half * 8;
                size_t idx0 = (size_t)r * N + cbase;
#pragma unroll
                for (int e = 0; e < 2; e++) {
                    float v = acc[mt][nt][half * 2 + e] + (e ? b1 : b0);
                    size_t idx = idx0 + e;
                    if (mode == 0) {
                        Cf[idx] = v;
                    } else if (mode == 2) {
                        Cb[idx] = __float2bfloat16(v);
                    } else if (mode == 3) {
                        Cb[idx] = __float2bfloat16(fmaxf(v, 0.f));
                    } else if (mode == 4) {
                        float s = 1.f / (1.f + __expf(-v));
                        Cb[idx] = __float2bfloat16(s * __bfloat162float(aux[idx]));
                    } else {
                        float z = 1.f / (1.f + __expf(-__bfloat162float(zpre[idx])));
                        float o = (1.f - z) * __bfloat162float(aux[idx]) + z * tanhf(v);
                        if (Cf) Cf[idx] = o;
                        if (Cb) Cb[idx] = __float2bfloat16(o);
                    }
                }
            }
        }
    }
}

// ---------- exact fp32 GEMM, 64x64 tiles (critic head) ----------
__global__ void sgemm64_kernel(const float* __restrict__ A, const float* __restrict__ W,
                               float* __restrict__ C, int M, int N, int K,
                               const float* __restrict__ bias, float cadd, int flags)
{
    __shared__ float As[8][64];
    __shared__ float Bs[8][65];
    int tid = threadIdx.x;
    int row0 = blockIdx.y * 64, col0 = blockIdx.x * 64;
    int tx = tid & 15, ty = tid >> 4;
    float acc[4][4];
#pragma unroll
    for (int i = 0; i < 4; i++)
#pragma unroll
        for (int j = 0; j < 4; j++) acc[i][j] = 0.f;

    int ar = tid >> 2, ac2 = (tid & 3) * 2;
    int br = tid >> 5, bc = tid & 31;

    for (int k0 = 0; k0 < K; k0 += 8) {
        float2 a2 = *reinterpret_cast<const float2*>(A + (size_t)(row0 + ar) * K + k0 + ac2);
        As[ac2][ar] = a2.x;
        As[ac2 + 1][ar] = a2.y;
        float w0 = (col0 + bc < N)      ? W[(size_t)(k0 + br) * N + col0 + bc]      : 0.f;
        float w1 = (col0 + bc + 32 < N) ? W[(size_t)(k0 + br) * N + col0 + bc + 32] : 0.f;
        Bs[br][bc] = w0;
        Bs[br][bc + 32] = w1;
        __syncthreads();
#pragma unroll
        for (int kk = 0; kk < 8; kk++) {
            float av[4], bv[4];
#pragma unroll
            for (int i = 0; i < 4; i++) av[i] = As[kk][ty * 4 + i];
#pragma unroll
            for (int j = 0; j < 4; j++) bv[j] = Bs[kk][tx * 4 + j];
#pragma unroll
            for (int i = 0; i < 4; i++)
#pragma unroll
                for (int j = 0; j < 4; j++) acc[i][j] += av[i] * bv[j];
        }
        __syncthreads();
    }
#pragma unroll
    for (int i = 0; i < 4; i++) {
        int r = row0 + ty * 4 + i;
        if (r >= M) continue;
#pragma unroll
        for (int j = 0; j < 4; j++) {
            int c = col0 + tx * 4 + j;
            if (c >= N) continue;
            float val = acc[i][j] + cadd;
            if (bias) val += bias[c];
            size_t idx = (size_t)r * N + c;
            if (flags & 1) val += C[idx];
            if (flags & 2) val = fmaxf(val, 0.f);
            C[idx] = val;
        }
    }
}

// ---------- LayerNorm from f32 input; writes LN out (bf16) + raw bf16 copy ----------
__global__ void ln_kernel(const float* __restrict__ x, bf16* __restrict__ out,
                          bf16* __restrict__ rawb,
                          const float* __restrict__ g, const float* __restrict__ b, int rows)
{
    int warp = blockIdx.x * (blockDim.x >> 5) + (threadIdx.x >> 5);
    if (warp >= rows) return;
    int lane = threadIdx.x & 31;
    const float* xr = x + (size_t)warp * DD;
    float v[16], s1 = 0.f, s2 = 0.f;
#pragma unroll
    for (int i = 0; i < 16; i++) {
        float t = xr[i * 32 + lane];
        v[i] = t; s1 += t; s2 += t * t;
    }
#pragma unroll
    for (int o = 16; o; o >>= 1) {
        s1 += __shfl_xor_sync(0xffffffffu, s1, o);
        s2 += __shfl_xor_sync(0xffffffffu, s2, o);
    }
    float mu = s1 * (1.f / DD);
    float inv = rsqrtf(s2 * (1.f / DD) - mu * mu + 1e-5f);
    bf16* orow = out + (size_t)warp * DD;
    bf16* rrow = rawb ? rawb + (size_t)warp * DD : 0;
#pragma unroll
    for (int i = 0; i < 16; i++) {
        int d = i * 32 + lane;
        orow[d] = __float2bfloat16((v[i] - mu) * inv * g[d] + b[d]);
        if (rrow) rrow[d] = __float2bfloat16(v[i]);
    }
}

// ---------- LayerNorm from bf16 input ----------
__global__ void lnb_kernel(const bf16* __restrict__ x, bf16* __restrict__ out,
                           const float* __restrict__ g, const float* __restrict__ b, int rows)
{
    int warp = blockIdx.x * (blockDim.x >> 5) + (threadIdx.x >> 5);
    if (warp >= rows) return;
    int lane = threadIdx.x & 31;
    const bf16* xr = x + (size_t)warp * DD;
    float v[16], s1 = 0.f, s2 = 0.f;
#pragma unroll
    for (int i = 0; i < 16; i++) {
        float t = __bfloat162float(xr[i * 32 + lane]);
        v[i] = t; s1 += t; s2 += t * t;
    }
#pragma unroll
    for (int o = 16; o; o >>= 1) {
        s1 += __shfl_xor_sync(0xffffffffu, s1, o);
        s2 += __shfl_xor_sync(0xffffffffu, s2, o);
    }
    float mu = s1 * (1.f / DD);
    float inv = rsqrtf(s2 * (1.f / DD) - mu * mu + 1e-5f);
    bf16* orow = out + (size_t)warp * DD;
#pragma unroll
    for (int i = 0; i < 16; i++) {
        int d = i * 32 + lane;
        orow[d] = __float2bfloat16((v[i] - mu) * inv * g[d] + b[d]);
    }
}

// ---------- attention: q/k/v from one fused QKV buffer (src rows then memory rows) ----------
__global__ void attn_kernel(const float* __restrict__ qkv,
                            const float* __restrict__ p, const float* __restrict__ uu,
                            const float* __restrict__ vvec, bf16* __restrict__ av)
{
    int b = blockIdx.x, h = blockIdx.y;
    __shared__ float Ks[JJ][33];
    __shared__ float Vs[JJ][33];
    __shared__ float att[4][JJ];
    __shared__ float qsu[4][32];
    __shared__ float qsv[4][32];
    int tid = threadIdx.x;
    for (int idx = tid; idx < JJ * 32; idx += 128) {
        int j = idx >> 5, d = idx & 31;
        size_t rr = (j < MM) ? ((size_t)NROW + (size_t)j * BB + b)
                             : ((size_t)(j - MM) * BB + b);
        const float* row = qkv + rr * 192 + 64 + h * 32 + d;
        Ks[j][d] = row[0];
        Vs[j][d] = row[64];
    }
    __syncthreads();
    int warp = tid >> 5, lane = tid & 31;
    float ul = uu[h * 32 + lane], vl = vvec[h * 32 + lane];
    for (int i = warp; i < TT; i += 4) {
        float qv = qkv[((size_t)i * BB + b) * 192 + h * 32 + lane];
        qsu[warp][lane] = qv + ul;
        qsv[warp][lane] = qv + vl;
        __syncwarp();
        int jmax = i + MM;
        float sv[5], smax = -1e30f;
        int cnt = 0;
        for (int j = lane; j <= jmax; j += 32) {
            const float* prow = p + (size_t)(j + TT - 1 - i) * 64 + h * 32;
            float s = 0.f;
#pragma unroll
            for (int d = 0; d < 32; d++)
                s += qsu[warp][d] * Ks[j][d] + qsv[warp][d] * prow[d];
            s *= 0.1767766952966369f;
            sv[cnt++] = s;
            smax = fmaxf(smax, s);
        }
#pragma unroll
        for (int o = 16; o; o >>= 1) smax = fmaxf(smax, __shfl_xor_sync(0xffffffffu, smax, o));
        float sum = 0.f; cnt = 0;
        for (int j = lane; j <= jmax; j += 32) {
            float e = __expf(sv[cnt++] - smax);
            att[warp][j] = e;
            sum += e;
        }
#pragma unroll
        for (int o = 16; o; o >>= 1) sum += __shfl_xor_sync(0xffffffffu, sum, o);
        float inv = 1.f / sum;
        __syncwarp();
        float acc = 0.f;
        for (int j = 0; j <= jmax; j++) acc += att[warp][j] * Vs[j][lane];
        av[((size_t)i * BB + b) * 64 + h * 32 + lane] = __float2bfloat16(acc * inv);
        __syncwarp();
    }
}

// ---------- mega prep: all weight transposes + memory convert + pos-emb in ONE launch ----------
__device__ __forceinline__ void tpose_tile(const float* __restrict__ in, bf16* __restrict__ out,
                                           int K, int N)
{
    __shared__ float t[32][33];
    int k0 = blockIdx.y * 32, n0 = blockIdx.x * 32;
    if (k0 >= K || n0 >= N) return;
    int x = threadIdx.x, y = threadIdx.y;
    for (int i = y; i < 32; i += 8)
        t[i][x] = in[(size_t)(k0 + i) * N + n0 + x];
    __syncthreads();
    for (int i = y; i < 32; i += 8)
        out[(size_t)(n0 + i) * K + k0 + x] = __float2bfloat16(t[x][i]);
}

__global__ void megaprep_kernel(const float* __restrict__ g1W, const float* __restrict__ g2W,
                                const float* __restrict__ Wq, const float* __restrict__ Wkv,
                                const float* __restrict__ Wout, const float* __restrict__ ffW1,
                                const float* __restrict__ ffW2, const float* __restrict__ Wp,
                                const float* __restrict__ memory)
{
    int z = blockIdx.z;
    if (z < 12) {
        const float* in = ((z < 6) ? g1W : g2W) + (size_t)(z % 6) * DD * DD;
        bf16* out = ((z < 6) ? gb_g1 : gb_g2) + (size_t)(z % 6) * DD * DD;
        tpose_tile(in, out, DD, DD);
    } else if (z == 12) {
        tpose_tile(Wq, gb_wqkv, DD, 64);
    } else if (z == 13) {
        tpose_tile(Wkv, gb_wqkv + 64 * DD, DD, 128);
    } else if (z == 14) {
        tpose_tile(Wout, gb_wout, 64, DD);
    } else if (z == 15) {
        tpose_tile(ffW1, gb_ff1, DD, DFF);
    } else if (z == 16) {
        tpose_tile(ffW2, gb_ff2, DFF, DD);
    } else if (z == 17) {
        // memory f32 -> bf16 into the tail of gb_lnm
        int bid = blockIdx.y * 16 + blockIdx.x;
        int tid = threadIdx.y * 32 + threadIdx.x;
        const int n4 = MROW * DD / 4;
        bf16* dst = gb_lnm + (size_t)NROW * DD;
        for (int i = bid * 256 + tid; i < n4; i += 256 * 256) {
            float4 v = reinterpret_cast<const float4*>(memory)[i];
            __nv_bfloat162* o = reinterpret_cast<__nv_bfloat162*>(dst + (size_t)i * 4);
            o[0] = __floats2bfloat162_rn(v.x, v.y);
            o[1] = __floats2bfloat162_rn(v.z, v.w);
        }
    } else {
        // pos-emb @ W_p: one block per jj
        int jj = blockIdx.y * 16 + blockIdx.x;
        if (jj >= JJ) return;
        __shared__ float pe[DD];
        int tid = threadIdx.y * 32 + threadIdx.x;
        float pos = (float)(JJ - 1 - jj);
        for (int d = tid; d < DD; d += 256) {
            int i = (d < 256) ? d : d - 256;
            float f = __expf(-(float)(2 * i) * (1.f / 512.f) * 9.210340371976184f);
            float a = pos * f;
            pe[d] = (d < 256) ? sinf(a) : cosf(a);
        }
        __syncthreads();
        if (tid < 64) {
            float acc = 0.f;
            for (int d = 0; d < DD; d++) acc += pe[d] * Wp[d * 64 + tid];
            g_p[jj * 64 + tid] = acc;
        }
    }
}

// ---------- mean pool (vectorized) ----------
__global__ void meanpool_kernel(const float4* __restrict__ in, float4* __restrict__ ts)
{
    int idx = blockIdx.x * blockDim.x + threadIdx.x;
    const int n4 = BB * DD / 4;
    if (idx >= n4) return;
    float4 s = make_float4(0.f, 0.f, 0.f, 0.f);
    for (int t = 0; t < TT; t++) {
        float4 v = in[(size_t)t * n4 + idx];
        s.x += v.x; s.y += v.y; s.z += v.z; s.w += v.w;
    }
    const float inv = 1.f / TT;
    s.x *= inv; s.y *= inv; s.z *= inv; s.w *= inv;
    ts[idx] = s;
}

// ---------- final head ----------
__global__ void final_kernel(const float* __restrict__ h3, const float* __restrict__ w,
                             const float* __restrict__ bb, float* __restrict__ out)
{
    int row = blockIdx.x * 4 + (threadIdx.x >> 5);
    int lane = threadIdx.x & 31;
    if (row >= BB) return;
    float s = 0.f;
    for (int k = lane; k < 300; k += 32) s += h3[(size_t)row * 300 + k] * w[k];
#pragma unroll
    for (int o = 16; o; o >>= 1) s += __shfl_xor_sync(0xffffffffu, s, o);
    if (lane == 0) out[row] = fmaxf(s + bb[0], 0.f);
}

// ---------- host ----------
static inline void launch_tc(const bf16* A0, const bf16* W0, int K0,
                             const bf16* A1, const bf16* W1, int K1,
                             int M, int N, int NT,
                             float* Cf, bf16* Cb,
                             const float* b1, const float* b2, float cadd,
                             const bf16* zpre, const bf16* aux, int mode)
{
    dim3 grid(N / NT, M / 128);
    if (NT == 128) {
        size_t dsz = 3 * (size_t)(128 + 128) * 144;
        bgemm<128><<<grid, 256, dsz>>>(A0, W0, K0, A1, W1, K1, N, Cf, Cb, b1, b2, cadd, zpre, aux, mode);
    } else {
        size_t dsz = 3 * (size_t)(128 + 64) * 144;
        bgemm<64><<<grid, 256, dsz>>>(A0, W0, K0, A1, W1, K1, N, Cf, Cb, b1, b2, cadd, zpre, aux, mode);
    }
}
static inline void launch_sgemm(const float* A, const float* W, float* C,
                                int M, int N, int K, const float* bias, float cadd, int flags)
{
    dim3 grid((N + 63) / 64, (M + 63) / 64);
    sgemm64_kernel<<<grid, 256>>>(A, W, C, M, N, K, bias, cadd, flags);
}

extern "C" void kernel_launch(void* const* d_in, const int* in_sizes, int n_in,
                              void* d_out, int out_size)
{
    const float* x      = (const float*)d_in[0];
    const float* action = (const float*)d_in[1];
    const float* memory = (const float*)d_in[2];
    const float* W_q    = (const float*)d_in[3];
    const float* W_kv   = (const float*)d_in[4];
    const float* W_p    = (const float*)d_in[5];
    const float* W_out  = (const float*)d_in[6];
    const float* u      = (const float*)d_in[7];
    const float* v      = (const float*)d_in[8];
    const float* ln1_g  = (const float*)d_in[9];
    const float* ln1_b  = (const float*)d_in[10];
    const float* ln2_g  = (const float*)d_in[11];
    const float* ln2_b  = (const float*)d_in[12];
    const float* ff_W1  = (const float*)d_in[13];
    const float* ff_b1  = (const float*)d_in[14];
    const float* ff_W2  = (const float*)d_in[15];
    const float* ff_b2  = (const float*)d_in[16];
    const float* g1W    = (const float*)d_in[17];
    const float* g1b    = (const float*)d_in[18];
    const float* g2W    = (const float*)d_in[19];
    const float* g2b    = (const float*)d_in[20];
    const float* d1W    = (const float*)d_in[21];
    const float* d1b    = (const float*)d_in[22];
    const float* d2W    = (const float*)d_in[23];
    const float* d2b    = (const float*)d_in[24];
    const float* d3W    = (const float*)d_in[25];
    const float* d3b    = (const float*)d_in[26];
    const float* d4W    = (const float*)d_in[27];
    const float* d4b    = (const float*)d_in[28];

    cudaFuncSetAttribute(bgemm<128>, cudaFuncAttributeMaxDynamicSharedMemorySize, 111000);
    cudaFuncSetAttribute(bgemm<64>,  cudaFuncAttributeMaxDynamicSharedMemorySize, 84000);

    float *B1, *QKV, *P, *TS, *H1, *H2, *H3;
    bf16 *XB, *LNM, *YB, *RXB, *ZB, *SRCB, *FFHB, *AVB;
    bf16 *WQKVT, *WOUTT, *G1T, *G2T, *FF1T, *FF2T;
    cudaGetSymbolAddress((void**)&B1,   g_B1);
    cudaGetSymbolAddress((void**)&QKV,  g_qkv);
    cudaGetSymbolAddress((void**)&P,    g_p);
    cudaGetSymbolAddress((void**)&TS,   g_ts);
    cudaGetSymbolAddress((void**)&H1,   g_h1);
    cudaGetSymbolAddress((void**)&H2,   g_h2);
    cudaGetSymbolAddress((void**)&H3,   g_h3);
    cudaGetSymbolAddress((void**)&XB,   gb_x);
    cudaGetSymbolAddress((void**)&LNM,  gb_lnm);
    cudaGetSymbolAddress((void**)&YB,   gb_y);
    cudaGetSymbolAddress((void**)&RXB,  gb_rx);
    cudaGetSymbolAddress((void**)&ZB,   gb_z);
    cudaGetSymbolAddress((void**)&SRCB, gb_src);
    cudaGetSymbolAddress((void**)&FFHB, gb_ffh);
    cudaGetSymbolAddress((void**)&AVB,  gb_av);
    cudaGetSymbolAddress((void**)&WQKVT,gb_wqkv);
    cudaGetSymbolAddress((void**)&WOUTT,gb_wout);
    cudaGetSymbolAddress((void**)&G1T,  gb_g1);
    cudaGetSymbolAddress((void**)&G2T,  gb_g2);
    cudaGetSymbolAddress((void**)&FF1T, gb_ff1);
    cudaGetSymbolAddress((void**)&FF2T, gb_ff2);

    const size_t SZ = (size_t)DD * DD;

    // launch 0: ALL prep (12 gate transposes, 5 small transposes, memory cvt, pos-emb)
    megaprep_kernel<<<dim3(16, 16, 19), dim3(32, 8)>>>(
        g1W, g2W, W_q, W_kv, W_out, ff_W1, ff_W2, W_p, memory);

    // launch 1: LN1 -> LNM rows [0,NROW); also writes XB = bf16(x)
    ln_kernel<<<NROW / 8, 256>>>(x, LNM, XB, ln1_g, ln1_b, NROW);

    // launch 2: fused qkv over src+memory rows (M=68608, N=192)
    launch_tc(LNM, WQKVT, DD, 0, 0, 0, AROW, 192, 64, QKV, 0, 0, 0, 0.f, 0, 0, 0);

    // launch 3: attention -> AVB (bf16)
    attn_kernel<<<dim3(BB, HH), 128>>>(QKV, P, u, v, AVB);

    // launch 4: y = av @ W_out -> YB (bf16)
    launch_tc(AVB, WOUTT, 64, 0, 0, 0, NROW, DD, 128, 0, YB, 0, 0, 0.f, 0, 0, 2);

    // launch 5 (ncu capture target): gate 1 r*x
    launch_tc(YB, G1T + 0 * SZ, DD, XB, G1T + 1 * SZ, DD, NROW, DD, 128,
              0, RXB, g1b + 0 * DD, g1b + 1 * DD, 0.f, 0, XB, 4);
    // gate 1 z-pre
    launch_tc(YB, G1T + 2 * SZ, DD, XB, G1T + 3 * SZ, DD, NROW, DD, 128,
              0, ZB, g1b + 2 * DD, g1b + 3 * DD, -BG, 0, 0, 2);
    // gate 1 combine -> SRCB (bf16 only)
    launch_tc(YB, G1T + 4 * SZ, DD, RXB, G1T + 5 * SZ, DD, NROW, DD, 128,
              0, SRCB, g1b + 4 * DD, g1b + 5 * DD, 0.f, ZB, XB, 5);

    // ff = relu(LN2(src)@W1+b1)@W2+b2 -> XB (x/XB no longer needed as input)
    lnb_kernel<<<NROW / 8, 256>>>(SRCB, LNM, ln2_g, ln2_b, NROW);
    launch_tc(LNM, FF1T, DD, 0, 0, 0, NROW, DFF, 64, 0, FFHB, ff_b1, 0, 0.f, 0, 0, 3);
    launch_tc(FFHB, FF2T, DFF, 0, 0, 0, NROW, DD, 128, 0, XB, ff_b2, 0, 0.f, 0, 0, 2);

    // gate 2
    launch_tc(XB, G2T + 0 * SZ, DD, SRCB, G2T + 1 * SZ, DD, NROW, DD, 128,
              0, RXB, g2b + 0 * DD, g2b + 1 * DD, 0.f, 0, SRCB, 4);
    launch_tc(XB, G2T + 2 * SZ, DD, SRCB, G2T + 3 * SZ, DD, NROW, DD, 128,
              0, ZB, g2b + 2 * DD, g2b + 3 * DD, -BG, 0, 0, 2);
    launch_tc(XB, G2T + 4 * SZ, DD, RXB, G2T + 5 * SZ, DD, NROW, DD, 128,
              B1, 0, g2b + 4 * DD, g2b + 5 * DD, 0.f, ZB, SRCB, 5);

    // mean pool
    meanpool_kernel<<<(BB * DD / 4 + 255) / 256, 256>>>((const float4*)B1, (float4*)TS);

    // critic head (exact fp32)
    launch_sgemm(TS, d1W, H1, BB, 1024, DD, d1b, 0.f, 2);
    launch_sgemm(H1, d2W, H2, BB, 512, 1024, nullptr, 0.f, 0);
    launch_sgemm(action, d2W + (size_t)1024 * 512, H2, BB, 512, ACT, d2b, 0.f, 3);
    launch_sgemm(H2, d3W, H3, BB, 300, DD, d3b, 0.f, 2);
    final_kernel<<<BB / 4, 128>>>(H3, d4W, d4b, (float*)d_out);
}

// round 12
// speedup vs baseline: 1.2069x; 1.1822x over previous
#include <cuda_runtime.h>
#include <cuda_bf16.h>
#include <math.h>
#include <stdint.h>

#define TT   128
#define BB   512
#define DD   512
#define MM   6
#define JJ   (TT + MM)
#define HH   2
#define DFF  64
#define ACT  64
#define NROW (TT * BB)
#define MROW (MM * BB)
#define AROW (NROW + MROW)      // 68608
#define BG   0.1f

typedef __nv_bfloat16 bf16;

// ---------- static scratch ----------
__device__ __align__(256) float g_B1[NROW * DD];
__device__ __align__(256) float g_qkv[AROW * 192];
__device__ __align__(256) float g_p  [JJ * 64];
__device__ __align__(256) float g_ts [BB * DD];
__device__ __align__(256) float g_h1 [BB * 1024];
__device__ __align__(256) float g_h2 [BB * 512];
__device__ __align__(256) float g_h3 [BB * 300];
__device__ __align__(256) float g_bc2[3 * DD];              // gate2 combined biases
__device__ __align__(256) bf16 gb_x   [NROW * DD];
__device__ __align__(256) bf16 gb_lnm [AROW * DD];
__device__ __align__(256) bf16 gb_rx  [NROW * DD];
__device__ __align__(256) bf16 gb_z   [NROW * DD];
__device__ __align__(256) bf16 gb_src [NROW * DD];
__device__ __align__(256) bf16 gb_ffh [NROW * DFF];
__device__ __align__(256) bf16 gb_av  [NROW * 64];
__device__ __align__(256) bf16 gb_wqkv[192 * DD];
__device__ __align__(256) bf16 gb_g1  [6 * DD * DD];
__device__ __align__(256) bf16 gb_g2  [6 * DD * DD];
__device__ __align__(256) bf16 gb_ff1 [DFF * DD];
__device__ __align__(256) bf16 gb_cw  [6 * DD * 64];        // folded y-side weights, [n][k]

// ---------- helpers ----------
__device__ __forceinline__ uint32_t s2u(const void* p) {
    return (uint32_t)__cvta_generic_to_shared(p);
}
__device__ __forceinline__ void cp16(uint32_t s, const void* g) {
    asm volatile("cp.async.cg.shared.global [%0], [%1], 16;" :: "r"(s), "l"(g));
}
__device__ __forceinline__ void cp_commit() { asm volatile("cp.async.commit_group;" ::: "memory"); }
__device__ __forceinline__ void cp_wait0()  { asm volatile("cp.async.wait_group 0;" ::: "memory"); }
__device__ __forceinline__ void cp_wait1()  { asm volatile("cp.async.wait_group 1;" ::: "memory"); }
__device__ __forceinline__ void ldsm4(uint32_t* r, uint32_t addr) {
    asm volatile("ldmatrix.sync.aligned.m8n8.x4.shared.b16 {%0,%1,%2,%3}, [%4];"
                 : "=r"(r[0]), "=r"(r[1]), "=r"(r[2]), "=r"(r[3]) : "r"(addr));
}
__device__ __forceinline__ void mma_bf16(float* c, const uint32_t* a, const uint32_t* b) {
    asm volatile(
        "mma.sync.aligned.m16n8k16.row.col.f32.bf16.bf16.f32 "
        "{%0,%1,%2,%3}, {%4,%5,%6,%7}, {%8,%9}, {%0,%1,%2,%3};"
        : "+f"(c[0]), "+f"(c[1]), "+f"(c[2]), "+f"(c[3])
        : "r"(a[0]), "r"(a[1]), "r"(a[2]), "r"(a[3]), "r"(b[0]), "r"(b[1]));
}

// ---------- bf16 dual-source tensor GEMM (ldmatrix + 3-stage cp.async) ----------
// C[M,N] = A0[M,K0]@W0[N,K0]^T + A1[M,K1]@W1[N,K1]^T (+bias1+bias2+cadd)
// modes: 0 f32 | 2 bf16 | 3 bf16 relu | 4 bf16 = sigmoid(v)*aux(bf16)
//        5 (1-sig(zpre))*aux + sig(zpre)*tanh(v) -> Cf and/or Cb

template<int NT>
__global__ __launch_bounds__(256, 2)
void bgemm(const bf16* __restrict__ A0, const bf16* __restrict__ W0, int K0,
           const bf16* __restrict__ A1, const bf16* __restrict__ W1, int K1,
           int N,
           float* __restrict__ Cf, bf16* __restrict__ Cb,
           const float* __restrict__ bias1, const float* __restrict__ bias2,
           float cadd, const bf16* __restrict__ zpre, const bf16* __restrict__ aux,
           int mode)
{
    extern __shared__ char dsm[];
    constexpr int NTI = NT / 32;
    constexpr int STG = (128 + NT) * 144;

    const int tid  = threadIdx.x;
    const int warp = tid >> 5, lane = tid & 31;
    const int grp  = lane >> 2, thr = lane & 3;
    const int wm   = warp & 1,  wn  = warp >> 1;
    const int m_base = wm * 64;
    const int n_base = wn * (NT / 4);
    const int row0 = blockIdx.y * 128;
    const int col0 = blockIdx.x * NT;
    const uint32_t sb = s2u(dsm);

    float acc[4][NTI][4];
#pragma unroll
    for (int i = 0; i < 4; i++)
#pragma unroll
        for (int j = 0; j < NTI; j++)
#pragma unroll
            for (int r = 0; r < 4; r++) acc[i][j][r] = 0.f;

    const int NC0 = K0 >> 6;
    const int NC  = NC0 + (K1 >> 6);

    auto load_stage = [&](int c, int buf) {
        const bf16 *a, *w; int k, kb;
        if (c < NC0) { a = A0; w = W0; k = K0; kb = c << 6; }
        else         { a = A1; w = W1; k = K1; kb = (c - NC0) << 6; }
        uint32_t ab = sb + (uint32_t)buf * STG;
#pragma unroll
        for (int i = 0; i < 4; i++) {
            int u = tid + i * 256;
            int r = u >> 3, cc = u & 7;
            cp16(ab + (uint32_t)(r * 144 + cc * 16),
                 a + (size_t)(row0 + r) * k + kb + cc * 8);
        }
        uint32_t bb = ab + 128u * 144u;
#pragma unroll
        for (int i = 0; i < NT / 32; i++) {
            int u = tid + i * 256;
            int r = u >> 3, cc = u & 7;
            cp16(bb + (uint32_t)(r * 144 + cc * 16),
                 w + (size_t)(col0 + r) * k + kb + cc * 8);
        }
        cp_commit();
    };

    load_stage(0, 0);
    if (NC > 1) load_stage(1, 1);

    for (int c = 0; c < NC; c++) {
        if (c == NC - 1) cp_wait0(); else cp_wait1();
        __syncthreads();
        if (c + 2 < NC) load_stage(c + 2, (c + 2) % 3);

        uint32_t ab = sb + (uint32_t)(c % 3) * STG;
        uint32_t bb = ab + 128u * 144u;

        const uint32_t a_lrow = (uint32_t)(lane & 15);
        const uint32_t a_koff = (uint32_t)((lane >> 4) << 3);
        const uint32_t b_cofs = (uint32_t)(((lane >> 4) << 3) + (lane & 7));
        const uint32_t b_koff = (uint32_t)(((lane >> 3) & 1) << 3);

#pragma unroll
        for (int ks = 0; ks < 4; ks++) {
            const int kc = ks * 16;
            uint32_t af[4][4], bfr[NTI][2];
#pragma unroll
            for (int mt = 0; mt < 4; mt++) {
                uint32_t addr = ab + (uint32_t)(m_base + mt * 16 + a_lrow) * 144u
                                   + (uint32_t)(kc + a_koff) * 2u;
                ldsm4(af[mt], addr);
            }
#pragma unroll
            for (int p = 0; p < NTI / 2; p++) {
                uint32_t col = (uint32_t)(n_base + p * 16) + b_cofs;
                uint32_t addr = bb + col * 144u + (uint32_t)(kc + b_koff) * 2u;
                uint32_t r[4];
                ldsm4(r, addr);
                bfr[2 * p][0]     = r[0]; bfr[2 * p][1]     = r[1];
                bfr[2 * p + 1][0] = r[2]; bfr[2 * p + 1][1] = r[3];
            }
#pragma unroll
            for (int mt = 0; mt < 4; mt++)
#pragma unroll
                for (int nt = 0; nt < NTI; nt++)
                    mma_bf16(acc[mt][nt], af[mt], bfr[nt]);
        }
    }

    // epilogue
#pragma unroll
    for (int mt = 0; mt < 4; mt++) {
#pragma unroll
        for (int nt = 0; nt < NTI; nt++) {
            int cbase = col0 + n_base + nt * 8 + thr * 2;
            float b0 = cadd, b1 = cadd;
            if (bias1) { b0 += bias1[cbase]; b1 += bias1[cbase + 1]; }
            if (bias2) { b0 += bias2[cbase]; b1 += bias2[cbase + 1]; }
#pragma unroll
            for (int half = 0; half < 2; half++) {
                int r = row0 + m_base + mt * 16 + grp + half * 8;
                size_t idx0 = (size_t)r * N + cbase;
#pragma unroll
                for (int e = 0; e < 2; e++) {
                    float v = acc[mt][nt][half * 2 + e] + (e ? b1 : b0);
                    size_t idx = idx0 + e;
                    if (mode == 0) {
                        Cf[idx] = v;
                    } else if (mode == 2) {
                        Cb[idx] = __float2bfloat16(v);
                    } else if (mode == 3) {
                        Cb[idx] = __float2bfloat16(fmaxf(v, 0.f));
                    } else if (mode == 4) {
                        float s = 1.f / (1.f + __expf(-v));
                        Cb[idx] = __float2bfloat16(s * __bfloat162float(aux[idx]));
                    } else {
                        float z = 1.f / (1.f + __expf(-__bfloat162float(zpre[idx])));
                        float o = (1.f - z) * __bfloat162float(aux[idx]) + z * tanhf(v);
                        if (Cf) Cf[idx] = o;
                        if (Cb) Cb[idx] = __float2bfloat16(o);
                    }
                }
            }
        }
    }
}

// ---------- exact fp32 GEMM, 64x64 tiles (critic head) ----------
__global__ void sgemm64_kernel(const float* __restrict__ A, const float* __restrict__ W,
                               float* __restrict__ C, int M, int N, int K,
                               const float* __restrict__ bias, float cadd, int flags)
{
    __shared__ float As[8][64];
    __shared__ float Bs[8][65];
    int tid = threadIdx.x;
    int row0 = blockIdx.y * 64, col0 = blockIdx.x * 64;
    int tx = tid & 15, ty = tid >> 4;
    float acc[4][4];
#pragma unroll
    for (int i = 0; i < 4; i++)
#pragma unroll
        for (int j = 0; j < 4; j++) acc[i][j] = 0.f;

    int ar = tid >> 2, ac2 = (tid & 3) * 2;
    int br = tid >> 5, bc = tid & 31;

    for (int k0 = 0; k0 < K; k0 += 8) {
        float2 a2 = *reinterpret_cast<const float2*>(A + (size_t)(row0 + ar) * K + k0 + ac2);
        As[ac2][ar] = a2.x;
        As[ac2 + 1][ar] = a2.y;
        float w0 = (col0 + bc < N)      ? W[(size_t)(k0 + br) * N + col0 + bc]      : 0.f;
        float w1 = (col0 + bc + 32 < N) ? W[(size_t)(k0 + br) * N + col0 + bc + 32] : 0.f;
        Bs[br][bc] = w0;
        Bs[br][bc + 32] = w1;
        __syncthreads();
#pragma unroll
        for (int kk = 0; kk < 8; kk++) {
            float av[4], bv[4];
#pragma unroll
            for (int i = 0; i < 4; i++) av[i] = As[kk][ty * 4 + i];
#pragma unroll
            for (int j = 0; j < 4; j++) bv[j] = Bs[kk][tx * 4 + j];
#pragma unroll
            for (int i = 0; i < 4; i++)
#pragma unroll
                for (int j = 0; j < 4; j++) acc[i][j] += av[i] * bv[j];
        }
        __syncthreads();
    }
#pragma unroll
    for (int i = 0; i < 4; i++) {
        int r = row0 + ty * 4 + i;
        if (r >= M) continue;
#pragma unroll
        for (int j = 0; j < 4; j++) {
            int c = col0 + tx * 4 + j;
            if (c >= N) continue;
            float val = acc[i][j] + cadd;
            if (bias) val += bias[c];
            size_t idx = (size_t)r * N + c;
            if (flags & 1) val += C[idx];
            if (flags & 2) val = fmaxf(val, 0.f);
            C[idx] = val;
        }
    }
}

// ---------- LayerNorm from f32; writes LN out (bf16) + raw bf16 copy ----------
__global__ void ln_kernel(const float* __restrict__ x, bf16* __restrict__ out,
                          bf16* __restrict__ rawb,
                          const float* __restrict__ g, const float* __restrict__ b, int rows)
{
    int warp = blockIdx.x * (blockDim.x >> 5) + (threadIdx.x >> 5);
    if (warp >= rows) return;
    int lane = threadIdx.x & 31;
    const float* xr = x + (size_t)warp * DD;
    float v[16], s1 = 0.f, s2 = 0.f;
#pragma unroll
    for (int i = 0; i < 16; i++) {
        float t = xr[i * 32 + lane];
        v[i] = t; s1 += t; s2 += t * t;
    }
#pragma unroll
    for (int o = 16; o; o >>= 1) {
        s1 += __shfl_xor_sync(0xffffffffu, s1, o);
        s2 += __shfl_xor_sync(0xffffffffu, s2, o);
    }
    float mu = s1 * (1.f / DD);
    float inv = rsqrtf(s2 * (1.f / DD) - mu * mu + 1e-5f);
    bf16* orow = out + (size_t)warp * DD;
    bf16* rrow = rawb ? rawb + (size_t)warp * DD : 0;
#pragma unroll
    for (int i = 0; i < 16; i++) {
        int d = i * 32 + lane;
        orow[d] = __float2bfloat16((v[i] - mu) * inv * g[d] + b[d]);
        if (rrow) rrow[d] = __float2bfloat16(v[i]);
    }
}

// ---------- LayerNorm from bf16 input ----------
__global__ void lnb_kernel(const bf16* __restrict__ x, bf16* __restrict__ out,
                           const float* __restrict__ g, const float* __restrict__ b, int rows)
{
    int warp = blockIdx.x * (blockDim.x >> 5) + (threadIdx.x >> 5);
    if (warp >= rows) return;
    int lane = threadIdx.x & 31;
    const bf16* xr = x + (size_t)warp * DD;
    float v[16], s1 = 0.f, s2 = 0.f;
#pragma unroll
    for (int i = 0; i < 16; i++) {
        float t = __bfloat162float(xr[i * 32 + lane]);
        v[i] = t; s1 += t; s2 += t * t;
    }
#pragma unroll
    for (int o = 16; o; o >>= 1) {
        s1 += __shfl_xor_sync(0xffffffffu, s1, o);
        s2 += __shfl_xor_sync(0xffffffffu, s2, o);
    }
    float mu = s1 * (1.f / DD);
    float inv = rsqrtf(s2 * (1.f / DD) - mu * mu + 1e-5f);
    bf16* orow = out + (size_t)warp * DD;
#pragma unroll
    for (int i = 0; i < 16; i++) {
        int d = i * 32 + lane;
        orow[d] = __float2bfloat16((v[i] - mu) * inv * g[d] + b[d]);
    }
}

// ---------- attention ----------
__global__ void attn_kernel(const float* __restrict__ qkv,
                            const float* __restrict__ p, const float* __restrict__ uu,
                            const float* __restrict__ vvec, bf16* __restrict__ av)
{
    int b = blockIdx.x, h = blockIdx.y;
    __shared__ float Ks[JJ][33];
    __shared__ float Vs[JJ][33];
    __shared__ float att[4][JJ];
    __shared__ float qsu[4][32];
    __shared__ float qsv[4][32];
    int tid = threadIdx.x;
    for (int idx = tid; idx < JJ * 32; idx += 128) {
        int j = idx >> 5, d = idx & 31;
        size_t rr = (j < MM) ? ((size_t)NROW + (size_t)j * BB + b)
                             : ((size_t)(j - MM) * BB + b);
        const float* row = qkv + rr * 192 + 64 + h * 32 + d;
        Ks[j][d] = row[0];
        Vs[j][d] = row[64];
    }
    __syncthreads();
    int warp = tid >> 5, lane = tid & 31;
    float ul = uu[h * 32 + lane], vl = vvec[h * 32 + lane];
    for (int i = warp; i < TT; i += 4) {
        float qv = qkv[((size_t)i * BB + b) * 192 + h * 32 + lane];
        qsu[warp][lane] = qv + ul;
        qsv[warp][lane] = qv + vl;
        __syncwarp();
        int jmax = i + MM;
        float sv[5], smax = -1e30f;
        int cnt = 0;
        for (int j = lane; j <= jmax; j += 32) {
            const float* prow = p + (size_t)(j + TT - 1 - i) * 64 + h * 32;
            float s = 0.f;
#pragma unroll
            for (int d = 0; d < 32; d++)
                s += qsu[warp][d] * Ks[j][d] + qsv[warp][d] * prow[d];
            s *= 0.1767766952966369f;
            sv[cnt++] = s;
            smax = fmaxf(smax, s);
        }
#pragma unroll
        for (int o = 16; o; o >>= 1) smax = fmaxf(smax, __shfl_xor_sync(0xffffffffu, smax, o));
        float sum = 0.f; cnt = 0;
        for (int j = lane; j <= jmax; j += 32) {
            float e = __expf(sv[cnt++] - smax);
            att[warp][j] = e;
            sum += e;
        }
#pragma unroll
        for (int o = 16; o; o >>= 1) sum += __shfl_xor_sync(0xffffffffu, sum, o);
        float inv = 1.f / sum;
        __syncwarp();
        float acc = 0.f;
        for (int j = 0; j <= jmax; j++) acc += att[warp][j] * Vs[j][lane];
        av[((size_t)i * BB + b) * 64 + h * 32 + lane] = __float2bfloat16(acc * inv);
        __syncwarp();
    }
}

// ---------- mega prep ----------
__device__ __forceinline__ void tpose_tile(const float* __restrict__ in, bf16* __restrict__ out,
                                           int K, int N)
{
    __shared__ float t[32][33];
    int k0 = blockIdx.y * 32, n0 = blockIdx.x * 32;
    if (k0 >= K || n0 >= N) return;
    int x = threadIdx.x, y = threadIdx.y;
    for (int i = y; i < 32; i += 8)
        t[i][x] = in[(size_t)(k0 + i) * N + n0 + x];
    __syncthreads();
    for (int i = y; i < 32; i += 8)
        out[(size_t)(n0 + i) * K + k0 + x] = __float2bfloat16(t[x][i]);
}

__global__ void megaprep_kernel(const float* __restrict__ g1W, const float* __restrict__ g2W,
                                const float* __restrict__ Wq, const float* __restrict__ Wkv,
                                const float* __restrict__ ffW1, const float* __restrict__ Wp,
                                const float* __restrict__ memory)
{
    int z = blockIdx.z;
    if (z < 12) {
        const float* in = ((z < 6) ? g1W : g2W) + (size_t)(z % 6) * DD * DD;
        bf16* out = ((z < 6) ? gb_g1 : gb_g2) + (size_t)(z % 6) * DD * DD;
        tpose_tile(in, out, DD, DD);
    } else if (z == 12) {
        tpose_tile(Wq, gb_wqkv, DD, 64);
    } else if (z == 13) {
        tpose_tile(Wkv, gb_wqkv + 64 * DD, DD, 128);
    } else if (z == 14) {
        tpose_tile(ffW1, gb_ff1, DD, DFF);
    } else if (z == 15) {
        int bid = blockIdx.y * 16 + blockIdx.x;
        int tid = threadIdx.y * 32 + threadIdx.x;
        const int n4 = MROW * DD / 4;
        bf16* dst = gb_lnm + (size_t)NROW * DD;
        for (int i = bid * 256 + tid; i < n4; i += 256 * 256) {
            float4 v = reinterpret_cast<const float4*>(memory)[i];
            __nv_bfloat162* o = reinterpret_cast<__nv_bfloat162*>(dst + (size_t)i * 4);
            o[0] = __floats2bfloat162_rn(v.x, v.y);
            o[1] = __floats2bfloat162_rn(v.z, v.w);
        }
    } else {
        int jj = blockIdx.y * 16 + blockIdx.x;
        if (jj >= JJ) return;
        __shared__ float pe[DD];
        int tid = threadIdx.y * 32 + threadIdx.x;
        float pos = (float)(JJ - 1 - jj);
        for (int d = tid; d < DD; d += 256) {
            int i = (d < 256) ? d : d - 256;
            float f = __expf(-(float)(2 * i) * (1.f / 512.f) * 9.210340371976184f);
            float a = pos * f;
            pe[d] = (d < 256) ? sinf(a) : cosf(a);
        }
        __syncthreads();
        if (tid < 64) {
            float acc = 0.f;
            for (int d = 0; d < DD; d++) acc += pe[d] * Wp[d * 64 + tid];
            g_p[jj * 64 + tid] = acc;
        }
    }
}

// ---------- folded-weight precompute: CW[m] = (A · G_slot)^T, bf16 [512n × 64k] ----------
// m 0..2: A = W_out [64x512], G = g1W slot {0,2,4};  m 3..5: A = ff_W2 [64x512], G = g2W slot {0,2,4}
__global__ void pregemm_kernel(const float* __restrict__ Wout, const float* __restrict__ ffW2,
                               const float* __restrict__ g1W, const float* __restrict__ g2W)
{
    __shared__ float sG[64][33];
    const int slot[3] = {0, 2, 4};
    int m = blockIdx.z;
    const float* A = (m < 3) ? Wout : ffW2;
    const float* G = ((m < 3) ? g1W : g2W) + (size_t)slot[m % 3] * DD * DD;
    bf16* out = gb_cw + (size_t)m * DD * 64;
    int n0 = blockIdx.x * 32, k0 = blockIdx.y * 8;
    int tx = threadIdx.x, ty = threadIdx.y;
    int tid = ty * 32 + tx;
    float acc = 0.f;
    for (int dc = 0; dc < 8; dc++) {
        __syncthreads();
        for (int idx = tid; idx < 64 * 32; idx += 256) {
            int i = idx >> 5, j = idx & 31;
            sG[i][j] = G[(size_t)(dc * 64 + i) * DD + n0 + j];
        }
        __syncthreads();
        const float* Ar = A + (size_t)(k0 + ty) * DD + dc * 64;
#pragma unroll 16
        for (int i = 0; i < 64; i++) acc += Ar[i] * sG[i][tx];
    }
    out[(size_t)(n0 + tx) * 64 + (k0 + ty)] = __float2bfloat16(acc);
}

// ---------- gate-2 combined bias: bc2[m] = g2b[2m] + g2b[2m+1] + ff_b2 @ g2W[slot m] ----------
__global__ void bc2_kernel(const float* __restrict__ ffb2, const float* __restrict__ g2W,
                           const float* __restrict__ g2b, float* __restrict__ bc)
{
    const int slot[3] = {0, 2, 4};
    int m = blockIdx.x;
    int n = threadIdx.x;
    const float* G = g2W + (size_t)slot[m] * DD * DD;
    float acc = g2b[(2 * m) * DD + n] + g2b[(2 * m + 1) * DD + n];
    for (int d = 0; d < DD; d++) acc += ffb2[d] * G[(size_t)d * DD + n];
    bc[m * DD + n] = acc;
}

// ---------- mean pool ----------
__global__ void meanpool_kernel(const float4* __restrict__ in, float4* __restrict__ ts)
{
    int idx = blockIdx.x * blockDim.x + threadIdx.x;
    const int n4 = BB * DD / 4;
    if (idx >= n4) return;
    float4 s = make_float4(0.f, 0.f, 0.f, 0.f);
    for (int t = 0; t < TT; t++) {
        float4 v = in[(size_t)t * n4 + idx];
        s.x += v.x; s.y += v.y; s.z += v.z; s.w += v.w;
    }
    const float inv = 1.f / TT;
    s.x *= inv; s.y *= inv; s.z *= inv; s.w *= inv;
    ts[idx] = s;
}

// ---------- final head ----------
__global__ void final_kernel(const float* __restrict__ h3, const float* __restrict__ w,
                             const float* __restrict__ bb, float* __restrict__ out)
{
    int row = blockIdx.x * 4 + (threadIdx.x >> 5);
    int lane = threadIdx.x & 31;
    if (row >= BB) return;
    float s = 0.f;
    for (int k = lane; k < 300; k += 32) s += h3[(size_t)row * 300 + k] * w[k];
#pragma unroll
    for (int o = 16; o; o >>= 1) s += __shfl_xor_sync(0xffffffffu, s, o);
    if (lane == 0) out[row] = fmaxf(s + bb[0], 0.f);
}

// ---------- host ----------
static inline void launch_tc(const bf16* A0, const bf16* W0, int K0,
                             const bf16* A1, const bf16* W1, int K1,
                             int M, int N, int NT,
                             float* Cf, bf16* Cb,
                             const float* b1, const float* b2, float cadd,
                             const bf16* zpre, const bf16* aux, int mode)
{
    dim3 grid(N / NT, M / 128);
    if (NT == 128) {
        size_t dsz = 3 * (size_t)(128 + 128) * 144;
        bgemm<128><<<grid, 256, dsz>>>(A0, W0, K0, A1, W1, K1, N, Cf, Cb, b1, b2, cadd, zpre, aux, mode);
    } else {
        size_t dsz = 3 * (size_t)(128 + 64) * 144;
        bgemm<64><<<grid, 256, dsz>>>(A0, W0, K0, A1, W1, K1, N, Cf, Cb, b1, b2, cadd, zpre, aux, mode);
    }
}
static inline void launch_sgemm(const float* A, const float* W, float* C,
                                int M, int N, int K, const float* bias, float cadd, int flags)
{
    dim3 grid((N + 63) / 64, (M + 63) / 64);
    sgemm64_kernel<<<grid, 256>>>(A, W, C, M, N, K, bias, cadd, flags);
}

extern "C" void kernel_launch(void* const* d_in, const int* in_sizes, int n_in,
                              void* d_out, int out_size)
{
    const float* x      = (const float*)d_in[0];
    const float* action = (const float*)d_in[1];
    const float* memory = (const float*)d_in[2];
    const float* W_q    = (const float*)d_in[3];
    const float* W_kv   = (const float*)d_in[4];
    const float* W_p    = (const float*)d_in[5];
    const float* W_out  = (const float*)d_in[6];
    const float* u      = (const float*)d_in[7];
    const float* v      = (const float*)d_in[8];
    const float* ln1_g  = (const float*)d_in[9];
    const float* ln1_b  = (const float*)d_in[10];
    const float* ln2_g  = (const float*)d_in[11];
    const float* ln2_b  = (const float*)d_in[12];
    const float* ff_W1  = (const float*)d_in[13];
    const float* ff_b1  = (const float*)d_in[14];
    const float* ff_W2  = (const float*)d_in[15];
    const float* ff_b2  = (const float*)d_in[16];
    const float* g1W    = (const float*)d_in[17];
    const float* g1b    = (const float*)d_in[18];
    const float* g2W    = (const float*)d_in[19];
    const float* g2b    = (const float*)d_in[20];
    const float* d1W    = (const float*)d_in[21];
    const float* d1b    = (const float*)d_in[22];
    const float* d2W    = (const float*)d_in[23];
    const float* d2b    = (const float*)d_in[24];
    const float* d3W    = (const float*)d_in[25];
    const float* d3b    = (const float*)d_in[26];
    const float* d4W    = (const float*)d_in[27];
    const float* d4b    = (const float*)d_in[28];

    cudaFuncSetAttribute(bgemm<128>, cudaFuncAttributeMaxDynamicSharedMemorySize, 111000);
    cudaFuncSetAttribute(bgemm<64>,  cudaFuncAttributeMaxDynamicSharedMemorySize, 84000);

    float *B1, *QKV, *P, *TS, *H1, *H2, *H3, *BC2;
    bf16 *XB, *LNM, *RXB, *ZB, *SRCB, *FFHB, *AVB;
    bf16 *WQKVT, *G1T, *G2T, *FF1T, *CW;
    cudaGetSymbolAddress((void**)&B1,   g_B1);
    cudaGetSymbolAddress((void**)&QKV,  g_qkv);
    cudaGetSymbolAddress((void**)&P,    g_p);
    cudaGetSymbolAddress((void**)&TS,   g_ts);
    cudaGetSymbolAddress((void**)&H1,   g_h1);
    cudaGetSymbolAddress((void**)&H2,   g_h2);
    cudaGetSymbolAddress((void**)&H3,   g_h3);
    cudaGetSymbolAddress((void**)&BC2,  g_bc2);
    cudaGetSymbolAddress((void**)&XB,   gb_x);
    cudaGetSymbolAddress((void**)&LNM,  gb_lnm);
    cudaGetSymbolAddress((void**)&RXB,  gb_rx);
    cudaGetSymbolAddress((void**)&ZB,   gb_z);
    cudaGetSymbolAddress((void**)&SRCB, gb_src);
    cudaGetSymbolAddress((void**)&FFHB, gb_ffh);
    cudaGetSymbolAddress((void**)&AVB,  gb_av);
    cudaGetSymbolAddress((void**)&WQKVT,gb_wqkv);
    cudaGetSymbolAddress((void**)&G1T,  gb_g1);
    cudaGetSymbolAddress((void**)&G2T,  gb_g2);
    cudaGetSymbolAddress((void**)&FF1T, gb_ff1);
    cudaGetSymbolAddress((void**)&CW,   gb_cw);

    const size_t SZ = (size_t)DD * DD;
    const size_t CWS = (size_t)DD * 64;

    // prep
    megaprep_kernel<<<dim3(16, 16, 17), dim3(32, 8)>>>(g1W, g2W, W_q, W_kv, ff_W1, W_p, memory);
    pregemm_kernel<<<dim3(16, 8, 6), dim3(32, 8)>>>(W_out, ff_W2, g1W, g2W);
    bc2_kernel<<<3, DD>>>(ff_b2, g2W, g2b, BC2);

    // LN1 -> LNM rows [0,NROW); also XB = bf16(x)
    ln_kernel<<<NROW / 8, 256>>>(x, LNM, XB, ln1_g, ln1_b, NROW);

    // fused qkv over src+memory rows (M=68608, N=192)
    launch_tc(LNM, WQKVT, DD, 0, 0, 0, AROW, 192, 64, QKV, 0, 0, 0, 0.f, 0, 0, 0);

    // attention -> AVB (bf16)
    attn_kernel<<<dim3(BB, HH), 128>>>(QKV, P, u, v, AVB);

    // gate 1 (y-side folded through W_out; K = 64 + 512)
    launch_tc(AVB, CW + 0 * CWS, 64, XB, G1T + 1 * SZ, DD, NROW, DD, 128,
              0, RXB, g1b + 0 * DD, g1b + 1 * DD, 0.f, 0, XB, 4);
    launch_tc(AVB, CW + 1 * CWS, 64, XB, G1T + 3 * SZ, DD, NROW, DD, 128,
              0, ZB, g1b + 2 * DD, g1b + 3 * DD, -BG, 0, 0, 2);
    launch_tc(AVB, CW + 2 * CWS, 64, RXB, G1T + 5 * SZ, DD, NROW, DD, 128,
              0, SRCB, g1b + 4 * DD, g1b + 5 * DD, 0.f, ZB, XB, 5);

    // ffh = relu(LN2(src) @ ff_W1 + b1)   (ff2 folded into gate-2 weights)
    lnb_kernel<<<NROW / 8, 256>>>(SRCB, LNM, ln2_g, ln2_b, NROW);
    launch_tc(LNM, FF1T, DD, 0, 0, 0, NROW, DFF, 64, 0, FFHB, ff_b1, 0, 0.f, 0, 0, 3);

    // gate 2 (y-side = ff folded through ff_W2; K = 64 + 512; biases pre-combined)
    launch_tc(FFHB, CW + 3 * CWS, 64, SRCB, G2T + 1 * SZ, DD, NROW, DD, 128,
              0, RXB, BC2 + 0 * DD, 0, 0.f, 0, SRCB, 4);
    launch_tc(FFHB, CW + 4 * CWS, 64, SRCB, G2T + 3 * SZ, DD, NROW, DD, 128,
              0, ZB, BC2 + 1 * DD, 0, -BG, 0, 0, 2);
    launch_tc(FFHB, CW + 5 * CWS, 64, RXB, G2T + 5 * SZ, DD, NROW, DD, 128,
              B1, 0, BC2 + 2 * DD, 0, 0.f, ZB, SRCB, 5);

    // mean pool
    meanpool_kernel<<<(BB * DD / 4 + 255) / 256, 256>>>((const float4*)B1, (float4*)TS);

    // critic head (exact fp32)
    launch_sgemm(TS, d1W, H1, BB, 1024, DD, d1b, 0.f, 2);
    launch_sgemm(H1, d2W, H2, BB, 512, 1024, nullptr, 0.f, 0);
    launch_sgemm(action, d2W + (size_t)1024 * 512, H2, BB, 512, ACT, d2b, 0.f, 3);
    launch_sgemm(H2, d3W, H3, BB, 300, DD, d3b, 0.f, 2);
    final_kernel<<<BB / 4, 128>>>(H3, d4W, d4b, (float*)d_out);
}

// round 13
// speedup vs baseline: 1.2204x; 1.0112x over previous
#include <cuda_runtime.h>
#include <cuda_bf16.h>
#include <math.h>
#include <stdint.h>

#define TT   128
#define BB   512
#define DD   512
#define MM   6
#define JJ   (TT + MM)
#define HH   2
#define DFF  64
#define ACT  64
#define NROW (TT * BB)
#define MROW (MM * BB)
#define AROW (NROW + MROW)      // 68608
#define BG   0.1f

typedef __nv_bfloat16 bf16;

// ---------- static scratch ----------
__device__ __align__(256) float g_B1[NROW * DD];
__device__ __align__(256) float g_qkv[AROW * 192];
__device__ __align__(256) float g_p  [JJ * 64];
__device__ __align__(256) float g_ts [BB * DD];
__device__ __align__(256) float g_h1 [BB * 1024];
__device__ __align__(256) float g_h2 [BB * 512];
__device__ __align__(256) float g_h3 [BB * 300];
__device__ __align__(256) float g_bc2[3 * DD];
__device__ __align__(256) bf16 gb_x   [NROW * DD];
__device__ __align__(256) bf16 gb_lnm [AROW * DD];
__device__ __align__(256) bf16 gb_rx  [NROW * DD];
__device__ __align__(256) bf16 gb_z   [NROW * DD];
__device__ __align__(256) bf16 gb_src [NROW * DD];
__device__ __align__(256) bf16 gb_ffh [NROW * DFF];
__device__ __align__(256) bf16 gb_av  [NROW * 64];
__device__ __align__(256) bf16 gb_wqkv[192 * DD];
__device__ __align__(256) bf16 gb_g1  [6 * DD * DD];
__device__ __align__(256) bf16 gb_g2  [6 * DD * DD];
__device__ __align__(256) bf16 gb_ff1 [DFF * DD];
__device__ __align__(256) bf16 gb_cw  [6 * DD * 64];

// ---------- helpers ----------
__device__ __forceinline__ uint32_t s2u(const void* p) {
    return (uint32_t)__cvta_generic_to_shared(p);
}
__device__ __forceinline__ void cp16(uint32_t s, const void* g) {
    asm volatile("cp.async.cg.shared.global [%0], [%1], 16;" :: "r"(s), "l"(g));
}
__device__ __forceinline__ void cp16g(uint32_t s, const void* g, int src_bytes) {
    asm volatile("cp.async.cg.shared.global [%0], [%1], 16, %2;"
                 :: "r"(s), "l"(g), "r"(src_bytes));
}
__device__ __forceinline__ void cp_commit() { asm volatile("cp.async.commit_group;" ::: "memory"); }
__device__ __forceinline__ void cp_wait0()  { asm volatile("cp.async.wait_group 0;" ::: "memory"); }
__device__ __forceinline__ void cp_wait1()  { asm volatile("cp.async.wait_group 1;" ::: "memory"); }
__device__ __forceinline__ void ldsm4(uint32_t* r, uint32_t addr) {
    asm volatile("ldmatrix.sync.aligned.m8n8.x4.shared.b16 {%0,%1,%2,%3}, [%4];"
                 : "=r"(r[0]), "=r"(r[1]), "=r"(r[2]), "=r"(r[3]) : "r"(addr));
}
__device__ __forceinline__ void mma_bf16(float* c, const uint32_t* a, const uint32_t* b) {
    asm volatile(
        "mma.sync.aligned.m16n8k16.row.col.f32.bf16.bf16.f32 "
        "{%0,%1,%2,%3}, {%4,%5,%6,%7}, {%8,%9}, {%0,%1,%2,%3};"
        : "+f"(c[0]), "+f"(c[1]), "+f"(c[2]), "+f"(c[3])
        : "r"(a[0]), "r"(a[1]), "r"(a[2]), "r"(a[3]), "r"(b[0]), "r"(b[1]));
}
__device__ __forceinline__ uint32_t f2tf(float x) {
    uint32_t r;
    asm("cvt.rna.tf32.f32 %0, %1;" : "=r"(r) : "f"(x));
    return r;
}
__device__ __forceinline__ void mma_tf32(float* c, const uint32_t* a, const uint32_t* b) {
    asm volatile(
        "mma.sync.aligned.m16n8k8.row.col.f32.tf32.tf32.f32 "
        "{%0,%1,%2,%3}, {%4,%5,%6,%7}, {%8,%9}, {%0,%1,%2,%3};"
        : "+f"(c[0]), "+f"(c[1]), "+f"(c[2]), "+f"(c[3])
        : "r"(a[0]), "r"(a[1]), "r"(a[2]), "r"(a[3]), "r"(b[0]), "r"(b[1]));
}

// ---------- bf16 dual-source tensor GEMM (ldmatrix + 3-stage cp.async) ----------
// modes: 0 f32 | 2 bf16 | 3 bf16 relu | 4 bf16 = sigmoid(v)*aux(bf16)
//        5 (1-sig(zpre))*aux + sig(zpre)*tanh(v) -> Cf and/or Cb

template<int NT>
__global__ __launch_bounds__(256, 2)
void bgemm(const bf16* __restrict__ A0, const bf16* __restrict__ W0, int K0,
           const bf16* __restrict__ A1, const bf16* __restrict__ W1, int K1,
           int N,
           float* __restrict__ Cf, bf16* __restrict__ Cb,
           const float* __restrict__ bias1, const float* __restrict__ bias2,
           float cadd, const bf16* __restrict__ zpre, const bf16* __restrict__ aux,
           int mode)
{
    extern __shared__ char dsm[];
    constexpr int NTI = NT / 32;
    constexpr int STG = (128 + NT) * 144;

    const int tid  = threadIdx.x;
    const int warp = tid >> 5, lane = tid & 31;
    const int grp  = lane >> 2, thr = lane & 3;
    const int wm   = warp & 1,  wn  = warp >> 1;
    const int m_base = wm * 64;
    const int n_base = wn * (NT / 4);
    const int row0 = blockIdx.y * 128;
    const int col0 = blockIdx.x * NT;
    const uint32_t sb = s2u(dsm);

    float acc[4][NTI][4];
#pragma unroll
    for (int i = 0; i < 4; i++)
#pragma unroll
        for (int j = 0; j < NTI; j++)
#pragma unroll
            for (int r = 0; r < 4; r++) acc[i][j][r] = 0.f;

    const int NC0 = K0 >> 6;
    const int NC  = NC0 + (K1 >> 6);

    auto load_stage = [&](int c, int buf) {
        const bf16 *a, *w; int k, kb;
        if (c < NC0) { a = A0; w = W0; k = K0; kb = c << 6; }
        else         { a = A1; w = W1; k = K1; kb = (c - NC0) << 6; }
        uint32_t ab = sb + (uint32_t)buf * STG;
#pragma unroll
        for (int i = 0; i < 4; i++) {
            int u = tid + i * 256;
            int r = u >> 3, cc = u & 7;
            cp16(ab + (uint32_t)(r * 144 + cc * 16),
                 a + (size_t)(row0 + r) * k + kb + cc * 8);
        }
        uint32_t bb = ab + 128u * 144u;
#pragma unroll
        for (int i = 0; i < NT / 32; i++) {
            int u = tid + i * 256;
            int r = u >> 3, cc = u & 7;
            cp16(bb + (uint32_t)(r * 144 + cc * 16),
                 w + (size_t)(col0 + r) * k + kb + cc * 8);
        }
        cp_commit();
    };

    load_stage(0, 0);
    if (NC > 1) load_stage(1, 1);

    for (int c = 0; c < NC; c++) {
        if (c == NC - 1) cp_wait0(); else cp_wait1();
        __syncthreads();
        if (c + 2 < NC) load_stage(c + 2, (c + 2) % 3);

        uint32_t ab = sb + (uint32_t)(c % 3) * STG;
        uint32_t bb = ab + 128u * 144u;

        const uint32_t a_lrow = (uint32_t)(lane & 15);
        const uint32_t a_koff = (uint32_t)((lane >> 4) << 3);
        const uint32_t b_cofs = (uint32_t)(((lane >> 4) << 3) + (lane & 7));
        const uint32_t b_koff = (uint32_t)(((lane >> 3) & 1) << 3);

#pragma unroll
        for (int ks = 0; ks < 4; ks++) {
            const int kc = ks * 16;
            uint32_t af[4][4], bfr[NTI][2];
#pragma unroll
            for (int mt = 0; mt < 4; mt++) {
                uint32_t addr = ab + (uint32_t)(m_base + mt * 16 + a_lrow) * 144u
                                   + (uint32_t)(kc + a_koff) * 2u;
                ldsm4(af[mt], addr);
            }
#pragma unroll
            for (int p = 0; p < NTI / 2; p++) {
                uint32_t col = (uint32_t)(n_base + p * 16) + b_cofs;
                uint32_t addr = bb + col * 144u + (uint32_t)(kc + b_koff) * 2u;
                uint32_t r[4];
                ldsm4(r, addr);
                bfr[2 * p][0]     = r[0]; bfr[2 * p][1]     = r[1];
                bfr[2 * p + 1][0] = r[2]; bfr[2 * p + 1][1] = r[3];
            }
#pragma unroll
            for (int mt = 0; mt < 4; mt++)
#pragma unroll
                for (int nt = 0; nt < NTI; nt++)
                    mma_bf16(acc[mt][nt], af[mt], bfr[nt]);
        }
    }

    // epilogue
#pragma unroll
    for (int mt = 0; mt < 4; mt++) {
#pragma unroll
        for (int nt = 0; nt < NTI; nt++) {
            int cbase = col0 + n_base + nt * 8 + thr * 2;
            float b0 = cadd, b1 = cadd;
            if (bias1) { b0 += bias1[cbase]; b1 += bias1[cbase + 1]; }
            if (bias2) { b0 += bias2[cbase]; b1 += bias2[cbase + 1]; }
#pragma unroll
            for (int half = 0; half < 2; half++) {
                int r = row0 + m_base + mt * 16 + grp + half * 8;
                size_t idx0 = (size_t)r * N + cbase;
#pragma unroll
                for (int e = 0; e < 2; e++) {
                    float v = acc[mt][nt][half * 2 + e] + (e ? b1 : b0);
                    size_t idx = idx0 + e;
                    if (mode == 0) {
                        Cf[idx] = v;
                    } else if (mode == 2) {
                        Cb[idx] = __float2bfloat16(v);
                    } else if (mode == 3) {
                        Cb[idx] = __float2bfloat16(fmaxf(v, 0.f));
                    } else if (mode == 4) {
                        float s = 1.f / (1.f + __expf(-v));
                        Cb[idx] = __float2bfloat16(s * __bfloat162float(aux[idx]));
                    } else {
                        float z = 1.f / (1.f + __expf(-__bfloat162float(zpre[idx])));
                        float o = (1.f - z) * __bfloat162float(aux[idx]) + z * tanhf(v);
                        if (Cf) Cf[idx] = o;
                        if (Cb) Cb[idx] = __float2bfloat16(o);
                    }
                }
            }
        }
    }
}

// ---------- tf32 tensor GEMM (critic head): C[M,N]=A[M,K]@W[K,N] ----------
// flags bit0 = accumulate, bit1 = relu. M%128==0, K%16==0, N%4==0.
#define AS_STRIDE 20
#define BS_STRIDE 136

__global__ __launch_bounds__(256, 2)
void tgemm_kernel(const float* __restrict__ A, const float* __restrict__ W,
                  float* __restrict__ C, int M, int N, int K,
                  const float* __restrict__ bias, float cadd, int flags)
{
    __shared__ float As[2][128 * AS_STRIDE];
    __shared__ float Bs[2][16 * BS_STRIDE];

    const int tid  = threadIdx.x;
    const int row0 = blockIdx.y * 128;
    const int col0 = blockIdx.x * 128;

    const int warp = tid >> 5;
    const int lane = tid & 31;
    const int grp  = lane >> 2;
    const int thr  = lane & 3;
    const int wm   = warp & 1;
    const int wn   = warp >> 1;
    const int m_base = wm * 64;
    const int n_base = wn * 32;

    const int a_row  = tid >> 2;
    const int a_col4 = (tid & 3) << 2;
    const int b_row  = tid >> 4;
    const int b_col4 = (tid & 15) << 3;

    uint32_t as_base = s2u(&As[0][0]);
    uint32_t bs_base = s2u(&Bs[0][0]);

    float acc[4][4][4];
#pragma unroll
    for (int i = 0; i < 4; i++)
#pragma unroll
        for (int j = 0; j < 4; j++)
#pragma unroll
            for (int r = 0; r < 4; r++) acc[i][j][r] = 0.f;

    const int KT = K / 16;

    auto load_stage = [&](int kt, int buf) {
        int k0 = kt * 16;
        uint32_t abuf = as_base + (uint32_t)buf * 128 * AS_STRIDE * 4;
#pragma unroll
        for (int h = 0; h < 2; h++) {
            int r = a_row + h * 64;
            const float* ga = A + (size_t)(row0 + r) * K + k0 + a_col4;
            cp16g(abuf + (r * AS_STRIDE + a_col4) * 4, ga, 16);
        }
        uint32_t bbuf = bs_base + (uint32_t)buf * 16 * BS_STRIDE * 4;
#pragma unroll
        for (int h = 0; h < 2; h++) {
            int c4 = b_col4 + h * 4;
            int gc = col0 + c4;
            int ok = (gc < N);
            const float* gb = W + (size_t)(k0 + b_row) * N + (ok ? gc : 0);
            cp16g(bbuf + (b_row * BS_STRIDE + c4) * 4, gb, ok ? 16 : 0);
        }
        cp_commit();
    };

    load_stage(0, 0);

    for (int kt = 0; kt < KT; kt++) {
        cp_wait0();
        __syncthreads();
        if (kt + 1 < KT) load_stage(kt + 1, (kt + 1) & 1);

        const float* as = &As[kt & 1][0];
        const float* bs = &Bs[kt & 1][0];

#pragma unroll
        for (int kk = 0; kk < 16; kk += 8) {
            uint32_t af[4][4], bf[4][2];
#pragma unroll
            for (int mt = 0; mt < 4; mt++) {
                int r = m_base + mt * 16 + grp;
                af[mt][0] = f2tf(as[(r)     * AS_STRIDE + kk + thr]);
                af[mt][1] = f2tf(as[(r + 8) * AS_STRIDE + kk + thr]);
                af[mt][2] = f2tf(as[(r)     * AS_STRIDE + kk + thr + 4]);
                af[mt][3] = f2tf(as[(r + 8) * AS_STRIDE + kk + thr + 4]);
            }
#pragma unroll
            for (int nt = 0; nt < 4; nt++) {
                int c = n_base + nt * 8 + grp;
                bf[nt][0] = f2tf(bs[(kk + thr)     * BS_STRIDE + c]);
                bf[nt][1] = f2tf(bs[(kk + thr + 4) * BS_STRIDE + c]);
            }
#pragma unroll
            for (int mt = 0; mt < 4; mt++)
#pragma unroll
                for (int nt = 0; nt < 4; nt++)
                    mma_tf32(acc[mt][nt], af[mt], bf[nt]);
        }
        __syncthreads();
    }

#pragma unroll
    for (int mt = 0; mt < 4; mt++) {
#pragma unroll
        for (int nt = 0; nt < 4; nt++) {
#pragma unroll
            for (int half = 0; half < 2; half++) {
                int r = row0 + m_base + mt * 16 + grp + half * 8;
#pragma unroll
                for (int e = 0; e < 2; e++) {
                    int c = col0 + n_base + nt * 8 + thr * 2 + e;
                    if (c >= N) continue;
                    float val = acc[mt][nt][half * 2 + e] + cadd;
                    if (bias) val += bias[c];
                    size_t idx = (size_t)r * N + c;
                    if (flags & 1) val += C[idx];
                    if (flags & 2) val = fmaxf(val, 0.f);
                    C[idx] = val;
                }
            }
        }
    }
}

// ---------- LayerNorm from f32; writes LN out (bf16) + raw bf16 copy ----------
__global__ void ln_kernel(const float* __restrict__ x, bf16* __restrict__ out,
                          bf16* __restrict__ rawb,
                          const float* __restrict__ g, const float* __restrict__ b, int rows)
{
    int warp = blockIdx.x * (blockDim.x >> 5) + (threadIdx.x >> 5);
    if (warp >= rows) return;
    int lane = threadIdx.x & 31;
    const float* xr = x + (size_t)warp * DD;
    float v[16], s1 = 0.f, s2 = 0.f;
#pragma unroll
    for (int i = 0; i < 16; i++) {
        float t = xr[i * 32 + lane];
        v[i] = t; s1 += t; s2 += t * t;
    }
#pragma unroll
    for (int o = 16; o; o >>= 1) {
        s1 += __shfl_xor_sync(0xffffffffu, s1, o);
        s2 += __shfl_xor_sync(0xffffffffu, s2, o);
    }
    float mu = s1 * (1.f / DD);
    float inv = rsqrtf(s2 * (1.f / DD) - mu * mu + 1e-5f);
    bf16* orow = out + (size_t)warp * DD;
    bf16* rrow = rawb ? rawb + (size_t)warp * DD : 0;
#pragma unroll
    for (int i = 0; i < 16; i++) {
        int d = i * 32 + lane;
        orow[d] = __float2bfloat16((v[i] - mu) * inv * g[d] + b[d]);
        if (rrow) rrow[d] = __float2bfloat16(v[i]);
    }
}

// ---------- LayerNorm from bf16 input ----------
__global__ void lnb_kernel(const bf16* __restrict__ x, bf16* __restrict__ out,
                           const float* __restrict__ g, const float* __restrict__ b, int rows)
{
    int warp = blockIdx.x * (blockDim.x >> 5) + (threadIdx.x >> 5);
    if (warp >= rows) return;
    int lane = threadIdx.x & 31;
    const bf16* xr = x + (size_t)warp * DD;
    float v[16], s1 = 0.f, s2 = 0.f;
#pragma unroll
    for (int i = 0; i < 16; i++) {
        float t = __bfloat162float(xr[i * 32 + lane]);
        v[i] = t; s1 += t; s2 += t * t;
    }
#pragma unroll
    for (int o = 16; o; o >>= 1) {
        s1 += __shfl_xor_sync(0xffffffffu, s1, o);
        s2 += __shfl_xor_sync(0xffffffffu, s2, o);
    }
    float mu = s1 * (1.f / DD);
    float inv = rsqrtf(s2 * (1.f / DD) - mu * mu + 1e-5f);
    bf16* orow = out + (size_t)warp * DD;
#pragma unroll
    for (int i = 0; i < 16; i++) {
        int d = i * 32 + lane;
        orow[d] = __float2bfloat16((v[i] - mu) * inv * g[d] + b[d]);
    }
}

// ---------- attention ----------
__global__ void attn_kernel(const float* __restrict__ qkv,
                            const float* __restrict__ p, const float* __restrict__ uu,
                            const float* __restrict__ vvec, bf16* __restrict__ av)
{
    int b = blockIdx.x, h = blockIdx.y;
    __shared__ float Ks[JJ][33];
    __shared__ float Vs[JJ][33];
    __shared__ float att[4][JJ];
    __shared__ float qsu[4][32];
    __shared__ float qsv[4][32];
    int tid = threadIdx.x;
    for (int idx = tid; idx < JJ * 32; idx += 128) {
        int j = idx >> 5, d = idx & 31;
        size_t rr = (j < MM) ? ((size_t)NROW + (size_t)j * BB + b)
                             : ((size_t)(j - MM) * BB + b);
        const float* row = qkv + rr * 192 + 64 + h * 32 + d;
        Ks[j][d] = row[0];
        Vs[j][d] = row[64];
    }
    __syncthreads();
    int warp = tid >> 5, lane = tid & 31;
    float ul = uu[h * 32 + lane], vl = vvec[h * 32 + lane];
    for (int i = warp; i < TT; i += 4) {
        float qv = qkv[((size_t)i * BB + b) * 192 + h * 32 + lane];
        qsu[warp][lane] = qv + ul;
        qsv[warp][lane] = qv + vl;
        __syncwarp();
        int jmax = i + MM;
        float sv[5], smax = -1e30f;
        int cnt = 0;
        for (int j = lane; j <= jmax; j += 32) {
            const float* prow = p + (size_t)(j + TT - 1 - i) * 64 + h * 32;
            float s = 0.f;
#pragma unroll
            for (int d = 0; d < 32; d++)
                s += qsu[warp][d] * Ks[j][d] + qsv[warp][d] * prow[d];
            s *= 0.1767766952966369f;
            sv[cnt++] = s;
            smax = fmaxf(smax, s);
        }
#pragma unroll
        for (int o = 16; o; o >>= 1) smax = fmaxf(smax, __shfl_xor_sync(0xffffffffu, smax, o));
        float sum = 0.f; cnt = 0;
        for (int j = lane; j <= jmax; j += 32) {
            float e = __expf(sv[cnt++] - smax);
            att[warp][j] = e;
            sum += e;
        }
#pragma unroll
        for (int o = 16; o; o >>= 1) sum += __shfl_xor_sync(0xffffffffu, sum, o);
        float inv = 1.f / sum;
        __syncwarp();
        float acc = 0.f;
        for (int j = 0; j <= jmax; j++) acc += att[warp][j] * Vs[j][lane];
        av[((size_t)i * BB + b) * 64 + h * 32 + lane] = __float2bfloat16(acc * inv);
        __syncwarp();
    }
}

// ---------- mega prep ----------
__device__ __forceinline__ void tpose_tile(const float* __restrict__ in, bf16* __restrict__ out,
                                           int K, int N)
{
    __shared__ float t[32][33];
    int k0 = blockIdx.y * 32, n0 = blockIdx.x * 32;
    if (k0 >= K || n0 >= N) return;
    int x = threadIdx.x, y = threadIdx.y;
    for (int i = y; i < 32; i += 8)
        t[i][x] = in[(size_t)(k0 + i) * N + n0 + x];
    __syncthreads();
    for (int i = y; i < 32; i += 8)
        out[(size_t)(n0 + i) * K + k0 + x] = __float2bfloat16(t[x][i]);
}

__global__ void megaprep_kernel(const float* __restrict__ g1W, const float* __restrict__ g2W,
                                const float* __restrict__ Wq, const float* __restrict__ Wkv,
                                const float* __restrict__ ffW1, const float* __restrict__ Wp,
                                const float* __restrict__ memory)
{
    int z = blockIdx.z;
    if (z < 12) {
        const float* in = ((z < 6) ? g1W : g2W) + (size_t)(z % 6) * DD * DD;
        bf16* out = ((z < 6) ? gb_g1 : gb_g2) + (size_t)(z % 6) * DD * DD;
        tpose_tile(in, out, DD, DD);
    } else if (z == 12) {
        tpose_tile(Wq, gb_wqkv, DD, 64);
    } else if (z == 13) {
        tpose_tile(Wkv, gb_wqkv + 64 * DD, DD, 128);
    } else if (z == 14) {
        tpose_tile(ffW1, gb_ff1, DD, DFF);
    } else if (z == 15) {
        int bid = blockIdx.y * 16 + blockIdx.x;
        int tid = threadIdx.y * 32 + threadIdx.x;
        const int n4 = MROW * DD / 4;
        bf16* dst = gb_lnm + (size_t)NROW * DD;
        for (int i = bid * 256 + tid; i < n4; i += 256 * 256) {
            float4 v = reinterpret_cast<const float4*>(memory)[i];
            __nv_bfloat162* o = reinterpret_cast<__nv_bfloat162*>(dst + (size_t)i * 4);
            o[0] = __floats2bfloat162_rn(v.x, v.y);
            o[1] = __floats2bfloat162_rn(v.z, v.w);
        }
    } else {
        int jj = blockIdx.y * 16 + blockIdx.x;
        if (jj >= JJ) return;
        __shared__ float pe[DD];
        int tid = threadIdx.y * 32 + threadIdx.x;
        float pos = (float)(JJ - 1 - jj);
        for (int d = tid; d < DD; d += 256) {
            int i = (d < 256) ? d : d - 256;
            float f = __expf(-(float)(2 * i) * (1.f / 512.f) * 9.210340371976184f);
            float a = pos * f;
            pe[d] = (d < 256) ? sinf(a) : cosf(a);
        }
        __syncthreads();
        if (tid < 64) {
            float acc = 0.f;
            for (int d = 0; d < DD; d++) acc += pe[d] * Wp[d * 64 + tid];
            g_p[jj * 64 + tid] = acc;
        }
    }
}

// ---------- folded-weight precompute ----------
__global__ void pregemm_kernel(const float* __restrict__ Wout, const float* __restrict__ ffW2,
                               const float* __restrict__ g1W, const float* __restrict__ g2W)
{
    __shared__ float sG[64][33];
    const int slot[3] = {0, 2, 4};
    int m = blockIdx.z;
    const float* A = (m < 3) ? Wout : ffW2;
    const float* G = ((m < 3) ? g1W : g2W) + (size_t)slot[m % 3] * DD * DD;
    bf16* out = gb_cw + (size_t)m * DD * 64;
    int n0 = blockIdx.x * 32, k0 = blockIdx.y * 8;
    int tx = threadIdx.x, ty = threadIdx.y;
    int tid = ty * 32 + tx;
    float acc = 0.f;
    for (int dc = 0; dc < 8; dc++) {
        __syncthreads();
        for (int idx = tid; idx < 64 * 32; idx += 256) {
            int i = idx >> 5, j = idx & 31;
            sG[i][j] = G[(size_t)(dc * 64 + i) * DD + n0 + j];
        }
        __syncthreads();
        const float* Ar = A + (size_t)(k0 + ty) * DD + dc * 64;
#pragma unroll 16
        for (int i = 0; i < 64; i++) acc += Ar[i] * sG[i][tx];
    }
    out[(size_t)(n0 + tx) * 64 + (k0 + ty)] = __float2bfloat16(acc);
}

// ---------- gate-2 combined bias ----------
__global__ void bc2_kernel(const float* __restrict__ ffb2, const float* __restrict__ g2W,
                           const float* __restrict__ g2b, float* __restrict__ bc)
{
    const int slot[3] = {0, 2, 4};
    int m = blockIdx.x;
    int n = threadIdx.x;
    const float* G = g2W + (size_t)slot[m] * DD * DD;
    float acc = g2b[(2 * m) * DD + n] + g2b[(2 * m + 1) * DD + n];
    for (int d = 0; d < DD; d++) acc += ffb2[d] * G[(size_t)d * DD + n];
    bc[m * DD + n] = acc;
}

// ---------- mean pool ----------
__global__ void meanpool_kernel(const float4* __restrict__ in, float4* __restrict__ ts)
{
    int idx = blockIdx.x * blockDim.x + threadIdx.x;
    const int n4 = BB * DD / 4;
    if (idx >= n4) return;
    float4 s = make_float4(0.f, 0.f, 0.f, 0.f);
    for (int t = 0; t < TT; t++) {
        float4 v = in[(size_t)t * n4 + idx];
        s.x += v.x; s.y += v.y; s.z += v.z; s.w += v.w;
    }
    const float inv = 1.f / TT;
    s.x *= inv; s.y *= inv; s.z *= inv; s.w *= inv;
    ts[idx] = s;
}

// ---------- final head ----------
__global__ void final_kernel(const float* __restrict__ h3, const float* __restrict__ w,
                             const float* __restrict__ bb, float* __restrict__ out)
{
    int row = blockIdx.x * 4 + (threadIdx.x >> 5);
    int lane = threadIdx.x & 31;
    if (row >= BB) return;
    float s = 0.f;
    for (int k = lane; k < 300; k += 32) s += h3[(size_t)row * 300 + k] * w[k];
#pragma unroll
    for (int o = 16; o; o >>= 1) s += __shfl_xor_sync(0xffffffffu, s, o);
    if (lane == 0) out[row] = fmaxf(s + bb[0], 0.f);
}

// ---------- host ----------
static inline void launch_tc(const bf16* A0, const bf16* W0, int K0,
                             const bf16* A1, const bf16* W1, int K1,
                             int M, int N, int NT,
                             float* Cf, bf16* Cb,
                             const float* b1, const float* b2, float cadd,
                             const bf16* zpre, const bf16* aux, int mode)
{
    dim3 grid(N / NT, M / 128);
    if (NT == 128) {
        size_t dsz = 3 * (size_t)(128 + 128) * 144;
        bgemm<128><<<grid, 256, dsz>>>(A0, W0, K0, A1, W1, K1, N, Cf, Cb, b1, b2, cadd, zpre, aux, mode);
    } else {
        size_t dsz = 3 * (size_t)(128 + 64) * 144;
        bgemm<64><<<grid, 256, dsz>>>(A0, W0, K0, A1, W1, K1, N, Cf, Cb, b1, b2, cadd, zpre, aux, mode);
    }
}
static inline void launch_tf(const float* A, const float* W, float* C,
                             int M, int N, int K, const float* bias, float cadd, int flags)
{
    dim3 grid((N + 127) / 128, M / 128);
    tgemm_kernel<<<grid, 256>>>(A, W, C, M, N, K, bias, cadd, flags);
}

extern "C" void kernel_launch(void* const* d_in, const int* in_sizes, int n_in,
                              void* d_out, int out_size)
{
    const float* x      = (const float*)d_in[0];
    const float* action = (const float*)d_in[1];
    const float* memory = (const float*)d_in[2];
    const float* W_q    = (const float*)d_in[3];
    const float* W_kv   = (const float*)d_in[4];
    const float* W_p    = (const float*)d_in[5];
    const float* W_out  = (const float*)d_in[6];
    const float* u      = (const float*)d_in[7];
    const float* v      = (const float*)d_in[8];
    const float* ln1_g  = (const float*)d_in[9];
    const float* ln1_b  = (const float*)d_in[10];
    const float* ln2_g  = (const float*)d_in[11];
    const float* ln2_b  = (const float*)d_in[12];
    const float* ff_W1  = (const float*)d_in[13];
    const float* ff_b1  = (const float*)d_in[14];
    const float* ff_W2  = (const float*)d_in[15];
    const float* ff_b2  = (const float*)d_in[16];
    const float* g1W    = (const float*)d_in[17];
    const float* g1b    = (const float*)d_in[18];
    const float* g2W    = (const float*)d_in[19];
    const float* g2b    = (const float*)d_in[20];
    const float* d1W    = (const float*)d_in[21];
    const float* d1b    = (const float*)d_in[22];
    const float* d2W    = (const float*)d_in[23];
    const float* d2b    = (const float*)d_in[24];
    const float* d3W    = (const float*)d_in[25];
    const float* d3b    = (const float*)d_in[26];
    const float* d4W    = (const float*)d_in[27];
    const float* d4b    = (const float*)d_in[28];

    cudaFuncSetAttribute(bgemm<128>, cudaFuncAttributeMaxDynamicSharedMemorySize, 111000);
    cudaFuncSetAttribute(bgemm<64>,  cudaFuncAttributeMaxDynamicSharedMemorySize, 84000);

    float *B1, *QKV, *P, *TS, *H1, *H2, *H3, *BC2;
    bf16 *XB, *LNM, *RXB, *ZB, *SRCB, *FFHB, *AVB;
    bf16 *WQKVT, *G1T, *G2T, *FF1T, *CW;
    cudaGetSymbolAddress((void**)&B1,   g_B1);
    cudaGetSymbolAddress((void**)&QKV,  g_qkv);
    cudaGetSymbolAddress((void**)&P,    g_p);
    cudaGetSymbolAddress((void**)&TS,   g_ts);
    cudaGetSymbolAddress((void**)&H1,   g_h1);
    cudaGetSymbolAddress((void**)&H2,   g_h2);
    cudaGetSymbolAddress((void**)&H3,   g_h3);
    cudaGetSymbolAddress((void**)&BC2,  g_bc2);
    cudaGetSymbolAddress((void**)&XB,   gb_x);
    cudaGetSymbolAddress((void**)&LNM,  gb_lnm);
    cudaGetSymbolAddress((void**)&RXB,  gb_rx);
    cudaGetSymbolAddress((void**)&ZB,   gb_z);
    cudaGetSymbolAddress((void**)&SRCB, gb_src);
    cudaGetSymbolAddress((void**)&FFHB, gb_ffh);
    cudaGetSymbolAddress((void**)&AVB,  gb_av);
    cudaGetSymbolAddress((void**)&WQKVT,gb_wqkv);
    cudaGetSymbolAddress((void**)&G1T,  gb_g1);
    cudaGetSymbolAddress((void**)&G2T,  gb_g2);
    cudaGetSymbolAddress((void**)&FF1T, gb_ff1);
    cudaGetSymbolAddress((void**)&CW,   gb_cw);

    const size_t SZ = (size_t)DD * DD;
    const size_t CWS = (size_t)DD * 64;

    // prep
    megaprep_kernel<<<dim3(16, 16, 17), dim3(32, 8)>>>(g1W, g2W, W_q, W_kv, ff_W1, W_p, memory);
    pregemm_kernel<<<dim3(16, 8, 6), dim3(32, 8)>>>(W_out, ff_W2, g1W, g2W);
    bc2_kernel<<<3, DD>>>(ff_b2, g2W, g2b, BC2);

    // LN1 -> LNM rows [0,NROW); also XB = bf16(x)
    ln_kernel<<<NROW / 8, 256>>>(x, LNM, XB, ln1_g, ln1_b, NROW);

    // fused qkv over src+memory rows (M=68608, N=192)
    launch_tc(LNM, WQKVT, DD, 0, 0, 0, AROW, 192, 64, QKV, 0, 0, 0, 0.f, 0, 0, 0);

    // attention -> AVB (bf16)
    attn_kernel<<<dim3(BB, HH), 128>>>(QKV, P, u, v, AVB);

    // gate 1 (y-side folded through W_out; K = 64 + 512)
    launch_tc(AVB, CW + 0 * CWS, 64, XB, G1T + 1 * SZ, DD, NROW, DD, 128,
              0, RXB, g1b + 0 * DD, g1b + 1 * DD, 0.f, 0, XB, 4);
    launch_tc(AVB, CW + 1 * CWS, 64, XB, G1T + 3 * SZ, DD, NROW, DD, 128,
              0, ZB, g1b + 2 * DD, g1b + 3 * DD, -BG, 0, 0, 2);
    launch_tc(AVB, CW + 2 * CWS, 64, RXB, G1T + 5 * SZ, DD, NROW, DD, 128,
              0, SRCB, g1b + 4 * DD, g1b + 5 * DD, 0.f, ZB, XB, 5);

    // ffh = relu(LN2(src) @ ff_W1 + b1)   (ff2 folded into gate-2 weights)
    lnb_kernel<<<NROW / 8, 256>>>(SRCB, LNM, ln2_g, ln2_b, NROW);
    launch_tc(LNM, FF1T, DD, 0, 0, 0, NROW, DFF, 64, 0, FFHB, ff_b1, 0, 0.f, 0, 0, 3);

    // gate 2 (y-side = ff folded through ff_W2; K = 64 + 512; biases pre-combined)
    launch_tc(FFHB, CW + 3 * CWS, 64, SRCB, G2T + 1 * SZ, DD, NROW, DD, 128,
              0, RXB, BC2 + 0 * DD, 0, 0.f, 0, SRCB, 4);
    launch_tc(FFHB, CW + 4 * CWS, 64, SRCB, G2T + 3 * SZ, DD, NROW, DD, 128,
              0, ZB, BC2 + 1 * DD, 0, -BG, 0, 0, 2);
    launch_tc(FFHB, CW + 5 * CWS, 64, RXB, G2T + 5 * SZ, DD, NROW, DD, 128,
              B1, 0, BC2 + 2 * DD, 0, 0.f, ZB, SRCB, 5);

    // mean pool
    meanpool_kernel<<<(BB * DD / 4 + 255) / 256, 256>>>((const float4*)B1, (float4*)TS);

    // critic head (tf32 tensor cores)
    launch_tf(TS, d1W, H1, BB, 1024, DD, d1b, 0.f, 2);
    launch_tf(H1, d2W, H2, BB, 512, 1024, nullptr, 0.f, 0);
    launch_tf(action, d2W + (size_t)1024 * 512, H2, BB, 512, ACT, d2b, 0.f, 3);
    launch_tf(H2, d3W, H3, BB, 300, DD, d3b, 0.f, 2);
    final_kernel<<<BB / 4, 128>>>(H3, d4W, d4b, (float*)d_out);
}

// round 14
// speedup vs baseline: 1.3488x; 1.1052x over previous
#include <cuda_runtime.h>
#include <cuda_bf16.h>
#include <math.h>
#include <stdint.h>

#define TT   128
#define BB   512
#define DD   512
#define MM   6
#define JJ   (TT + MM)
#define HH   2
#define DFF  64
#define ACT  64
#define NROW (TT * BB)
#define MROW (MM * BB)
#define AROW (NROW + MROW)
#define BG   0.1f

typedef __nv_bfloat16 bf16;

// ---------- static scratch ----------
__device__ __align__(256) float g_qkv[AROW * 192];
__device__ __align__(256) float g_p  [JJ * 64];
__device__ __align__(256) float g_ts [BB * DD];
__device__ __align__(256) float g_h1 [BB * 1024];
__device__ __align__(256) float g_h2 [BB * 512];
__device__ __align__(256) float g_h3 [BB * 300];
__device__ __align__(256) float g_bc2[3 * DD];
__device__ __align__(256) bf16 gb_x   [NROW * DD];   // x bf16; later gate-2 output
__device__ __align__(256) bf16 gb_lnm [AROW * DD];
__device__ __align__(256) bf16 gb_rx  [NROW * DD];
__device__ __align__(256) bf16 gb_z   [NROW * DD];
__device__ __align__(256) bf16 gb_src [NROW * DD];
__device__ __align__(256) bf16 gb_ffh [NROW * DFF];
__device__ __align__(256) bf16 gb_av  [NROW * 64];
__device__ __align__(256) bf16 gb_wqkv[192 * DD];
__device__ __align__(256) bf16 gb_g1  [6 * DD * DD];
__device__ __align__(256) bf16 gb_g2  [6 * DD * DD];
__device__ __align__(256) bf16 gb_ff1 [DFF * DD];
__device__ __align__(256) bf16 gb_cw  [6 * DD * 64];

// ---------- helpers ----------
__device__ __forceinline__ uint32_t s2u(const void* p) {
    return (uint32_t)__cvta_generic_to_shared(p);
}
__device__ __forceinline__ void cp16(uint32_t s, const void* g) {
    asm volatile("cp.async.cg.shared.global [%0], [%1], 16;" :: "r"(s), "l"(g));
}
__device__ __forceinline__ void cp_commit() { asm volatile("cp.async.commit_group;" ::: "memory"); }
__device__ __forceinline__ void cp_wait0()  { asm volatile("cp.async.wait_group 0;" ::: "memory"); }
__device__ __forceinline__ void cp_wait1()  { asm volatile("cp.async.wait_group 1;" ::: "memory"); }
__device__ __forceinline__ void ldsm4(uint32_t* r, uint32_t addr) {
    asm volatile("ldmatrix.sync.aligned.m8n8.x4.shared.b16 {%0,%1,%2,%3}, [%4];"
                 : "=r"(r[0]), "=r"(r[1]), "=r"(r[2]), "=r"(r[3]) : "r"(addr));
}
__device__ __forceinline__ void mma_bf16(float* c, const uint32_t* a, const uint32_t* b) {
    asm volatile(
        "mma.sync.aligned.m16n8k16.row.col.f32.bf16.bf16.f32 "
        "{%0,%1,%2,%3}, {%4,%5,%6,%7}, {%8,%9}, {%0,%1,%2,%3};"
        : "+f"(c[0]), "+f"(c[1]), "+f"(c[2]), "+f"(c[3])
        : "r"(a[0]), "r"(a[1]), "r"(a[2]), "r"(a[3]), "r"(b[0]), "r"(b[1]));
}
__device__ __forceinline__ float tanh_fast(float x) {
    float r;
    asm("tanh.approx.f32 %0, %1;" : "=f"(r) : "f"(x));
    return r;
}

// ---------- bf16 dual-source tensor GEMM ----------
// modes: 0 f32 | 2 bf16 | 3 bf16 relu | 4 bf16 = sigmoid(v)*aux(bf16)
//        5 (1-sig(zpre))*aux + sig(zpre)*tanh(v) -> Cf and/or Cb

template<int NT>
__global__ __launch_bounds__(256, 2)
void bgemm(const bf16* __restrict__ A0, const bf16* __restrict__ W0, int K0,
           const bf16* __restrict__ A1, const bf16* __restrict__ W1, int K1,
           int N,
           float* __restrict__ Cf, bf16* __restrict__ Cb,
           const float* __restrict__ bias1, const float* __restrict__ bias2,
           float cadd, const bf16* __restrict__ zpre, const bf16* __restrict__ aux,
           int mode)
{
    extern __shared__ char dsm[];
    constexpr int NTI = NT / 32;
    constexpr int STG = (128 + NT) * 144;

    const int tid  = threadIdx.x;
    const int warp = tid >> 5, lane = tid & 31;
    const int grp  = lane >> 2, thr = lane & 3;
    const int wm   = warp & 1,  wn  = warp >> 1;
    const int m_base = wm * 64;
    const int n_base = wn * (NT / 4);
    const int row0 = blockIdx.y * 128;
    const int col0 = blockIdx.x * NT;
    const uint32_t sb = s2u(dsm);

    float acc[4][NTI][4];
#pragma unroll
    for (int i = 0; i < 4; i++)
#pragma unroll
        for (int j = 0; j < NTI; j++)
#pragma unroll
            for (int r = 0; r < 4; r++) acc[i][j][r] = 0.f;

    const int NC0 = K0 >> 6;
    const int NC  = NC0 + (K1 >> 6);

    auto load_stage = [&](int c, int buf) {
        const bf16 *a, *w; int k, kb;
        if (c < NC0) { a = A0; w = W0; k = K0; kb = c << 6; }
        else         { a = A1; w = W1; k = K1; kb = (c - NC0) << 6; }
        uint32_t ab = sb + (uint32_t)buf * STG;
#pragma unroll
        for (int i = 0; i < 4; i++) {
            int u = tid + i * 256;
            int r = u >> 3, cc = u & 7;
            cp16(ab + (uint32_t)(r * 144 + cc * 16),
                 a + (size_t)(row0 + r) * k + kb + cc * 8);
        }
        uint32_t bb = ab + 128u * 144u;
#pragma unroll
        for (int i = 0; i < NT / 32; i++) {
            int u = tid + i * 256;
            int r = u >> 3, cc = u & 7;
            cp16(bb + (uint32_t)(r * 144 + cc * 16),
                 w + (size_t)(col0 + r) * k + kb + cc * 8);
        }
        cp_commit();
    };

    load_stage(0, 0);
    if (NC > 1) load_stage(1, 1);

    for (int c = 0; c < NC; c++) {
        if (c == NC - 1) cp_wait0(); else cp_wait1();
        __syncthreads();
        if (c + 2 < NC) load_stage(c + 2, (c + 2) % 3);

        uint32_t ab = sb + (uint32_t)(c % 3) * STG;
        uint32_t bb = ab + 128u * 144u;

        const uint32_t a_lrow = (uint32_t)(lane & 15);
        const uint32_t a_koff = (uint32_t)((lane >> 4) << 3);
        const uint32_t b_cofs = (uint32_t)(((lane >> 4) << 3) + (lane & 7));
        const uint32_t b_koff = (uint32_t)(((lane >> 3) & 1) << 3);

#pragma unroll
        for (int ks = 0; ks < 4; ks++) {
            const int kc = ks * 16;
            uint32_t af[4][4], bfr[NTI][2];
#pragma unroll
            for (int mt = 0; mt < 4; mt++) {
                uint32_t addr = ab + (uint32_t)(m_base + mt * 16 + a_lrow) * 144u
                                   + (uint32_t)(kc + a_koff) * 2u;
                ldsm4(af[mt], addr);
            }
#pragma unroll
            for (int p = 0; p < NTI / 2; p++) {
                uint32_t col = (uint32_t)(n_base + p * 16) + b_cofs;
                uint32_t addr = bb + col * 144u + (uint32_t)(kc + b_koff) * 2u;
                uint32_t r[4];
                ldsm4(r, addr);
                bfr[2 * p][0]     = r[0]; bfr[2 * p][1]     = r[1];
                bfr[2 * p + 1][0] = r[2]; bfr[2 * p + 1][1] = r[3];
            }
#pragma unroll
            for (int mt = 0; mt < 4; mt++)
#pragma unroll
                for (int nt = 0; nt < NTI; nt++)
                    mma_bf16(acc[mt][nt], af[mt], bfr[nt]);
        }
    }

    // epilogue (vectorized pair stores)
#pragma unroll
    for (int mt = 0; mt < 4; mt++) {
#pragma unroll
        for (int nt = 0; nt < NTI; nt++) {
            int cbase = col0 + n_base + nt * 8 + thr * 2;
            float b0 = cadd, b1 = cadd;
            if (bias1) { b0 += bias1[cbase]; b1 += bias1[cbase + 1]; }
            if (bias2) { b0 += bias2[cbase]; b1 += bias2[cbase + 1]; }
#pragma unroll
            for (int half = 0; half < 2; half++) {
                int r = row0 + m_base + mt * 16 + grp + half * 8;
                size_t idx = (size_t)r * N + cbase;
                float v0 = acc[mt][nt][half * 2 + 0] + b0;
                float v1 = acc[mt][nt][half * 2 + 1] + b1;
                if (mode == 0) {
                    *reinterpret_cast<float2*>(Cf + idx) = make_float2(v0, v1);
                } else if (mode == 2) {
                    *reinterpret_cast<__nv_bfloat162*>(Cb + idx) = __floats2bfloat162_rn(v0, v1);
                } else if (mode == 3) {
                    *reinterpret_cast<__nv_bfloat162*>(Cb + idx) =
                        __floats2bfloat162_rn(fmaxf(v0, 0.f), fmaxf(v1, 0.f));
                } else if (mode == 4) {
                    __nv_bfloat162 a2 = *reinterpret_cast<const __nv_bfloat162*>(aux + idx);
                    float s0 = 1.f / (1.f + __expf(-v0));
                    float s1 = 1.f / (1.f + __expf(-v1));
                    *reinterpret_cast<__nv_bfloat162*>(Cb + idx) =
                        __floats2bfloat162_rn(s0 * __bfloat162float(a2.x),
                                              s1 * __bfloat162float(a2.y));
                } else {
                    __nv_bfloat162 z2 = *reinterpret_cast<const __nv_bfloat162*>(zpre + idx);
                    __nv_bfloat162 a2 = *reinterpret_cast<const __nv_bfloat162*>(aux + idx);
                    float z0 = 1.f / (1.f + __expf(-__bfloat162float(z2.x)));
                    float z1 = 1.f / (1.f + __expf(-__bfloat162float(z2.y)));
                    float o0 = (1.f - z0) * __bfloat162float(a2.x) + z0 * tanh_fast(v0);
                    float o1 = (1.f - z1) * __bfloat162float(a2.y) + z1 * tanh_fast(v1);
                    if (Cf) *reinterpret_cast<float2*>(Cf + idx) = make_float2(o0, o1);
                    if (Cb) *reinterpret_cast<__nv_bfloat162*>(Cb + idx) =
                        __floats2bfloat162_rn(o0, o1);
                }
            }
        }
    }
}

// ---------- exact fp32 GEMM, 64x64 tiles (critic head) ----------
__global__ void sgemm64_kernel(const float* __restrict__ A, const float* __restrict__ W,
                               float* __restrict__ C, int M, int N, int K,
                               const float* __restrict__ bias, float cadd, int flags)
{
    __shared__ float As[8][64];
    __shared__ float Bs[8][65];
    int tid = threadIdx.x;
    int row0 = blockIdx.y * 64, col0 = blockIdx.x * 64;
    int tx = tid & 15, ty = tid >> 4;
    float acc[4][4];
#pragma unroll
    for (int i = 0; i < 4; i++)
#pragma unroll
        for (int j = 0; j < 4; j++) acc[i][j] = 0.f;

    int ar = tid >> 2, ac2 = (tid & 3) * 2;
    int br = tid >> 5, bc = tid & 31;

    for (int k0 = 0; k0 < K; k0 += 8) {
        float2 a2 = *reinterpret_cast<const float2*>(A + (size_t)(row0 + ar) * K + k0 + ac2);
        As[ac2][ar] = a2.x;
        As[ac2 + 1][ar] = a2.y;
        float w0 = (col0 + bc < N)      ? W[(size_t)(k0 + br) * N + col0 + bc]      : 0.f;
        float w1 = (col0 + bc + 32 < N) ? W[(size_t)(k0 + br) * N + col0 + bc + 32] : 0.f;
        Bs[br][bc] = w0;
        Bs[br][bc + 32] = w1;
        __syncthreads();
#pragma unroll
        for (int kk = 0; kk < 8; kk++) {
            float av[4], bv[4];
#pragma unroll
            for (int i = 0; i < 4; i++) av[i] = As[kk][ty * 4 + i];
#pragma unroll
            for (int j = 0; j < 4; j++) bv[j] = Bs[kk][tx * 4 + j];
#pragma unroll
            for (int i = 0; i < 4; i++)
#pragma unroll
                for (int j = 0; j < 4; j++) acc[i][j] += av[i] * bv[j];
        }
        __syncthreads();
    }
#pragma unroll
    for (int i = 0; i < 4; i++) {
        int r = row0 + ty * 4 + i;
        if (r >= M) continue;
#pragma unroll
        for (int j = 0; j < 4; j++) {
            int c = col0 + tx * 4 + j;
            if (c >= N) continue;
            float val = acc[i][j] + cadd;
            if (bias) val += bias[c];
            size_t idx = (size_t)r * N + c;
            if (flags & 1) val += C[idx];
            if (flags & 2) val = fmaxf(val, 0.f);
            C[idx] = val;
        }
    }
}

// ---------- LayerNorm from f32; writes LN out (bf16) + raw bf16 copy ----------
__global__ void ln_kernel(const float* __restrict__ x, bf16* __restrict__ out,
                          bf16* __restrict__ rawb,
                          const float* __restrict__ g, const float* __restrict__ b, int rows)
{
    int warp = blockIdx.x * (blockDim.x >> 5) + (threadIdx.x >> 5);
    if (warp >= rows) return;
    int lane = threadIdx.x & 31;
    const float* xr = x + (size_t)warp * DD;
    float v[16], s1 = 0.f, s2 = 0.f;
#pragma unroll
    for (int i = 0; i < 16; i++) {
        float t = xr[i * 32 + lane];
        v[i] = t; s1 += t; s2 += t * t;
    }
#pragma unroll
    for (int o = 16; o; o >>= 1) {
        s1 += __shfl_xor_sync(0xffffffffu, s1, o);
        s2 += __shfl_xor_sync(0xffffffffu, s2, o);
    }
    float mu = s1 * (1.f / DD);
    float inv = rsqrtf(s2 * (1.f / DD) - mu * mu + 1e-5f);
    bf16* orow = out + (size_t)warp * DD;
    bf16* rrow = rawb ? rawb + (size_t)warp * DD : 0;
#pragma unroll
    for (int i = 0; i < 16; i++) {
        int d = i * 32 + lane;
        orow[d] = __float2bfloat16((v[i] - mu) * inv * g[d] + b[d]);
        if (rrow) rrow[d] = __float2bfloat16(v[i]);
    }
}

// ---------- LayerNorm from bf16 input ----------
__global__ void lnb_kernel(const bf16* __restrict__ x, bf16* __restrict__ out,
                           const float* __restrict__ g, const float* __restrict__ b, int rows)
{
    int warp = blockIdx.x * (blockDim.x >> 5) + (threadIdx.x >> 5);
    if (warp >= rows) return;
    int lane = threadIdx.x & 31;
    const bf16* xr = x + (size_t)warp * DD;
    float v[16], s1 = 0.f, s2 = 0.f;
#pragma unroll
    for (int i = 0; i < 16; i++) {
        float t = __bfloat162float(xr[i * 32 + lane]);
        v[i] = t; s1 += t; s2 += t * t;
    }
#pragma unroll
    for (int o = 16; o; o >>= 1) {
        s1 += __shfl_xor_sync(0xffffffffu, s1, o);
        s2 += __shfl_xor_sync(0xffffffffu, s2, o);
    }
    float mu = s1 * (1.f / DD);
    float inv = rsqrtf(s2 * (1.f / DD) - mu * mu + 1e-5f);
    bf16* orow = out + (size_t)warp * DD;
#pragma unroll
    for (int i = 0; i < 16; i++) {
        int d = i * 32 + lane;
        orow[d] = __float2bfloat16((v[i] - mu) * inv * g[d] + b[d]);
    }
}

// ---------- attention ----------
__global__ void attn_kernel(const float* __restrict__ qkv,
                            const float* __restrict__ p, const float* __restrict__ uu,
                            const float* __restrict__ vvec, bf16* __restrict__ av)
{
    int b = blockIdx.x, h = blockIdx.y;
    __shared__ float Ks[JJ][33];
    __shared__ float Vs[JJ][33];
    __shared__ float att[4][JJ];
    __shared__ float qsu[4][32];
    __shared__ float qsv[4][32];
    int tid = threadIdx.x;
    for (int idx = tid; idx < JJ * 32; idx += 128) {
        int j = idx >> 5, d = idx & 31;
        size_t rr = (j < MM) ? ((size_t)NROW + (size_t)j * BB + b)
                             : ((size_t)(j - MM) * BB + b);
        const float* row = qkv + rr * 192 + 64 + h * 32 + d;
        Ks[j][d] = row[0];
        Vs[j][d] = row[64];
    }
    __syncthreads();
    int warp = tid >> 5, lane = tid & 31;
    float ul = uu[h * 32 + lane], vl = vvec[h * 32 + lane];
    for (int i = warp; i < TT; i += 4) {
        float qv = qkv[((size_t)i * BB + b) * 192 + h * 32 + lane];
        qsu[warp][lane] = qv + ul;
        qsv[warp][lane] = qv + vl;
        __syncwarp();
        int jmax = i + MM;
        float sv[5], smax = -1e30f;
        int cnt = 0;
        for (int j = lane; j <= jmax; j += 32) {
            const float* prow = p + (size_t)(j + TT - 1 - i) * 64 + h * 32;
            float s = 0.f;
#pragma unroll
            for (int d = 0; d < 32; d++)
                s += qsu[warp][d] * Ks[j][d] + qsv[warp][d] * prow[d];
            s *= 0.1767766952966369f;
            sv[cnt++] = s;
            smax = fmaxf(smax, s);
        }
#pragma unroll
        for (int o = 16; o; o >>= 1) smax = fmaxf(smax, __shfl_xor_sync(0xffffffffu, smax, o));
        float sum = 0.f; cnt = 0;
        for (int j = lane; j <= jmax; j += 32) {
            float e = __expf(sv[cnt++] - smax);
            att[warp][j] = e;
            sum += e;
        }
#pragma unroll
        for (int o = 16; o; o >>= 1) sum += __shfl_xor_sync(0xffffffffu, sum, o);
        float inv = 1.f / sum;
        __syncwarp();
        float acc = 0.f;
#pragma unroll 4
        for (int j = 0; j <= jmax; j++) acc += att[warp][j] * Vs[j][lane];
        av[((size_t)i * BB + b) * 64 + h * 32 + lane] = __float2bfloat16(acc * inv);
        __syncwarp();
    }
}

// ---------- mega prep ----------
__device__ __forceinline__ void tpose_tile(const float* __restrict__ in, bf16* __restrict__ out,
                                           int K, int N)
{
    __shared__ float t[32][33];
    int k0 = blockIdx.y * 32, n0 = blockIdx.x * 32;
    if (k0 >= K || n0 >= N) return;
    int x = threadIdx.x, y = threadIdx.y;
    for (int i = y; i < 32; i += 8)
        t[i][x] = in[(size_t)(k0 + i) * N + n0 + x];
    __syncthreads();
    for (int i = y; i < 32; i += 8)
        out[(size_t)(n0 + i) * K + k0 + x] = __float2bfloat16(t[x][i]);
}

__global__ void megaprep_kernel(const float* __restrict__ g1W, const float* __restrict__ g2W,
                                const float* __restrict__ Wq, const float* __restrict__ Wkv,
                                const float* __restrict__ ffW1, const float* __restrict__ Wp,
                                const float* __restrict__ memory)
{
    int z = blockIdx.z;
    if (z < 12) {
        const float* in = ((z < 6) ? g1W : g2W) + (size_t)(z % 6) * DD * DD;
        bf16* out = ((z < 6) ? gb_g1 : gb_g2) + (size_t)(z % 6) * DD * DD;
        tpose_tile(in, out, DD, DD);
    } else if (z == 12) {
        tpose_tile(Wq, gb_wqkv, DD, 64);
    } else if (z == 13) {
        tpose_tile(Wkv, gb_wqkv + 64 * DD, DD, 128);
    } else if (z == 14) {
        tpose_tile(ffW1, gb_ff1, DD, DFF);
    } else if (z == 15) {
        int bid = blockIdx.y * 16 + blockIdx.x;
        int tid = threadIdx.y * 32 + threadIdx.x;
        const int n4 = MROW * DD / 4;
        bf16* dst = gb_lnm + (size_t)NROW * DD;
        for (int i = bid * 256 + tid; i < n4; i += 256 * 256) {
            float4 v = reinterpret_cast<const float4*>(memory)[i];
            __nv_bfloat162* o = reinterpret_cast<__nv_bfloat162*>(dst + (size_t)i * 4);
            o[0] = __floats2bfloat162_rn(v.x, v.y);
            o[1] = __floats2bfloat162_rn(v.z, v.w);
        }
    } else {
        int jj = blockIdx.y * 16 + blockIdx.x;
        if (jj >= JJ) return;
        __shared__ float pe[DD];
        int tid = threadIdx.y * 32 + threadIdx.x;
        float pos = (float)(JJ - 1 - jj);
        for (int d = tid; d < DD; d += 256) {
            int i = (d < 256) ? d : d - 256;
            float f = __expf(-(float)(2 * i) * (1.f / 512.f) * 9.210340371976184f);
            float a = pos * f;
            pe[d] = (d < 256) ? sinf(a) : cosf(a);
        }
        __syncthreads();
        if (tid < 64) {
            float acc = 0.f;
            for (int d = 0; d < DD; d++) acc += pe[d] * Wp[d * 64 + tid];
            g_p[jj * 64 + tid] = acc;
        }
    }
}

// ---------- folded-weight precompute ----------
__global__ void pregemm_kernel(const float* __restrict__ Wout, const float* __restrict__ ffW2,
                               const float* __restrict__ g1W, const float* __restrict__ g2W)
{
    __shared__ float sG[64][33];
    const int slot[3] = {0, 2, 4};
    int m = blockIdx.z;
    const float* A = (m < 3) ? Wout : ffW2;
    const float* G = ((m < 3) ? g1W : g2W) + (size_t)slot[m % 3] * DD * DD;
    bf16* out = gb_cw + (size_t)m * DD * 64;
    int n0 = blockIdx.x * 32, k0 = blockIdx.y * 8;
    int tx = threadIdx.x, ty = threadIdx.y;
    int tid = ty * 32 + tx;
    float acc = 0.f;
    for (int dc = 0; dc < 8; dc++) {
        __syncthreads();
        for (int idx = tid; idx < 64 * 32; idx += 256) {
            int i = idx >> 5, j = idx & 31;
            sG[i][j] = G[(size_t)(dc * 64 + i) * DD + n0 + j];
        }
        __syncthreads();
        const float* Ar = A + (size_t)(k0 + ty) * DD + dc * 64;
#pragma unroll 16
        for (int i = 0; i < 64; i++) acc += Ar[i] * sG[i][tx];
    }
    out[(size_t)(n0 + tx) * 64 + (k0 + ty)] = __float2bfloat16(acc);
}

// ---------- gate-2 combined bias ----------
__global__ void bc2_kernel(const float* __restrict__ ffb2, const float* __restrict__ g2W,
                           const float* __restrict__ g2b, float* __restrict__ bc)
{
    const int slot[3] = {0, 2, 4};
    int m = blockIdx.x;
    int n = threadIdx.x;
    const float* G = g2W + (size_t)slot[m] * DD * DD;
    float acc = g2b[(2 * m) * DD + n] + g2b[(2 * m + 1) * DD + n];
    for (int d = 0; d < DD; d++) acc += ffb2[d] * G[(size_t)d * DD + n];
    bc[m * DD + n] = acc;
}

// ---------- mean pool from bf16 ----------
__global__ void meanpool_bf_kernel(const bf16* __restrict__ in, float* __restrict__ ts)
{
    int idx = blockIdx.x * blockDim.x + threadIdx.x;   // pair index
    const int n2 = BB * DD / 2;
    if (idx >= n2) return;
    float s0 = 0.f, s1 = 0.f;
    for (int t = 0; t < TT; t++) {
        __nv_bfloat162 v = *reinterpret_cast<const __nv_bfloat162*>(in + (size_t)t * BB * DD + idx * 2);
        s0 += __bfloat162float(v.x);
        s1 += __bfloat162float(v.y);
    }
    const float inv = 1.f / TT;
    *reinterpret_cast<float2*>(ts + (size_t)idx * 2) = make_float2(s0 * inv, s1 * inv);
}

// ---------- final head ----------
__global__ void final_kernel(const float* __restrict__ h3, const float* __restrict__ w,
                             const float* __restrict__ bb, float* __restrict__ out)
{
    int row = blockIdx.x * 4 + (threadIdx.x >> 5);
    int lane = threadIdx.x & 31;
    if (row >= BB) return;
    float s = 0.f;
    for (int k = lane; k < 300; k += 32) s += h3[(size_t)row * 300 + k] * w[k];
#pragma unroll
    for (int o = 16; o; o >>= 1) s += __shfl_xor_sync(0xffffffffu, s, o);
    if (lane == 0) out[row] = fmaxf(s + bb[0], 0.f);
}

// ---------- host ----------
static inline void launch_tc(const bf16* A0, const bf16* W0, int K0,
                             const bf16* A1, const bf16* W1, int K1,
                             int M, int N, int NT,
                             float* Cf, bf16* Cb,
                             const float* b1, const float* b2, float cadd,
                             const bf16* zpre, const bf16* aux, int mode)
{
    dim3 grid(N / NT, M / 128);
    if (NT == 128) {
        size_t dsz = 3 * (size_t)(128 + 128) * 144;
        bgemm<128><<<grid, 256, dsz>>>(A0, W0, K0, A1, W1, K1, N, Cf, Cb, b1, b2, cadd, zpre, aux, mode);
    } else {
        size_t dsz = 3 * (size_t)(128 + 64) * 144;
        bgemm<64><<<grid, 256, dsz>>>(A0, W0, K0, A1, W1, K1, N, Cf, Cb, b1, b2, cadd, zpre, aux, mode);
    }
}
static inline void launch_sgemm(const float* A, const float* W, float* C,
                                int M, int N, int K, const float* bias, float cadd, int flags)
{
    dim3 grid((N + 63) / 64, (M + 63) / 64);
    sgemm64_kernel<<<grid, 256>>>(A, W, C, M, N, K, bias, cadd, flags);
}

extern "C" void kernel_launch(void* const* d_in, const int* in_sizes, int n_in,
                              void* d_out, int out_size)
{
    const float* x      = (const float*)d_in[0];
    const float* action = (const float*)d_in[1];
    const float* memory = (const float*)d_in[2];
    const float* W_q    = (const float*)d_in[3];
    const float* W_kv   = (const float*)d_in[4];
    const float* W_p    = (const float*)d_in[5];
    const float* W_out  = (const float*)d_in[6];
    const float* u      = (const float*)d_in[7];
    const float* v      = (const float*)d_in[8];
    const float* ln1_g  = (const float*)d_in[9];
    const float* ln1_b  = (const float*)d_in[10];
    const float* ln2_g  = (const float*)d_in[11];
    const float* ln2_b  = (const float*)d_in[12];
    const float* ff_W1  = (const float*)d_in[13];
    const float* ff_b1  = (const float*)d_in[14];
    const float* ff_W2  = (const float*)d_in[15];
    const float* ff_b2  = (const float*)d_in[16];
    const float* g1W    = (const float*)d_in[17];
    const float* g1b    = (const float*)d_in[18];
    const float* g2W    = (const float*)d_in[19];
    const float* g2b    = (const float*)d_in[20];
    const float* d1W    = (const float*)d_in[21];
    const float* d1b    = (const float*)d_in[22];
    const float* d2W    = (const float*)d_in[23];
    const float* d2b    = (const float*)d_in[24];
    const float* d3W    = (const float*)d_in[25];
    const float* d3b    = (const float*)d_in[26];
    const float* d4W    = (const float*)d_in[27];
    const float* d4b    = (const float*)d_in[28];

    cudaFuncSetAttribute(bgemm<128>, cudaFuncAttributeMaxDynamicSharedMemorySize, 111000);
    cudaFuncSetAttribute(bgemm<64>,  cudaFuncAttributeMaxDynamicSharedMemorySize, 84000);

    float *QKV, *P, *TS, *H1, *H2, *H3, *BC2;
    bf16 *XB, *LNM, *RXB, *ZB, *SRCB, *FFHB, *AVB;
    bf16 *WQKVT, *G1T, *G2T, *FF1T, *CW;
    cudaGetSymbolAddress((void**)&QKV,  g_qkv);
    cudaGetSymbolAddress((void**)&P,    g_p);
    cudaGetSymbolAddress((void**)&TS,   g_ts);
    cudaGetSymbolAddress((void**)&H1,   g_h1);
    cudaGetSymbolAddress((void**)&H2,   g_h2);
    cudaGetSymbolAddress((void**)&H3,   g_h3);
    cudaGetSymbolAddress((void**)&BC2,  g_bc2);
    cudaGetSymbolAddress((void**)&XB,   gb_x);
    cudaGetSymbolAddress((void**)&LNM,  gb_lnm);
    cudaGetSymbolAddress((void**)&RXB,  gb_rx);
    cudaGetSymbolAddress((void**)&ZB,   gb_z);
    cudaGetSymbolAddress((void**)&SRCB, gb_src);
    cudaGetSymbolAddress((void**)&FFHB, gb_ffh);
    cudaGetSymbolAddress((void**)&AVB,  gb_av);
    cudaGetSymbolAddress((void**)&WQKVT,gb_wqkv);
    cudaGetSymbolAddress((void**)&G1T,  gb_g1);
    cudaGetSymbolAddress((void**)&G2T,  gb_g2);
    cudaGetSymbolAddress((void**)&FF1T, gb_ff1);
    cudaGetSymbolAddress((void**)&CW,   gb_cw);

    const size_t SZ = (size_t)DD * DD;
    const size_t CWS = (size_t)DD * 64;

    // prep
    megaprep_kernel<<<dim3(16, 16, 17), dim3(32, 8)>>>(g1W, g2W, W_q, W_kv, ff_W1, W_p, memory);
    pregemm_kernel<<<dim3(16, 8, 6), dim3(32, 8)>>>(W_out, ff_W2, g1W, g2W);
    bc2_kernel<<<3, DD>>>(ff_b2, g2W, g2b, BC2);

    // LN1 -> LNM rows [0,NROW); also XB = bf16(x)
    ln_kernel<<<NROW / 8, 256>>>(x, LNM, XB, ln1_g, ln1_b, NROW);

    // fused qkv over src+memory rows (M=68608, N=192)
    launch_tc(LNM, WQKVT, DD, 0, 0, 0, AROW, 192, 64, QKV, 0, 0, 0, 0.f, 0, 0, 0);

    // attention -> AVB (bf16)
    attn_kernel<<<dim3(BB, HH), 128>>>(QKV, P, u, v, AVB);

    // gate 1 (y-side folded through W_out; K = 64 + 512)
    launch_tc(AVB, CW + 0 * CWS, 64, XB, G1T + 1 * SZ, DD, NROW, DD, 128,
              0, RXB, g1b + 0 * DD, g1b + 1 * DD, 0.f, 0, XB, 4);
    launch_tc(AVB, CW + 1 * CWS, 64, XB, G1T + 3 * SZ, DD, NROW, DD, 128,
              0, ZB, g1b + 2 * DD, g1b + 3 * DD, -BG, 0, 0, 2);
    launch_tc(AVB, CW + 2 * CWS, 64, RXB, G1T + 5 * SZ, DD, NROW, DD, 128,
              0, SRCB, g1b + 4 * DD, g1b + 5 * DD, 0.f, ZB, XB, 5);

    // ffh = relu(LN2(src) @ ff_W1 + b1)   (ff2 folded into gate-2 weights)
    lnb_kernel<<<NROW / 8, 256>>>(SRCB, LNM, ln2_g, ln2_b, NROW);
    launch_tc(LNM, FF1T, DD, 0, 0, 0, NROW, DFF, 64, 0, FFHB, ff_b1, 0, 0.f, 0, 0, 3);

    // gate 2 (y-side = ff folded through ff_W2; K = 64 + 512; biases pre-combined)
    launch_tc(FFHB, CW + 3 * CWS, 64, SRCB, G2T + 1 * SZ, DD, NROW, DD, 128,
              0, RXB, BC2 + 0 * DD, 0, 0.f, 0, SRCB, 4);
    launch_tc(FFHB, CW + 4 * CWS, 64, SRCB, G2T + 3 * SZ, DD, NROW, DD, 128,
              0, ZB, BC2 + 1 * DD, 0, -BG, 0, 0, 2);
    launch_tc(FFHB, CW + 5 * CWS, 64, RXB, G2T + 5 * SZ, DD, NROW, DD, 128,
              0, XB, BC2 + 2 * DD, 0, 0.f, ZB, SRCB, 5);      // bf16 out -> XB

    // mean pool (bf16 in, f32 out)
    meanpool_bf_kernel<<<(BB * DD / 2 + 255) / 256, 256>>>(XB, TS);

    // critic head (exact fp32)
    launch_sgemm(TS, d1W, H1, BB, 1024, DD, d1b, 0.f, 2);
    launch_sgemm(H1, d2W, H2, BB, 512, 1024, nullptr, 0.f, 0);
    launch_sgemm(action, d2W + (size_t)1024 * 512, H2, BB, 512, ACT, d2b, 0.f, 3);
    launch_sgemm(H2, d3W, H3, BB, 300, DD, d3b, 0.f, 2);
    final_kernel<<<BB / 4, 128>>>(H3, d4W, d4b, (float*)d_out);
}

// round 15
// speedup vs baseline: 1.3826x; 1.0251x over previous
#include <cuda_runtime.h>
#include <cuda_bf16.h>
#include <math.h>
#include <stdint.h>

#define TT   128
#define BB   512
#define DD   512
#define MM   6
#define JJ   (TT + MM)
#define HH   2
#define DFF  64
#define ACT  64
#define NROW (TT * BB)
#define MROW (MM * BB)
#define AROW (NROW + MROW)
#define BG   0.1f

typedef __nv_bfloat16 bf16;

// ---------- static scratch ----------
__device__ __align__(256) float g_qkv[AROW * 192];
__device__ __align__(256) float g_p  [JJ * 64];
__device__ __align__(256) float g_ts [BB * DD];
__device__ __align__(256) float g_h1 [BB * 1024];
__device__ __align__(256) float g_h2 [BB * 512];
__device__ __align__(256) float g_h3 [BB * 300];
__device__ __align__(256) float g_bc2[3 * DD];
__device__ __align__(256) bf16 gb_x   [NROW * DD];
__device__ __align__(256) bf16 gb_lnm [AROW * DD];
__device__ __align__(256) bf16 gb_rx  [NROW * DD];
__device__ __align__(256) bf16 gb_z   [NROW * DD];
__device__ __align__(256) bf16 gb_src [NROW * DD];
__device__ __align__(256) bf16 gb_ffh [NROW * DFF];
__device__ __align__(256) bf16 gb_av  [NROW * 64];
__device__ __align__(256) bf16 gb_wqkv[192 * DD];
__device__ __align__(256) bf16 gb_g1  [6 * DD * DD];
__device__ __align__(256) bf16 gb_g2  [6 * DD * DD];
__device__ __align__(256) bf16 gb_ff1 [DFF * DD];
__device__ __align__(256) bf16 gb_cw  [6 * DD * 64];

// ---------- helpers ----------
__device__ __forceinline__ uint32_t s2u(const void* p) {
    return (uint32_t)__cvta_generic_to_shared(p);
}
__device__ __forceinline__ void cp16(uint32_t s, const void* g) {
    asm volatile("cp.async.cg.shared.global [%0], [%1], 16;" :: "r"(s), "l"(g));
}
__device__ __forceinline__ void cp_commit() { asm volatile("cp.async.commit_group;" ::: "memory"); }
__device__ __forceinline__ void cp_wait0()  { asm volatile("cp.async.wait_group 0;" ::: "memory"); }
__device__ __forceinline__ void cp_wait1()  { asm volatile("cp.async.wait_group 1;" ::: "memory"); }
__device__ __forceinline__ void ldsm4(uint32_t* r, uint32_t addr) {
    asm volatile("ldmatrix.sync.aligned.m8n8.x4.shared.b16 {%0,%1,%2,%3}, [%4];"
                 : "=r"(r[0]), "=r"(r[1]), "=r"(r[2]), "=r"(r[3]) : "r"(addr));
}
__device__ __forceinline__ void mma_bf16(float* c, const uint32_t* a, const uint32_t* b) {
    asm volatile(
        "mma.sync.aligned.m16n8k16.row.col.f32.bf16.bf16.f32 "
        "{%0,%1,%2,%3}, {%4,%5,%6,%7}, {%8,%9}, {%0,%1,%2,%3};"
        : "+f"(c[0]), "+f"(c[1]), "+f"(c[2]), "+f"(c[3])
        : "r"(a[0]), "r"(a[1]), "r"(a[2]), "r"(a[3]), "r"(b[0]), "r"(b[1]));
}
__device__ __forceinline__ float tanh_fast(float x) {
    float r;
    asm("tanh.approx.f32 %0, %1;" : "=f"(r) : "f"(x));
    return r;
}
__device__ __forceinline__ float sig_fast(float x) {
    return fmaf(0.5f, tanh_fast(0.5f * x), 0.5f);
}

// ---------- bf16 dual-source tensor GEMM ----------
// modes: 0 f32 | 2 bf16 | 3 bf16 relu | 4 bf16 = sigmoid(v)*aux(bf16)
//        5 (1-sig(zpre))*aux + sig(zpre)*tanh(v) -> Cf and/or Cb

template<int NT>
__global__ __launch_bounds__(256, 2)
void bgemm(const bf16* __restrict__ A0, const bf16* __restrict__ W0, int K0,
           const bf16* __restrict__ A1, const bf16* __restrict__ W1, int K1,
           int N,
           float* __restrict__ Cf, bf16* __restrict__ Cb,
           const float* __restrict__ bias1, const float* __restrict__ bias2,
           float cadd, const bf16* __restrict__ zpre, const bf16* __restrict__ aux,
           int mode)
{
    extern __shared__ char dsm[];
    constexpr int NTI = NT / 32;
    constexpr int STG = (128 + NT) * 144;

    const int tid  = threadIdx.x;
    const int warp = tid >> 5, lane = tid & 31;
    const int grp  = lane >> 2, thr = lane & 3;
    const int wm   = warp & 1,  wn  = warp >> 1;
    const int m_base = wm * 64;
    const int n_base = wn * (NT / 4);
    const int row0 = blockIdx.y * 128;
    const int col0 = blockIdx.x * NT;
    const uint32_t sb = s2u(dsm);

    float acc[4][NTI][4];
#pragma unroll
    for (int i = 0; i < 4; i++)
#pragma unroll
        for (int j = 0; j < NTI; j++)
#pragma unroll
            for (int r = 0; r < 4; r++) acc[i][j][r] = 0.f;

    const int NC0 = K0 >> 6;
    const int NC  = NC0 + (K1 >> 6);

    auto load_stage = [&](int c, int buf) {
        const bf16 *a, *w; int k, kb;
        if (c < NC0) { a = A0; w = W0; k = K0; kb = c << 6; }
        else         { a = A1; w = W1; k = K1; kb = (c - NC0) << 6; }
        uint32_t ab = sb + (uint32_t)buf * STG;
#pragma unroll
        for (int i = 0; i < 4; i++) {
            int u = tid + i * 256;
            int r = u >> 3, cc = u & 7;
            cp16(ab + (uint32_t)(r * 144 + cc * 16),
                 a + (size_t)(row0 + r) * k + kb + cc * 8);
        }
        uint32_t bb = ab + 128u * 144u;
#pragma unroll
        for (int i = 0; i < NT / 32; i++) {
            int u = tid + i * 256;
            int r = u >> 3, cc = u & 7;
            cp16(bb + (uint32_t)(r * 144 + cc * 16),
                 w + (size_t)(col0 + r) * k + kb + cc * 8);
        }
        cp_commit();
    };

    load_stage(0, 0);
    if (NC > 1) load_stage(1, 1);

    for (int c = 0; c < NC; c++) {
        if (c == NC - 1) cp_wait0(); else cp_wait1();
        __syncthreads();
        if (c + 2 < NC) load_stage(c + 2, (c + 2) % 3);

        uint32_t ab = sb + (uint32_t)(c % 3) * STG;
        uint32_t bb = ab + 128u * 144u;

        const uint32_t a_lrow = (uint32_t)(lane & 15);
        const uint32_t a_koff = (uint32_t)((lane >> 4) << 3);
        const uint32_t b_cofs = (uint32_t)(((lane >> 4) << 3) + (lane & 7));
        const uint32_t b_koff = (uint32_t)(((lane >> 3) & 1) << 3);

#pragma unroll
        for (int ks = 0; ks < 4; ks++) {
            const int kc = ks * 16;
            uint32_t af[4][4], bfr[NTI][2];
#pragma unroll
            for (int mt = 0; mt < 4; mt++) {
                uint32_t addr = ab + (uint32_t)(m_base + mt * 16 + a_lrow) * 144u
                                   + (uint32_t)(kc + a_koff) * 2u;
                ldsm4(af[mt], addr);
            }
#pragma unroll
            for (int p = 0; p < NTI / 2; p++) {
                uint32_t col = (uint32_t)(n_base + p * 16) + b_cofs;
                uint32_t addr = bb + col * 144u + (uint32_t)(kc + b_koff) * 2u;
                uint32_t r[4];
                ldsm4(r, addr);
                bfr[2 * p][0]     = r[0]; bfr[2 * p][1]     = r[1];
                bfr[2 * p + 1][0] = r[2]; bfr[2 * p + 1][1] = r[3];
            }
#pragma unroll
            for (int mt = 0; mt < 4; mt++)
#pragma unroll
                for (int nt = 0; nt < NTI; nt++)
                    mma_bf16(acc[mt][nt], af[mt], bfr[nt]);
        }
    }

    // epilogue (vectorized pair stores)
#pragma unroll
    for (int mt = 0; mt < 4; mt++) {
#pragma unroll
        for (int nt = 0; nt < NTI; nt++) {
            int cbase = col0 + n_base + nt * 8 + thr * 2;
            float b0 = cadd, b1 = cadd;
            if (bias1) { b0 += bias1[cbase]; b1 += bias1[cbase + 1]; }
            if (bias2) { b0 += bias2[cbase]; b1 += bias2[cbase + 1]; }
#pragma unroll
            for (int half = 0; half < 2; half++) {
                int r = row0 + m_base + mt * 16 + grp + half * 8;
                size_t idx = (size_t)r * N + cbase;
                float v0 = acc[mt][nt][half * 2 + 0] + b0;
                float v1 = acc[mt][nt][half * 2 + 1] + b1;
                if (mode == 0) {
                    *reinterpret_cast<float2*>(Cf + idx) = make_float2(v0, v1);
                } else if (mode == 2) {
                    *reinterpret_cast<__nv_bfloat162*>(Cb + idx) = __floats2bfloat162_rn(v0, v1);
                } else if (mode == 3) {
                    *reinterpret_cast<__nv_bfloat162*>(Cb + idx) =
                        __floats2bfloat162_rn(fmaxf(v0, 0.f), fmaxf(v1, 0.f));
                } else if (mode == 4) {
                    __nv_bfloat162 a2 = *reinterpret_cast<const __nv_bfloat162*>(aux + idx);
                    *reinterpret_cast<__nv_bfloat162*>(Cb + idx) =
                        __floats2bfloat162_rn(sig_fast(v0) * __bfloat162float(a2.x),
                                              sig_fast(v1) * __bfloat162float(a2.y));
                } else {
                    __nv_bfloat162 z2 = *reinterpret_cast<const __nv_bfloat162*>(zpre + idx);
                    __nv_bfloat162 a2 = *reinterpret_cast<const __nv_bfloat162*>(aux + idx);
                    float z0 = sig_fast(__bfloat162float(z2.x));
                    float z1 = sig_fast(__bfloat162float(z2.y));
                    float o0 = (1.f - z0) * __bfloat162float(a2.x) + z0 * tanh_fast(v0);
                    float o1 = (1.f - z1) * __bfloat162float(a2.y) + z1 * tanh_fast(v1);
                    if (Cf) *reinterpret_cast<float2*>(Cf + idx) = make_float2(o0, o1);
                    if (Cb) *reinterpret_cast<__nv_bfloat162*>(Cb + idx) =
                        __floats2bfloat162_rn(o0, o1);
                }
            }
        }
    }
}

// ---------- exact fp32 GEMM, 64x64 tiles (critic head) ----------
__global__ void sgemm64_kernel(const float* __restrict__ A, const float* __restrict__ W,
                               float* __restrict__ C, int M, int N, int K,
                               const float* __restrict__ bias, float cadd, int flags)
{
    __shared__ float As[8][64];
    __shared__ float Bs[8][65];
    int tid = threadIdx.x;
    int row0 = blockIdx.y * 64, col0 = blockIdx.x * 64;
    int tx = tid & 15, ty = tid >> 4;
    float acc[4][4];
#pragma unroll
    for (int i = 0; i < 4; i++)
#pragma unroll
        for (int j = 0; j < 4; j++) acc[i][j] = 0.f;

    int ar = tid >> 2, ac2 = (tid & 3) * 2;
    int br = tid >> 5, bc = tid & 31;

    for (int k0 = 0; k0 < K; k0 += 8) {
        float2 a2 = *reinterpret_cast<const float2*>(A + (size_t)(row0 + ar) * K + k0 + ac2);
        As[ac2][ar] = a2.x;
        As[ac2 + 1][ar] = a2.y;
        float w0 = (col0 + bc < N)      ? W[(size_t)(k0 + br) * N + col0 + bc]      : 0.f;
        float w1 = (col0 + bc + 32 < N) ? W[(size_t)(k0 + br) * N + col0 + bc + 32] : 0.f;
        Bs[br][bc] = w0;
        Bs[br][bc + 32] = w1;
        __syncthreads();
#pragma unroll
        for (int kk = 0; kk < 8; kk++) {
            float av[4], bv[4];
#pragma unroll
            for (int i = 0; i < 4; i++) av[i] = As[kk][ty * 4 + i];
#pragma unroll
            for (int j = 0; j < 4; j++) bv[j] = Bs[kk][tx * 4 + j];
#pragma unroll
            for (int i = 0; i < 4; i++)
#pragma unroll
                for (int j = 0; j < 4; j++) acc[i][j] += av[i] * bv[j];
        }
        __syncthreads();
    }
#pragma unroll
    for (int i = 0; i < 4; i++) {
        int r = row0 + ty * 4 + i;
        if (r >= M) continue;
#pragma unroll
        for (int j = 0; j < 4; j++) {
            int c = col0 + tx * 4 + j;
            if (c >= N) continue;
            float val = acc[i][j] + cadd;
            if (bias) val += bias[c];
            size_t idx = (size_t)r * N + c;
            if (flags & 1) val += C[idx];
            if (flags & 2) val = fmaxf(val, 0.f);
            C[idx] = val;
        }
    }
}

// ---------- LayerNorm from f32 (vectorized); LN out bf16 + raw bf16 copy ----------
__global__ void ln_kernel(const float* __restrict__ x, bf16* __restrict__ out,
                          bf16* __restrict__ rawb,
                          const float* __restrict__ g, const float* __restrict__ b, int rows)
{
    int warp = blockIdx.x * (blockDim.x >> 5) + (threadIdx.x >> 5);
    if (warp >= rows) return;
    int lane = threadIdx.x & 31;
    const float4* xr = reinterpret_cast<const float4*>(x + (size_t)warp * DD);
    float4 v[4];
    float s1 = 0.f, s2 = 0.f;
#pragma unroll
    for (int i = 0; i < 4; i++) {
        v[i] = xr[i * 32 + lane];
        s1 += v[i].x + v[i].y + v[i].z + v[i].w;
        s2 += v[i].x * v[i].x + v[i].y * v[i].y + v[i].z * v[i].z + v[i].w * v[i].w;
    }
#pragma unroll
    for (int o = 16; o; o >>= 1) {
        s1 += __shfl_xor_sync(0xffffffffu, s1, o);
        s2 += __shfl_xor_sync(0xffffffffu, s2, o);
    }
    float mu = s1 * (1.f / DD);
    float inv = rsqrtf(s2 * (1.f / DD) - mu * mu + 1e-5f);
    const float4* g4 = reinterpret_cast<const float4*>(g);
    const float4* b4 = reinterpret_cast<const float4*>(b);
    uint2* orow = reinterpret_cast<uint2*>(out + (size_t)warp * DD);
    uint2* rrow = rawb ? reinterpret_cast<uint2*>(rawb + (size_t)warp * DD) : 0;
#pragma unroll
    for (int i = 0; i < 4; i++) {
        int q = i * 32 + lane;
        float4 gg = g4[q], bb = b4[q];
        float o0 = (v[i].x - mu) * inv * gg.x + bb.x;
        float o1 = (v[i].y - mu) * inv * gg.y + bb.y;
        float o2 = (v[i].z - mu) * inv * gg.z + bb.z;
        float o3 = (v[i].w - mu) * inv * gg.w + bb.w;
        __nv_bfloat162 p0 = __floats2bfloat162_rn(o0, o1);
        __nv_bfloat162 p1 = __floats2bfloat162_rn(o2, o3);
        uint2 pk;
        pk.x = *reinterpret_cast<uint32_t*>(&p0);
        pk.y = *reinterpret_cast<uint32_t*>(&p1);
        orow[q] = pk;
        if (rrow) {
            __nv_bfloat162 r0 = __floats2bfloat162_rn(v[i].x, v[i].y);
            __nv_bfloat162 r1 = __floats2bfloat162_rn(v[i].z, v[i].w);
            uint2 rk;
            rk.x = *reinterpret_cast<uint32_t*>(&r0);
            rk.y = *reinterpret_cast<uint32_t*>(&r1);
            rrow[q] = rk;
        }
    }
}

// ---------- LayerNorm from bf16 input (vectorized) ----------
__global__ void lnb_kernel(const bf16* __restrict__ x, bf16* __restrict__ out,
                           const float* __restrict__ g, const float* __restrict__ b, int rows)
{
    int warp = blockIdx.x * (blockDim.x >> 5) + (threadIdx.x >> 5);
    if (warp >= rows) return;
    int lane = threadIdx.x & 31;
    const uint2* xr = reinterpret_cast<const uint2*>(x + (size_t)warp * DD);
    float v[16];
    float s1 = 0.f, s2 = 0.f;
#pragma unroll
    for (int i = 0; i < 4; i++) {
        uint2 pk = xr[i * 32 + lane];
        __nv_bfloat162 p0 = *reinterpret_cast<__nv_bfloat162*>(&pk.x);
        __nv_bfloat162 p1 = *reinterpret_cast<__nv_bfloat162*>(&pk.y);
        float t0 = __bfloat162float(p0.x), t1 = __bfloat162float(p0.y);
        float t2 = __bfloat162float(p1.x), t3 = __bfloat162float(p1.y);
        v[i * 4 + 0] = t0; v[i * 4 + 1] = t1; v[i * 4 + 2] = t2; v[i * 4 + 3] = t3;
        s1 += t0 + t1 + t2 + t3;
        s2 += t0 * t0 + t1 * t1 + t2 * t2 + t3 * t3;
    }
#pragma unroll
    for (int o = 16; o; o >>= 1) {
        s1 += __shfl_xor_sync(0xffffffffu, s1, o);
        s2 += __shfl_xor_sync(0xffffffffu, s2, o);
    }
    float mu = s1 * (1.f / DD);
    float inv = rsqrtf(s2 * (1.f / DD) - mu * mu + 1e-5f);
    const float4* g4 = reinterpret_cast<const float4*>(g);
    const float4* b4 = reinterpret_cast<const float4*>(b);
    uint2* orow = reinterpret_cast<uint2*>(out + (size_t)warp * DD);
#pragma unroll
    for (int i = 0; i < 4; i++) {
        int q = i * 32 + lane;
        float4 gg = g4[q], bb = b4[q];
        float o0 = (v[i * 4 + 0] - mu) * inv * gg.x + bb.x;
        float o1 = (v[i * 4 + 1] - mu) * inv * gg.y + bb.y;
        float o2 = (v[i * 4 + 2] - mu) * inv * gg.z + bb.z;
        float o3 = (v[i * 4 + 3] - mu) * inv * gg.w + bb.w;
        __nv_bfloat162 p0 = __floats2bfloat162_rn(o0, o1);
        __nv_bfloat162 p1 = __floats2bfloat162_rn(o2, o3);
        uint2 pk;
        pk.x = *reinterpret_cast<uint32_t*>(&p0);
        pk.y = *reinterpret_cast<uint32_t*>(&p1);
        orow[q] = pk;
    }
}

// ---------- attention ----------
__global__ void attn_kernel(const float* __restrict__ qkv,
                            const float* __restrict__ p, const float* __restrict__ uu,
                            const float* __restrict__ vvec, bf16* __restrict__ av)
{
    int b = blockIdx.x, h = blockIdx.y;
    __shared__ float Ks[JJ][33];
    __shared__ float Vs[JJ][33];
    __shared__ float att[4][JJ];
    __shared__ float qsu[4][32];
    __shared__ float qsv[4][32];
    int tid = threadIdx.x;
    for (int idx = tid; idx < JJ * 32; idx += 128) {
        int j = idx >> 5, d = idx & 31;
        size_t rr = (j < MM) ? ((size_t)NROW + (size_t)j * BB + b)
                             : ((size_t)(j - MM) * BB + b);
        const float* row = qkv + rr * 192 + 64 + h * 32 + d;
        Ks[j][d] = row[0];
        Vs[j][d] = row[64];
    }
    __syncthreads();
    int warp = tid >> 5, lane = tid & 31;
    float ul = uu[h * 32 + lane], vl = vvec[h * 32 + lane];
    for (int i = warp; i < TT; i += 4) {
        float qv = qkv[((size_t)i * BB + b) * 192 + h * 32 + lane];
        qsu[warp][lane] = qv + ul;
        qsv[warp][lane] = qv + vl;
        __syncwarp();
        int jmax = i + MM;
        float sv[5], smax = -1e30f;
        int cnt = 0;
        for (int j = lane; j <= jmax; j += 32) {
            const float* prow = p + (size_t)(j + TT - 1 - i) * 64 + h * 32;
            float s = 0.f;
#pragma unroll
            for (int d = 0; d < 32; d++)
                s += qsu[warp][d] * Ks[j][d] + qsv[warp][d] * prow[d];
            s *= 0.1767766952966369f;
            sv[cnt++] = s;
            smax = fmaxf(smax, s);
        }
#pragma unroll
        for (int o = 16; o; o >>= 1) smax = fmaxf(smax, __shfl_xor_sync(0xffffffffu, smax, o));
        float sum = 0.f; cnt = 0;
        for (int j = lane; j <= jmax; j += 32) {
            float e = __expf(sv[cnt++] - smax);
            att[warp][j] = e;
            sum += e;
        }
#pragma unroll
        for (int o = 16; o; o >>= 1) sum += __shfl_xor_sync(0xffffffffu, sum, o);
        float inv = 1.f / sum;
        __syncwarp();
        float acc = 0.f;
#pragma unroll 4
        for (int j = 0; j <= jmax; j++) acc += att[warp][j] * Vs[j][lane];
        av[((size_t)i * BB + b) * 64 + h * 32 + lane] = __float2bfloat16(acc * inv);
        __syncwarp();
    }
}

// ---------- mega prep ----------
__device__ __forceinline__ void tpose_tile(const float* __restrict__ in, bf16* __restrict__ out,
                                           int K, int N)
{
    __shared__ float t[32][33];
    int k0 = blockIdx.y * 32, n0 = blockIdx.x * 32;
    if (k0 >= K || n0 >= N) return;
    int x = threadIdx.x, y = threadIdx.y;
    for (int i = y; i < 32; i += 8)
        t[i][x] = in[(size_t)(k0 + i) * N + n0 + x];
    __syncthreads();
    for (int i = y; i < 32; i += 8)
        out[(size_t)(n0 + i) * K + k0 + x] = __float2bfloat16(t[x][i]);
}

__global__ void megaprep_kernel(const float* __restrict__ g1W, const float* __restrict__ g2W,
                                const float* __restrict__ Wq, const float* __restrict__ Wkv,
                                const float* __restrict__ ffW1, const float* __restrict__ Wp,
                                const float* __restrict__ memory)
{
    int z = blockIdx.z;
    if (z < 12) {
        const float* in = ((z < 6) ? g1W : g2W) + (size_t)(z % 6) * DD * DD;
        bf16* out = ((z < 6) ? gb_g1 : gb_g2) + (size_t)(z % 6) * DD * DD;
        tpose_tile(in, out, DD, DD);
    } else if (z == 12) {
        tpose_tile(Wq, gb_wqkv, DD, 64);
    } else if (z == 13) {
        tpose_tile(Wkv, gb_wqkv + 64 * DD, DD, 128);
    } else if (z == 14) {
        tpose_tile(ffW1, gb_ff1, DD, DFF);
    } else if (z == 15) {
        int bid = blockIdx.y * 16 + blockIdx.x;
        int tid = threadIdx.y * 32 + threadIdx.x;
        const int n4 = MROW * DD / 4;
        bf16* dst = gb_lnm + (size_t)NROW * DD;
        for (int i = bid * 256 + tid; i < n4; i += 256 * 256) {
            float4 v = reinterpret_cast<const float4*>(memory)[i];
            __nv_bfloat162* o = reinterpret_cast<__nv_bfloat162*>(dst + (size_t)i * 4);
            o[0] = __floats2bfloat162_rn(v.x, v.y);
            o[1] = __floats2bfloat162_rn(v.z, v.w);
        }
    } else {
        int jj = blockIdx.y * 16 + blockIdx.x;
        if (jj >= JJ) return;
        __shared__ float pe[DD];
        int tid = threadIdx.y * 32 + threadIdx.x;
        float pos = (float)(JJ - 1 - jj);
        for (int d = tid; d < DD; d += 256) {
            int i = (d < 256) ? d : d - 256;
            float f = __expf(-(float)(2 * i) * (1.f / 512.f) * 9.210340371976184f);
            float a = pos * f;
            pe[d] = (d < 256) ? sinf(a) : cosf(a);
        }
        __syncthreads();
        if (tid < 64) {
            float acc = 0.f;
            for (int d = 0; d < DD; d++) acc += pe[d] * Wp[d * 64 + tid];
            g_p[jj * 64 + tid] = acc;
        }
    }
}

// ---------- folded-weight precompute ----------
__global__ void pregemm_kernel(const float* __restrict__ Wout, const float* __restrict__ ffW2,
                               const float* __restrict__ g1W, const float* __restrict__ g2W)
{
    __shared__ float sG[64][33];
    const int slot[3] = {0, 2, 4};
    int m = blockIdx.z;
    const float* A = (m < 3) ? Wout : ffW2;
    const float* G = ((m < 3) ? g1W : g2W) + (size_t)slot[m % 3] * DD * DD;
    bf16* out = gb_cw + (size_t)m * DD * 64;
    int n0 = blockIdx.x * 32, k0 = blockIdx.y * 8;
    int tx = threadIdx.x, ty = threadIdx.y;
    int tid = ty * 32 + tx;
    float acc = 0.f;
    for (int dc = 0; dc < 8; dc++) {
        __syncthreads();
        for (int idx = tid; idx < 64 * 32; idx += 256) {
            int i = idx >> 5, j = idx & 31;
            sG[i][j] = G[(size_t)(dc * 64 + i) * DD + n0 + j];
        }
        __syncthreads();
        const float* Ar = A + (size_t)(k0 + ty) * DD + dc * 64;
#pragma unroll 16
        for (int i = 0; i < 64; i++) acc += Ar[i] * sG[i][tx];
    }
    out[(size_t)(n0 + tx) * 64 + (k0 + ty)] = __float2bfloat16(acc);
}

// ---------- gate-2 combined bias ----------
__global__ void bc2_kernel(const float* __restrict__ ffb2, const float* __restrict__ g2W,
                           const float* __restrict__ g2b, float* __restrict__ bc)
{
    const int slot[3] = {0, 2, 4};
    int m = blockIdx.x;
    int n = threadIdx.x;
    const float* G = g2W + (size_t)slot[m] * DD * DD;
    float acc = g2b[(2 * m) * DD + n] + g2b[(2 * m + 1) * DD + n];
    for (int d = 0; d < DD; d++) acc += ffb2[d] * G[(size_t)d * DD + n];
    bc[m * DD + n] = acc;
}

// ---------- mean pool from bf16 ----------
__global__ void meanpool_bf_kernel(const bf16* __restrict__ in, float* __restrict__ ts)
{
    int idx = blockIdx.x * blockDim.x + threadIdx.x;
    const int n2 = BB * DD / 2;
    if (idx >= n2) return;
    float s0 = 0.f, s1 = 0.f;
    for (int t = 0; t < TT; t++) {
        __nv_bfloat162 v = *reinterpret_cast<const __nv_bfloat162*>(in + (size_t)t * BB * DD + idx * 2);
        s0 += __bfloat162float(v.x);
        s1 += __bfloat162float(v.y);
    }
    const float inv = 1.f / TT;
    *reinterpret_cast<float2*>(ts + (size_t)idx * 2) = make_float2(s0 * inv, s1 * inv);
}

// ---------- final head ----------
__global__ void final_kernel(const float* __restrict__ h3, const float* __restrict__ w,
                             const float* __restrict__ bb, float* __restrict__ out)
{
    int row = blockIdx.x * 4 + (threadIdx.x >> 5);
    int lane = threadIdx.x & 31;
    if (row >= BB) return;
    float s = 0.f;
    for (int k = lane; k < 300; k += 32) s += h3[(size_t)row * 300 + k] * w[k];
#pragma unroll
    for (int o = 16; o; o >>= 1) s += __shfl_xor_sync(0xffffffffu, s, o);
    if (lane == 0) out[row] = fmaxf(s + bb[0], 0.f);
}

// ---------- host ----------
static inline void launch_tc(const bf16* A0, const bf16* W0, int K0,
                             const bf16* A1, const bf16* W1, int K1,
                             int M, int N, int NT,
                             float* Cf, bf16* Cb,
                             const float* b1, const float* b2, float cadd,
                             const bf16* zpre, const bf16* aux, int mode)
{
    dim3 grid(N / NT, M / 128);
    if (NT == 128) {
        size_t dsz = 3 * (size_t)(128 + 128) * 144;
        bgemm<128><<<grid, 256, dsz>>>(A0, W0, K0, A1, W1, K1, N, Cf, Cb, b1, b2, cadd, zpre, aux, mode);
    } else {
        size_t dsz = 3 * (size_t)(128 + 64) * 144;
        bgemm<64><<<grid, 256, dsz>>>(A0, W0, K0, A1, W1, K1, N, Cf, Cb, b1, b2, cadd, zpre, aux, mode);
    }
}
static inline void launch_sgemm(const float* A, const float* W, float* C,
                                int M, int N, int K, const float* bias, float cadd, int flags)
{
    dim3 grid((N + 63) / 64, (M + 63) / 64);
    sgemm64_kernel<<<grid, 256>>>(A, W, C, M, N, K, bias, cadd, flags);
}

extern "C" void kernel_launch(void* const* d_in, const int* in_sizes, int n_in,
                              void* d_out, int out_size)
{
    const float* x      = (const float*)d_in[0];
    const float* action = (const float*)d_in[1];
    const float* memory = (const float*)d_in[2];
    const float* W_q    = (const float*)d_in[3];
    const float* W_kv   = (const float*)d_in[4];
    const float* W_p    = (const float*)d_in[5];
    const float* W_out  = (const float*)d_in[6];
    const float* u      = (const float*)d_in[7];
    const float* v      = (const float*)d_in[8];
    const float* ln1_g  = (const float*)d_in[9];
    const float* ln1_b  = (const float*)d_in[10];
    const float* ln2_g  = (const float*)d_in[11];
    const float* ln2_b  = (const float*)d_in[12];
    const float* ff_W1  = (const float*)d_in[13];
    const float* ff_b1  = (const float*)d_in[14];
    const float* ff_W2  = (const float*)d_in[15];
    const float* ff_b2  = (const float*)d_in[16];
    const float* g1W    = (const float*)d_in[17];
    const float* g1b    = (const float*)d_in[18];
    const float* g2W    = (const float*)d_in[19];
    const float* g2b    = (const float*)d_in[20];
    const float* d1W    = (const float*)d_in[21];
    const float* d1b    = (const float*)d_in[22];
    const float* d2W    = (const float*)d_in[23];
    const float* d2b    = (const float*)d_in[24];
    const float* d3W    = (const float*)d_in[25];
    const float* d3b    = (const float*)d_in[26];
    const float* d4W    = (const float*)d_in[27];
    const float* d4b    = (const float*)d_in[28];

    cudaFuncSetAttribute(bgemm<128>, cudaFuncAttributeMaxDynamicSharedMemorySize, 111000);
    cudaFuncSetAttribute(bgemm<64>,  cudaFuncAttributeMaxDynamicSharedMemorySize, 84000);

    float *QKV, *P, *TS, *H1, *H2, *H3, *BC2;
    bf16 *XB, *LNM, *RXB, *ZB, *SRCB, *FFHB, *AVB;
    bf16 *WQKVT, *G1T, *G2T, *FF1T, *CW;
    cudaGetSymbolAddress((void**)&QKV,  g_qkv);
    cudaGetSymbolAddress((void**)&P,    g_p);
    cudaGetSymbolAddress((void**)&TS,   g_ts);
    cudaGetSymbolAddress((void**)&H1,   g_h1);
    cudaGetSymbolAddress((void**)&H2,   g_h2);
    cudaGetSymbolAddress((void**)&H3,   g_h3);
    cudaGetSymbolAddress((void**)&BC2,  g_bc2);
    cudaGetSymbolAddress((void**)&XB,   gb_x);
    cudaGetSymbolAddress((void**)&LNM,  gb_lnm);
    cudaGetSymbolAddress((void**)&RXB,  gb_rx);
    cudaGetSymbolAddress((void**)&ZB,   gb_z);
    cudaGetSymbolAddress((void**)&SRCB, gb_src);
    cudaGetSymbolAddress((void**)&FFHB, gb_ffh);
    cudaGetSymbolAddress((void**)&AVB,  gb_av);
    cudaGetSymbolAddress((void**)&WQKVT,gb_wqkv);
    cudaGetSymbolAddress((void**)&G1T,  gb_g1);
    cudaGetSymbolAddress((void**)&G2T,  gb_g2);
    cudaGetSymbolAddress((void**)&FF1T, gb_ff1);
    cudaGetSymbolAddress((void**)&CW,   gb_cw);

    const size_t SZ = (size_t)DD * DD;
    const size_t CWS = (size_t)DD * 64;

    // prep
    megaprep_kernel<<<dim3(16, 16, 17), dim3(32, 8)>>>(g1W, g2W, W_q, W_kv, ff_W1, W_p, memory);
    pregemm_kernel<<<dim3(16, 8, 6), dim3(32, 8)>>>(W_out, ff_W2, g1W, g2W);
    bc2_kernel<<<3, DD>>>(ff_b2, g2W, g2b, BC2);

    // LN1 -> LNM rows [0,NROW); also XB = bf16(x)
    ln_kernel<<<NROW / 8, 256>>>(x, LNM, XB, ln1_g, ln1_b, NROW);

    // fused qkv over src+memory rows (M=68608, N=192)
    launch_tc(LNM, WQKVT, DD, 0, 0, 0, AROW, 192, 64, QKV, 0, 0, 0, 0.f, 0, 0, 0);

    // attention -> AVB (bf16)
    attn_kernel<<<dim3(BB, HH), 128>>>(QKV, P, u, v, AVB);

    // gate 1 (y-side folded through W_out; K = 64 + 512)
    launch_tc(AVB, CW + 0 * CWS, 64, XB, G1T + 1 * SZ, DD, NROW, DD, 128,
              0, RXB, g1b + 0 * DD, g1b + 1 * DD, 0.f, 0, XB, 4);
    launch_tc(AVB, CW + 1 * CWS, 64, XB, G1T + 3 * SZ, DD, NROW, DD, 128,
              0, ZB, g1b + 2 * DD, g1b + 3 * DD, -BG, 0, 0, 2);
    launch_tc(AVB, CW + 2 * CWS, 64, RXB, G1T + 5 * SZ, DD, NROW, DD, 128,
              0, SRCB, g1b + 4 * DD, g1b + 5 * DD, 0.f, ZB, XB, 5);

    // ffh = relu(LN2(src) @ ff_W1 + b1)
    lnb_kernel<<<NROW / 8, 256>>>(SRCB, LNM, ln2_g, ln2_b, NROW);
    launch_tc(LNM, FF1T, DD, 0, 0, 0, NROW, DFF, 64, 0, FFHB, ff_b1, 0, 0.f, 0, 0, 3);

    // gate 2 (y-side = ff folded through ff_W2)
    launch_tc(FFHB, CW + 3 * CWS, 64, SRCB, G2T + 1 * SZ, DD, NROW, DD, 128,
              0, RXB, BC2 + 0 * DD, 0, 0.f, 0, SRCB, 4);
    launch_tc(FFHB, CW + 4 * CWS, 64, SRCB, G2T + 3 * SZ, DD, NROW, DD, 128,
              0, ZB, BC2 + 1 * DD, 0, -BG, 0, 0, 2);
    launch_tc(FFHB, CW + 5 * CWS, 64, RXB, G2T + 5 * SZ, DD, NROW, DD, 128,
              0, XB, BC2 + 2 * DD, 0, 0.f, ZB, SRCB, 5);

    // mean pool (bf16 in, f32 out)
    meanpool_bf_kernel<<<(BB * DD / 2 + 255) / 256, 256>>>(XB, TS);

    // critic head (exact fp32)
    launch_sgemm(TS, d1W, H1, BB, 1024, DD, d1b, 0.f, 2);
    launch_sgemm(H1, d2W, H2, BB, 512, 1024, nullptr, 0.f, 0);
    launch_sgemm(action, d2W + (size_t)1024 * 512, H2, BB, 512, ACT, d2b, 0.f, 3);
    launch_sgemm(H2, d3W, H3, BB, 300, DD, d3b, 0.f, 2);
    final_kernel<<<BB / 4, 128>>>(H3, d4W, d4b, (float*)d_out);
}